// round 4
// baseline (speedup 1.0000x reference)
#include <cuda_runtime.h>
#include <cstdint>

#define SQ   2048
#define DM   2048
#define NH   16
#define DH   128
#define TDM  6144
#define SPAD 132
#define SSPAD 129

__device__ float g_qkv[SQ * TDM];
__device__ float g_a[NH * SQ];
__device__ float g_A[NH * SQ];
__device__ float g_ret[SQ * DM];
__device__ float g_u[SQ * DM];
__device__ float g_nsp[NH * 16 * DH * DH];

// ---------------- SGEMM: C[M,N] = A[M,K] @ B[N,K]^T ----------------
__global__ __launch_bounds__(256) void sgemm_nt(const float* __restrict__ A,
                                                const float* __restrict__ B,
                                                float* __restrict__ C,
                                                int M, int N, int K)
{
    __shared__ float sA[16][SPAD];
    __shared__ float sB[16][SPAD];
    const int bm = blockIdx.y * 128, bn = blockIdx.x * 128;
    const int tid = threadIdx.x;
    const int tx = tid & 15, ty = tid >> 4;
    const int lr = tid >> 2, lk = (tid & 3) * 4;

    const float* Ap = A + (size_t)(bm + lr) * K + lk;
    const float* Aq = A + (size_t)(bm + lr + 64) * K + lk;
    const float* Bp = B + (size_t)(bn + lr) * K + lk;
    const float* Bq = B + (size_t)(bn + lr + 64) * K + lk;

    float acc[8][8] = {};
    const int nk = K >> 4;
    float4 ra0 = *(const float4*)(Ap);
    float4 ra1 = *(const float4*)(Aq);
    float4 rb0 = *(const float4*)(Bp);
    float4 rb1 = *(const float4*)(Bq);

    for (int kt = 0; kt < nk; kt++) {
        sA[lk+0][lr]    = ra0.x; sA[lk+1][lr]    = ra0.y; sA[lk+2][lr]    = ra0.z; sA[lk+3][lr]    = ra0.w;
        sA[lk+0][lr+64] = ra1.x; sA[lk+1][lr+64] = ra1.y; sA[lk+2][lr+64] = ra1.z; sA[lk+3][lr+64] = ra1.w;
        sB[lk+0][lr]    = rb0.x; sB[lk+1][lr]    = rb0.y; sB[lk+2][lr]    = rb0.z; sB[lk+3][lr]    = rb0.w;
        sB[lk+0][lr+64] = rb1.x; sB[lk+1][lr+64] = rb1.y; sB[lk+2][lr+64] = rb1.z; sB[lk+3][lr+64] = rb1.w;
        __syncthreads();
        if (kt + 1 < nk) {
            int off = (kt + 1) * 16;
            ra0 = *(const float4*)(Ap + off); ra1 = *(const float4*)(Aq + off);
            rb0 = *(const float4*)(Bp + off); rb1 = *(const float4*)(Bq + off);
        }
        #pragma unroll
        for (int kk = 0; kk < 16; kk++) {
            float4 a0 = *(const float4*)(&sA[kk][ty*8]);
            float4 a1 = *(const float4*)(&sA[kk][ty*8+4]);
            float4 b0 = *(const float4*)(&sB[kk][tx*8]);
            float4 b1 = *(const float4*)(&sB[kk][tx*8+4]);
            float av[8] = {a0.x,a0.y,a0.z,a0.w,a1.x,a1.y,a1.z,a1.w};
            float bv[8] = {b0.x,b0.y,b0.z,b0.w,b1.x,b1.y,b1.z,b1.w};
            #pragma unroll
            for (int r = 0; r < 8; r++)
                #pragma unroll
                for (int c = 0; c < 8; c++)
                    acc[r][c] = fmaf(av[r], bv[c], acc[r][c]);
        }
        __syncthreads();
    }
    float* Cp = C + (size_t)(bm + ty*8) * N + bn + tx*8;
    #pragma unroll
    for (int r = 0; r < 8; r++) {
        *(float4*)(Cp + (size_t)r * N)     = make_float4(acc[r][0], acc[r][1], acc[r][2], acc[r][3]);
        *(float4*)(Cp + (size_t)r * N + 4) = make_float4(acc[r][4], acc[r][5], acc[r][6], acc[r][7]);
    }
}

// ---------------- alpha: a[h,i] = ab[h]*8*sigmoid(x_i.Wa[h]+ba[h]) ----------------
__global__ __launch_bounds__(256) void alpha_kernel(const float* __restrict__ x,
                                                    const float* __restrict__ Wa,
                                                    const float* __restrict__ ba,
                                                    const float* __restrict__ ab)
{
    int warp = (blockIdx.x * 256 + threadIdx.x) >> 5;
    int lane = threadIdx.x & 31;
    int h = warp >> 11, i = warp & 2047;
    const float* xr = x + (size_t)i * DM;
    const float* wr = Wa + (size_t)h * DM;
    float s = 0.f;
    #pragma unroll 8
    for (int t = lane; t < DM; t += 32) s = fmaf(xr[t], wr[t], s);
    #pragma unroll
    for (int o = 16; o; o >>= 1) s += __shfl_xor_sync(0xffffffffu, s, o);
    if (lane == 0) {
        float sig = 1.f / (1.f + __expf(-(s + ba[h])));
        g_a[h * SQ + i] = ab[h] * 8.f * sig;
    }
}

// ---------------- inclusive cumsum per head ----------------
__global__ __launch_bounds__(256) void cumsum_kernel()
{
    int h = blockIdx.x, t = threadIdx.x;
    __shared__ float tot[256];
    float v[8], run = 0.f;
    #pragma unroll
    for (int c = 0; c < 8; c++) { run += g_a[h * SQ + t * 8 + c]; v[c] = run; }
    tot[t] = run;
    __syncthreads();
    for (int off = 1; off < 256; off <<= 1) {
        float add = (t >= off) ? tot[t - off] : 0.f;
        __syncthreads();
        tot[t] += add;
        __syncthreads();
    }
    float base = (t > 0) ? tot[t - 1] : 0.f;
    #pragma unroll
    for (int c = 0; c < 8; c++) g_A[h * SQ + t * 8 + c] = v[c] + base;
}

// ---------------- xpos rotate q (scale) and k (inv scale * (1-exp(a))) ----------------
__global__ __launch_bounds__(64) void xpos_kernel(const int* __restrict__ offp)
{
    int i = blockIdx.x, j = threadIdx.x;
    float pos = (float)(i + (offp ? *offp : 0));
    float ps  = pos * (1.f / 512.f);
    float freq = exp2f((float)j * (-13.287712379549449f / 64.f));
    float ang  = pos * freq;
    float sn = sinf(ang), cs = cosf(ang);
    float zeta = ((float)(2 * j) + 51.2f) * (1.f / 179.2f);
    float e = log2f(zeta) * ps;
    float scq = exp2f(e), sck0 = exp2f(-e);

    #pragma unroll 4
    for (int h = 0; h < NH; h++) {
        float sck = sck0 * (1.f - __expf(g_a[h * SQ + i]));
        float* qp = g_qkv + (size_t)i * TDM + h * DH;
        float* kp = qp + DM;
        float q1 = qp[j], q2 = qp[j + 64];
        qp[j]      = (q1 * cs - q2 * sn) * scq;
        qp[j + 64] = (q2 * cs + q1 * sn) * scq;
        float k1 = kp[j], k2 = kp[j + 64];
        kp[j]      = (k1 * cs - k2 * sn) * sck;
        kp[j + 64] = (k2 * cs + k1 * sn) * sck;
    }
}

// ---------------- retention ----------------
__device__ __forceinline__ void block_mm_dd(const float* __restrict__ sa,
                                            const float* __restrict__ sb,
                                            int ty, int tx, float acc[8][8])
{
    #pragma unroll 8
    for (int d = 0; d < 128; d++) {
        const float* ap = sa + d * SPAD + ty * 8;
        const float* bp = sb + d * SPAD + tx * 8;
        float4 a0 = *(const float4*)ap;
        float4 a1 = *(const float4*)(ap + 4);
        float4 b0 = *(const float4*)bp;
        float4 b1 = *(const float4*)(bp + 4);
        float av[8] = {a0.x,a0.y,a0.z,a0.w,a1.x,a1.y,a1.z,a1.w};
        float bv[8] = {b0.x,b0.y,b0.z,b0.w,b1.x,b1.y,b1.z,b1.w};
        #pragma unroll
        for (int r = 0; r < 8; r++)
            #pragma unroll
            for (int c = 0; c < 8; c++)
                acc[r][c] = fmaf(av[r], bv[c], acc[r][c]);
    }
}

__global__ __launch_bounds__(256) void retention_kernel(const float* __restrict__ state)
{
    extern __shared__ float sm[];
    float* sQ  = sm;
    float* sB  = sm + 128 * SPAD;
    float* sS  = sm + 2 * 128 * SPAD;
    float* sEi = sm + 2 * 128 * SPAD + 128 * SSPAD;
    float* sFj = sEi + 128;
    float* sE0 = sFj + 128;

    const int h = blockIdx.y, bi = blockIdx.x;
    const int gi0 = bi * 128;
    const int tid = threadIdx.x;
    const int tx = tid & 15, ty = tid >> 4;
    const int jr = tid >> 1, d0 = (tid & 1) * 64;

    { // Q transposed [d][i]
        const float* qp = g_qkv + (size_t)(gi0 + jr) * TDM + h * DH + d0;
        #pragma unroll
        for (int c = 0; c < 16; c++) {
            float4 v4 = *(const float4*)(qp + c * 4);
            int d = d0 + c * 4;
            sQ[(d+0)*SPAD + jr] = v4.x; sQ[(d+1)*SPAD + jr] = v4.y;
            sQ[(d+2)*SPAD + jr] = v4.z; sQ[(d+3)*SPAD + jr] = v4.w;
        }
    }
    { // state[h] as [d][e]
        const float* sp = state + (size_t)h * DH * DH + (size_t)jr * DH + d0;
        float* db = sB + jr * SPAD + d0;
        #pragma unroll
        for (int c = 0; c < 16; c++)
            *(float4*)(db + c * 4) = *(const float4*)(sp + c * 4);
    }
    const float Aref = g_A[h * SQ + gi0];
    if (tid < 128) {
        float Ai = g_A[h * SQ + gi0 + tid];
        sEi[tid] = __expf(Ai - Aref);
        sE0[tid] = __expf(Ai);
    }
    __syncthreads();

    float acc[8][8] = {};
    if (Aref > -87.f) block_mm_dd(sQ, sB, ty, tx, acc);   // Q @ state
    #pragma unroll
    for (int r = 0; r < 8; r++) {
        float e0 = sE0[ty * 8 + r];
        #pragma unroll
        for (int c = 0; c < 8; c++) acc[r][c] *= e0;
    }

    for (int bj = bi; bj >= 0; bj--) {
        int gj0 = bj * 128;
        if (Aref - g_A[h * SQ + gj0 + 127] < -80.f) break;
        __syncthreads();
        { // K transposed [d][j]
            const float* kp = g_qkv + (size_t)(gj0 + jr) * TDM + DM + h * DH + d0;
            #pragma unroll
            for (int c = 0; c < 16; c++) {
                float4 v4 = *(const float4*)(kp + c * 4);
                int d = d0 + c * 4;
                sB[(d+0)*SPAD + jr] = v4.x; sB[(d+1)*SPAD + jr] = v4.y;
                sB[(d+2)*SPAD + jr] = v4.z; sB[(d+3)*SPAD + jr] = v4.w;
            }
        }
        if (tid < 128) sFj[tid] = __expf(Aref - g_A[h * SQ + gj0 + tid]);
        __syncthreads();

        float s[8][8] = {};
        block_mm_dd(sQ, sB, ty, tx, s);     // S = Q K^T
        bool diag = (bj == bi);
        #pragma unroll
        for (int r = 0; r < 8; r++) {
            int il = ty * 8 + r;
            float ei = sEi[il];
            #pragma unroll
            for (int c = 0; c < 8; c++) {
                int jl = tx * 8 + c;
                float val = s[r][c] * ei * sFj[jl];
                if (diag && jl > il) val = 0.f;
                sS[il * SSPAD + jl] = val;
            }
        }
        __syncthreads();
        { // V [j][e]
            const float* vp = g_qkv + (size_t)(gj0 + jr) * TDM + 2 * DM + h * DH + d0;
            float* db = sB + jr * SPAD + d0;
            #pragma unroll
            for (int c = 0; c < 16; c++)
                *(float4*)(db + c * 4) = *(const float4*)(vp + c * 4);
        }
        __syncthreads();
        #pragma unroll 4
        for (int j = 0; j < 128; j++) {      // acc += S @ V
            float av[8];
            #pragma unroll
            for (int r = 0; r < 8; r++) av[r] = sS[(ty * 8 + r) * SSPAD + j];
            const float* bp = sB + j * SPAD + tx * 8;
            float4 b0 = *(const float4*)bp;
            float4 b1 = *(const float4*)(bp + 4);
            float bv[8] = {b0.x,b0.y,b0.z,b0.w,b1.x,b1.y,b1.z,b1.w};
            #pragma unroll
            for (int r = 0; r < 8; r++)
                #pragma unroll
                for (int c = 0; c < 8; c++)
                    acc[r][c] = fmaf(av[r], bv[c], acc[r][c]);
        }
    }

    float* Cp = g_ret + (size_t)(gi0 + ty * 8) * DM + h * DH + tx * 8;
    #pragma unroll
    for (int r = 0; r < 8; r++) {
        *(float4*)(Cp + (size_t)r * DM)     = make_float4(acc[r][0], acc[r][1], acc[r][2], acc[r][3]);
        *(float4*)(Cp + (size_t)r * DM + 4) = make_float4(acc[r][4], acc[r][5], acc[r][6], acc[r][7]);
    }
}

// ---------------- new_state partials ----------------
__global__ __launch_bounds__(256) void nstate_partial_kernel()
{
    const int ch = blockIdx.x, h = blockIdx.y;
    const int gi0 = ch * 128;
    const int tid = threadIdx.x;
    const int tx = tid & 15, ty = tid >> 4;
    float* out = g_nsp + (size_t)(h * 16 + ch) * DH * DH;

    float Alast = g_A[h * SQ + SQ - 1];
    if (Alast - g_A[h * SQ + gi0 + 127] < -80.f) {
        for (int idx = tid; idx < DH * DH; idx += 256) out[idx] = 0.f;
        return;
    }
    __shared__ float sK[16][SPAD];
    __shared__ float sV[16][SPAD];
    __shared__ float w[128];
    if (tid < 128) w[tid] = __expf(Alast - g_A[h * SQ + gi0 + tid]);
    __syncthreads();

    float acc[8][8] = {};
    for (int it = 0; it < 8; it++) {
        int i0 = gi0 + it * 16;
        #pragma unroll
        for (int q = 0; q < 2; q++) {
            int f = tid + 256 * q;
            int ir = f >> 5, d4 = (f & 31) * 4;
            float wi = w[it * 16 + ir];
            float4 kv = *(const float4*)(g_qkv + (size_t)(i0 + ir) * TDM + DM + h * DH + d4);
            float4 vv = *(const float4*)(g_qkv + (size_t)(i0 + ir) * TDM + 2 * DM + h * DH + d4);
            sK[ir][d4+0] = kv.x * wi; sK[ir][d4+1] = kv.y * wi;
            sK[ir][d4+2] = kv.z * wi; sK[ir][d4+3] = kv.w * wi;
            *(float4*)(&sV[ir][d4]) = vv;
        }
        __syncthreads();
        #pragma unroll
        for (int i = 0; i < 16; i++) {
            float4 a0 = *(const float4*)(&sK[i][ty*8]);
            float4 a1 = *(const float4*)(&sK[i][ty*8+4]);
            float4 b0 = *(const float4*)(&sV[i][tx*8]);
            float4 b1 = *(const float4*)(&sV[i][tx*8+4]);
            float av[8] = {a0.x,a0.y,a0.z,a0.w,a1.x,a1.y,a1.z,a1.w};
            float bv[8] = {b0.x,b0.y,b0.z,b0.w,b1.x,b1.y,b1.z,b1.w};
            #pragma unroll
            for (int r = 0; r < 8; r++)
                #pragma unroll
                for (int c = 0; c < 8; c++)
                    acc[r][c] = fmaf(av[r], bv[c], acc[r][c]);
        }
        __syncthreads();
    }
    #pragma unroll
    for (int r = 0; r < 8; r++)
        #pragma unroll
        for (int c = 0; c < 8; c++)
            out[(ty * 8 + r) * DH + tx * 8 + c] = acc[r][c];
}

__global__ __launch_bounds__(256) void nstate_reduce_kernel(const float* __restrict__ state,
                                                            float* __restrict__ outNS)
{
    int idx = blockIdx.x * 256 + threadIdx.x;
    int h = idx >> 14, de = idx & 16383;
    float s = __expf(g_A[h * SQ + SQ - 1]) * state[idx];
    #pragma unroll
    for (int c = 0; c < 16; c++) s += g_nsp[(size_t)(h * 16 + c) * DH * DH + de];
    outNS[idx] = s;
}

// ---------------- group norm in-place on g_ret ----------------
__global__ __launch_bounds__(256) void gnorm_kernel(const float* __restrict__ gw,
                                                    const float* __restrict__ gb)
{
    int warp = (blockIdx.x * 256 + threadIdx.x) >> 5;
    int lane = threadIdx.x & 31;
    int i = warp >> 4, h = warp & 15;
    float* p = g_ret + (size_t)i * DM + h * DH;
    float v[4], s = 0.f;
    #pragma unroll
    for (int c = 0; c < 4; c++) { v[c] = p[lane + 32 * c]; s += v[c]; }
    #pragma unroll
    for (int o = 16; o; o >>= 1) s += __shfl_xor_sync(0xffffffffu, s, o);
    float mu = s * (1.f / 128.f), q = 0.f;
    #pragma unroll
    for (int c = 0; c < 4; c++) { float d = v[c] - mu; q = fmaf(d, d, q); }
    #pragma unroll
    for (int o = 16; o; o >>= 1) q += __shfl_xor_sync(0xffffffffu, q, o);
    float rs = rsqrtf(q * (1.f / 128.f) + 1e-5f);
    #pragma unroll
    for (int c = 0; c < 4; c++) {
        int ch = h * DH + lane + 32 * c;
        p[lane + 32 * c] = (v[c] - mu) * rs * gw[ch] + gb[ch];
    }
}

// ---------------- u = swish(u) * ret ----------------
__global__ __launch_bounds__(256) void swish_kernel()
{
    int idx = blockIdx.x * 256 + threadIdx.x;
    float g = g_u[idx];
    g_u[idx] = g / (1.f + __expf(-g)) * g_ret[idx];
}

extern "C" void kernel_launch(void* const* d_in, const int* in_sizes, int n_in,
                              void* d_out, int out_size)
{
    const float* x     = (const float*)d_in[0];
    const float* state = (const float*)d_in[1];
    const float* Wqkv  = (const float*)d_in[2];
    const float* Wa    = (const float*)d_in[3];
    const float* ba    = (const float*)d_in[4];
    const float* ab    = (const float*)d_in[5];
    const float* gw    = (const float*)d_in[6];
    const float* gb    = (const float*)d_in[7];
    const float* Wout  = (const float*)d_in[8];
    const float* Wgate = (const float*)d_in[9];
    const int*   offp  = (n_in > 10) ? (const int*)d_in[10] : nullptr;

    float* out   = (float*)d_out;
    float* outNS = out + (size_t)SQ * DM;

    float *qkv_p, *ret_p, *u_p;
    cudaGetSymbolAddress((void**)&qkv_p, g_qkv);
    cudaGetSymbolAddress((void**)&ret_p, g_ret);
    cudaGetSymbolAddress((void**)&u_p,   g_u);

    const int RET_SMEM = (2 * 128 * SPAD + 128 * SSPAD + 3 * 128) * 4;
    cudaFuncSetAttribute(retention_kernel,
                         cudaFuncAttributeMaxDynamicSharedMemorySize, RET_SMEM);

    sgemm_nt<<<dim3(TDM/128, SQ/128), 256>>>(x, Wqkv, qkv_p, SQ, TDM, DM);
    alpha_kernel<<<NH * SQ / 8, 256>>>(x, Wa, ba, ab);
    cumsum_kernel<<<NH, 256>>>();
    xpos_kernel<<<SQ, 64>>>(offp);
    retention_kernel<<<dim3(SQ/128, NH), 256, RET_SMEM>>>(state);
    nstate_partial_kernel<<<dim3(16, NH), 256>>>();
    nstate_reduce_kernel<<<NH * DH * DH / 256, 256>>>(state, outNS);
    gnorm_kernel<<<SQ * NH / 8, 256>>>(gw, gb);
    sgemm_nt<<<dim3(DM/128, SQ/128), 256>>>(ret_p, Wgate, u_p, SQ, DM, DM);
    swish_kernel<<<SQ * DM / 256, 256>>>();
    sgemm_nt<<<dim3(DM/128, SQ/128), 256>>>(u_p, Wout, out, SQ, DM, DM);
}

// round 8
// speedup vs baseline: 1.4568x; 1.4568x over previous
#include <cuda_runtime.h>
#include <cuda_bf16.h>
#include <cstdint>

#define SQ   2048
#define DM   2048
#define NH   16
#define DH   128
#define TDM  6144
#define SPAD 132
#define SSPAD 129

// fp32 scratch
__device__ float g_qkv[SQ * TDM];
__device__ float g_a[NH * SQ];
__device__ float g_A[NH * SQ];
__device__ float g_ret[SQ * DM];
__device__ float g_u[SQ * DM];
__device__ float g_nsp[NH * 16 * DH * DH];
// bf16 split scratch
__device__ __nv_bfloat16 g_xh[SQ*DM],  g_xl[SQ*DM];
__device__ __nv_bfloat16 g_Wqh[TDM*DM], g_Wql[TDM*DM];
__device__ __nv_bfloat16 g_Wgh[DM*DM], g_Wgl[DM*DM];
__device__ __nv_bfloat16 g_Woh[DM*DM], g_Wol[DM*DM];
__device__ __nv_bfloat16 g_rh[SQ*DM],  g_rl[SQ*DM];
__device__ __nv_bfloat16 g_uh[SQ*DM],  g_ul[SQ*DM];

// ---------------- PTX helpers (sm_80-family, valid on bare sm_103) ----------------
__device__ __forceinline__ uint32_t smem_u32(const void* p) {
    uint32_t a;
    asm("{ .reg .u64 t; cvta.to.shared.u64 t, %1; cvt.u32.u64 %0, t; }" : "=r"(a) : "l"(p));
    return a;
}
__device__ __forceinline__ void ldsm4(uint32_t& r0, uint32_t& r1, uint32_t& r2, uint32_t& r3,
                                      uint32_t addr) {
    asm volatile("ldmatrix.sync.aligned.m8n8.x4.shared.b16 {%0,%1,%2,%3}, [%4];"
                 : "=r"(r0), "=r"(r1), "=r"(r2), "=r"(r3) : "r"(addr));
}
__device__ __forceinline__ void mma16816(float* c, uint32_t a0, uint32_t a1, uint32_t a2,
                                         uint32_t a3, uint32_t b0, uint32_t b1) {
    asm volatile("mma.sync.aligned.m16n8k16.row.col.f32.bf16.bf16.f32 "
                 "{%0,%1,%2,%3}, {%4,%5,%6,%7}, {%8,%9}, {%0,%1,%2,%3};"
                 : "+f"(c[0]), "+f"(c[1]), "+f"(c[2]), "+f"(c[3])
                 : "r"(a0), "r"(a1), "r"(a2), "r"(a3), "r"(b0), "r"(b1));
}

// ---------------- split fp32 -> (hi, lo) bf16 ----------------
__global__ __launch_bounds__(256) void split_kernel(const float* __restrict__ s,
                                                    __nv_bfloat16* __restrict__ h,
                                                    __nv_bfloat16* __restrict__ l)
{
    int i = blockIdx.x * 256 + threadIdx.x;
    float4 v = ((const float4*)s)[i];
    __nv_bfloat16 h0 = __float2bfloat16(v.x), h1 = __float2bfloat16(v.y);
    __nv_bfloat16 h2 = __float2bfloat16(v.z), h3 = __float2bfloat16(v.w);
    __nv_bfloat16 l0 = __float2bfloat16(v.x - __bfloat162float(h0));
    __nv_bfloat16 l1 = __float2bfloat16(v.y - __bfloat162float(h1));
    __nv_bfloat16 l2 = __float2bfloat16(v.z - __bfloat162float(h2));
    __nv_bfloat16 l3 = __float2bfloat16(v.w - __bfloat162float(h3));
    __nv_bfloat162 ph0; ph0.x = h0; ph0.y = h1;
    __nv_bfloat162 ph1; ph1.x = h2; ph1.y = h3;
    __nv_bfloat162 pl0; pl0.x = l0; pl0.y = l1;
    __nv_bfloat162 pl1; pl1.x = l2; pl1.y = l3;
    ((__nv_bfloat162*)h)[2*i]   = ph0;
    ((__nv_bfloat162*)h)[2*i+1] = ph1;
    ((__nv_bfloat162*)l)[2*i]   = pl0;
    ((__nv_bfloat162*)l)[2*i+1] = pl1;
}

// ---------------- HMMA split-bf16 GEMM: C[M,N] = A[M,K] @ B[N,K]^T ----------------
// 128x128 CTA tile, K-chunk 64 (128B rows, 16B XOR swizzle), 8 warps = 4x2 warp grid,
// warp tile 32x64 = 2x8 m16n8k16. 3 passes: Ah*Bh, Ah*Bl, Al*Bh.
__global__ __launch_bounds__(256, 2) void tgemm(const __nv_bfloat16* __restrict__ Ah,
                                                const __nv_bfloat16* __restrict__ Al,
                                                const __nv_bfloat16* __restrict__ Bh,
                                                const __nv_bfloat16* __restrict__ Bl,
                                                float* __restrict__ C, int N, int K)
{
    extern __shared__ char smem[];   // 4 tiles x 16 KB: Ah, Al, Bh, Bl
    const int tid  = threadIdx.x;
    const int wid  = tid >> 5, lane = tid & 31;
    const int mw   = wid & 3, nw = wid >> 2;      // warp grid 4(m) x 2(n)
    const int bm   = blockIdx.y * 128, bn = blockIdx.x * 128;
    const uint32_t sbase = smem_u32(smem);

    // per-lane ldmatrix row mappings
    const int rA = mw * 32 + (lane & 15);          // + t*16
    const int uA = lane >> 4;                      // k-unit offset (0/1)
    const int rB = nw * 64 + (lane & 7) + ((lane & 16) ? 8 : 0);  // + s8
    const int uB = (lane >> 3) & 1;

    const __nv_bfloat16* src[4] = { Ah + (size_t)bm * K, Al + (size_t)bm * K,
                                    Bh + (size_t)bn * K, Bl + (size_t)bn * K };
    const int lm = tid >> 3;        // 0..31 row within 32-row group
    const int lc = tid & 7;         // 16B unit 0..7

    float acc[2][8][4] = {};
    const int nchunk = K >> 6;

    for (int kc = 0; kc < nchunk; kc++) {
        #pragma unroll
        for (int t = 0; t < 16; t++) {
            const int tile = t >> 2;
            const int m = (t & 3) * 32 + lm;
            uint4 v = *(const uint4*)(src[tile] + (size_t)m * K + kc * 64 + lc * 8);
            *(uint4*)(smem + tile * 16384 + m * 128 + ((lc ^ (m & 7)) << 4)) = v;
        }
        __syncthreads();

        #pragma unroll
        for (int p = 0; p < 3; p++) {
            const uint32_t tA = sbase + ((p == 2) ? 16384 : 0);          // Al : Ah
            const uint32_t tB = sbase + ((p == 1) ? 49152 : 32768);      // Bl : Bh
            #pragma unroll
            for (int k16 = 0; k16 < 4; k16++) {
                uint32_t a[2][4];
                #pragma unroll
                for (int t = 0; t < 2; t++) {
                    const int row = rA + t * 16;
                    ldsm4(a[t][0], a[t][1], a[t][2], a[t][3],
                          tA + row * 128 + (((2 * k16 + uA) ^ (row & 7)) << 4));
                }
                uint32_t b[8][2];
                #pragma unroll
                for (int j = 0; j < 4; j++) {
                    const int row = rB + j * 16;
                    uint32_t r0, r1, r2, r3;
                    ldsm4(r0, r1, r2, r3,
                          tB + row * 128 + (((2 * k16 + uB) ^ (row & 7)) << 4));
                    b[2*j][0] = r0; b[2*j][1] = r1;
                    b[2*j+1][0] = r2; b[2*j+1][1] = r3;
                }
                #pragma unroll
                for (int t = 0; t < 2; t++)
                    #pragma unroll
                    for (int s = 0; s < 8; s++)
                        mma16816(acc[t][s], a[t][0], a[t][1], a[t][2], a[t][3],
                                 b[s][0], b[s][1]);
            }
        }
        __syncthreads();
    }

    float* Cw = C + (size_t)(bm + mw * 32 + (lane >> 2)) * N + bn + nw * 64 + (lane & 3) * 2;
    #pragma unroll
    for (int t = 0; t < 2; t++)
        #pragma unroll
        for (int s = 0; s < 8; s++) {
            *(float2*)(Cw + (size_t)(t * 16)     * N + s * 8) = make_float2(acc[t][s][0], acc[t][s][1]);
            *(float2*)(Cw + (size_t)(t * 16 + 8) * N + s * 8) = make_float2(acc[t][s][2], acc[t][s][3]);
        }
}

// ---------------- alpha ----------------
__global__ __launch_bounds__(256) void alpha_kernel(const float* __restrict__ x,
                                                    const float* __restrict__ Wa,
                                                    const float* __restrict__ ba,
                                                    const float* __restrict__ ab)
{
    int warp = (blockIdx.x * 256 + threadIdx.x) >> 5;
    int lane = threadIdx.x & 31;
    int h = warp >> 11, i = warp & 2047;
    const float* xr = x + (size_t)i * DM;
    const float* wr = Wa + (size_t)h * DM;
    float s = 0.f;
    #pragma unroll 8
    for (int t = lane; t < DM; t += 32) s = fmaf(xr[t], wr[t], s);
    #pragma unroll
    for (int o = 16; o; o >>= 1) s += __shfl_xor_sync(0xffffffffu, s, o);
    if (lane == 0) {
        float sig = 1.f / (1.f + __expf(-(s + ba[h])));
        g_a[h * SQ + i] = ab[h] * 8.f * sig;
    }
}

// ---------------- cumsum ----------------
__global__ __launch_bounds__(256) void cumsum_kernel()
{
    int h = blockIdx.x, t = threadIdx.x;
    __shared__ float tot[256];
    float v[8], run = 0.f;
    #pragma unroll
    for (int c = 0; c < 8; c++) { run += g_a[h * SQ + t * 8 + c]; v[c] = run; }
    tot[t] = run;
    __syncthreads();
    for (int off = 1; off < 256; off <<= 1) {
        float add = (t >= off) ? tot[t - off] : 0.f;
        __syncthreads();
        tot[t] += add;
        __syncthreads();
    }
    float base = (t > 0) ? tot[t - 1] : 0.f;
    #pragma unroll
    for (int c = 0; c < 8; c++) g_A[h * SQ + t * 8 + c] = v[c] + base;
}

// ---------------- xpos ----------------
__global__ __launch_bounds__(64) void xpos_kernel(const int* __restrict__ offp)
{
    int i = blockIdx.x, j = threadIdx.x;
    float pos = (float)(i + (offp ? *offp : 0));
    float ps  = pos * (1.f / 512.f);
    float freq = exp2f((float)j * (-13.287712379549449f / 64.f));
    float ang  = pos * freq;
    float sn = sinf(ang), cs = cosf(ang);
    float zeta = ((float)(2 * j) + 51.2f) * (1.f / 179.2f);
    float e = log2f(zeta) * ps;
    float scq = exp2f(e), sck0 = exp2f(-e);

    #pragma unroll 4
    for (int h = 0; h < NH; h++) {
        float sck = sck0 * (1.f - __expf(g_a[h * SQ + i]));
        float* qp = g_qkv + (size_t)i * TDM + h * DH;
        float* kp = qp + DM;
        float q1 = qp[j], q2 = qp[j + 64];
        qp[j]      = (q1 * cs - q2 * sn) * scq;
        qp[j + 64] = (q2 * cs + q1 * sn) * scq;
        float k1 = kp[j], k2 = kp[j + 64];
        kp[j]      = (k1 * cs - k2 * sn) * sck;
        kp[j + 64] = (k2 * cs + k1 * sn) * sck;
    }
}

// ---------------- retention ----------------
__device__ __forceinline__ void block_mm_dd(const float* __restrict__ sa,
                                            const float* __restrict__ sb,
                                            int ty, int tx, float acc[8][8])
{
    #pragma unroll 8
    for (int d = 0; d < 128; d++) {
        const float* ap = sa + d * SPAD + ty * 8;
        const float* bp = sb + d * SPAD + tx * 8;
        float4 a0 = *(const float4*)ap;
        float4 a1 = *(const float4*)(ap + 4);
        float4 b0 = *(const float4*)bp;
        float4 b1 = *(const float4*)(bp + 4);
        float av[8] = {a0.x,a0.y,a0.z,a0.w,a1.x,a1.y,a1.z,a1.w};
        float bv[8] = {b0.x,b0.y,b0.z,b0.w,b1.x,b1.y,b1.z,b1.w};
        #pragma unroll
        for (int r = 0; r < 8; r++)
            #pragma unroll
            for (int c = 0; c < 8; c++)
                acc[r][c] = fmaf(av[r], bv[c], acc[r][c]);
    }
}

__global__ __launch_bounds__(256) void retention_kernel(const float* __restrict__ state)
{
    extern __shared__ float sm[];
    float* sQ  = sm;
    float* sB  = sm + 128 * SPAD;
    float* sS  = sm + 2 * 128 * SPAD;
    float* sEi = sm + 2 * 128 * SPAD + 128 * SSPAD;
    float* sFj = sEi + 128;
    float* sE0 = sFj + 128;

    const int h = blockIdx.y, bi = blockIdx.x;
    const int gi0 = bi * 128;
    const int tid = threadIdx.x;
    const int tx = tid & 15, ty = tid >> 4;
    const int jr = tid >> 1, d0 = (tid & 1) * 64;

    {
        const float* qp = g_qkv + (size_t)(gi0 + jr) * TDM + h * DH + d0;
        #pragma unroll
        for (int c = 0; c < 16; c++) {
            float4 v4 = *(const float4*)(qp + c * 4);
            int d = d0 + c * 4;
            sQ[(d+0)*SPAD + jr] = v4.x; sQ[(d+1)*SPAD + jr] = v4.y;
            sQ[(d+2)*SPAD + jr] = v4.z; sQ[(d+3)*SPAD + jr] = v4.w;
        }
    }
    {
        const float* sp = state + (size_t)h * DH * DH + (size_t)jr * DH + d0;
        float* db = sB + jr * SPAD + d0;
        #pragma unroll
        for (int c = 0; c < 16; c++)
            *(float4*)(db + c * 4) = *(const float4*)(sp + c * 4);
    }
    const float Aref = g_A[h * SQ + gi0];
    if (tid < 128) {
        float Ai = g_A[h * SQ + gi0 + tid];
        sEi[tid] = __expf(Ai - Aref);
        sE0[tid] = __expf(Ai);
    }
    __syncthreads();

    float acc[8][8] = {};
    if (Aref > -87.f) block_mm_dd(sQ, sB, ty, tx, acc);
    #pragma unroll
    for (int r = 0; r < 8; r++) {
        float e0 = sE0[ty * 8 + r];
        #pragma unroll
        for (int c = 0; c < 8; c++) acc[r][c] *= e0;
    }

    for (int bj = bi; bj >= 0; bj--) {
        int gj0 = bj * 128;
        if (Aref - g_A[h * SQ + gj0 + 127] < -80.f) break;
        __syncthreads();
        {
            const float* kp = g_qkv + (size_t)(gj0 + jr) * TDM + DM + h * DH + d0;
            #pragma unroll
            for (int c = 0; c < 16; c++) {
                float4 v4 = *(const float4*)(kp + c * 4);
                int d = d0 + c * 4;
                sB[(d+0)*SPAD + jr] = v4.x; sB[(d+1)*SPAD + jr] = v4.y;
                sB[(d+2)*SPAD + jr] = v4.z; sB[(d+3)*SPAD + jr] = v4.w;
            }
        }
        if (tid < 128) sFj[tid] = __expf(Aref - g_A[h * SQ + gj0 + tid]);
        __syncthreads();

        float s[8][8] = {};
        block_mm_dd(sQ, sB, ty, tx, s);
        bool diag = (bj == bi);
        #pragma unroll
        for (int r = 0; r < 8; r++) {
            int il = ty * 8 + r;
            float ei = sEi[il];
            #pragma unroll
            for (int c = 0; c < 8; c++) {
                int jl = tx * 8 + c;
                float val = s[r][c] * ei * sFj[jl];
                if (diag && jl > il) val = 0.f;
                sS[il * SSPAD + jl] = val;
            }
        }
        __syncthreads();
        {
            const float* vp = g_qkv + (size_t)(gj0 + jr) * TDM + 2 * DM + h * DH + d0;
            float* db = sB + jr * SPAD + d0;
            #pragma unroll
            for (int c = 0; c < 16; c++)
                *(float4*)(db + c * 4) = *(const float4*)(vp + c * 4);
        }
        __syncthreads();
        #pragma unroll 4
        for (int j = 0; j < 128; j++) {
            float av[8];
            #pragma unroll
            for (int r = 0; r < 8; r++) av[r] = sS[(ty * 8 + r) * SSPAD + j];
            const float* bp = sB + j * SPAD + tx * 8;
            float4 b0 = *(const float4*)bp;
            float4 b1 = *(const float4*)(bp + 4);
            float bv[8] = {b0.x,b0.y,b0.z,b0.w,b1.x,b1.y,b1.z,b1.w};
            #pragma unroll
            for (int r = 0; r < 8; r++)
                #pragma unroll
                for (int c = 0; c < 8; c++)
                    acc[r][c] = fmaf(av[r], bv[c], acc[r][c]);
        }
    }

    float* Cp = g_ret + (size_t)(gi0 + ty * 8) * DM + h * DH + tx * 8;
    #pragma unroll
    for (int r = 0; r < 8; r++) {
        *(float4*)(Cp + (size_t)r * DM)     = make_float4(acc[r][0], acc[r][1], acc[r][2], acc[r][3]);
        *(float4*)(Cp + (size_t)r * DM + 4) = make_float4(acc[r][4], acc[r][5], acc[r][6], acc[r][7]);
    }
}

// ---------------- new_state ----------------
__global__ __launch_bounds__(256) void nstate_partial_kernel()
{
    const int ch = blockIdx.x, h = blockIdx.y;
    const int gi0 = ch * 128;
    const int tid = threadIdx.x;
    const int tx = tid & 15, ty = tid >> 4;
    float* out = g_nsp + (size_t)(h * 16 + ch) * DH * DH;

    float Alast = g_A[h * SQ + SQ - 1];
    if (Alast - g_A[h * SQ + gi0 + 127] < -80.f) {
        for (int idx = tid; idx < DH * DH; idx += 256) out[idx] = 0.f;
        return;
    }
    __shared__ float sK[16][SPAD];
    __shared__ float sV[16][SPAD];
    __shared__ float w[128];
    if (tid < 128) w[tid] = __expf(Alast - g_A[h * SQ + gi0 + tid]);
    __syncthreads();

    float acc[8][8] = {};
    for (int it = 0; it < 8; it++) {
        int i0 = gi0 + it * 16;
        #pragma unroll
        for (int q = 0; q < 2; q++) {
            int f = tid + 256 * q;
            int ir = f >> 5, d4 = (f & 31) * 4;
            float wi = w[it * 16 + ir];
            float4 kv = *(const float4*)(g_qkv + (size_t)(i0 + ir) * TDM + DM + h * DH + d4);
            float4 vv = *(const float4*)(g_qkv + (size_t)(i0 + ir) * TDM + 2 * DM + h * DH + d4);
            sK[ir][d4+0] = kv.x * wi; sK[ir][d4+1] = kv.y * wi;
            sK[ir][d4+2] = kv.z * wi; sK[ir][d4+3] = kv.w * wi;
            *(float4*)(&sV[ir][d4]) = vv;
        }
        __syncthreads();
        #pragma unroll
        for (int i = 0; i < 16; i++) {
            float4 a0 = *(const float4*)(&sK[i][ty*8]);
            float4 a1 = *(const float4*)(&sK[i][ty*8+4]);
            float4 b0 = *(const float4*)(&sV[i][tx*8]);
            float4 b1 = *(const float4*)(&sV[i][tx*8+4]);
            float av[8] = {a0.x,a0.y,a0.z,a0.w,a1.x,a1.y,a1.z,a1.w};
            float bv[8] = {b0.x,b0.y,b0.z,b0.w,b1.x,b1.y,b1.z,b1.w};
            #pragma unroll
            for (int r = 0; r < 8; r++)
                #pragma unroll
                for (int c = 0; c < 8; c++)
                    acc[r][c] = fmaf(av[r], bv[c], acc[r][c]);
        }
        __syncthreads();
    }
    #pragma unroll
    for (int r = 0; r < 8; r++)
        #pragma unroll
        for (int c = 0; c < 8; c++)
            out[(ty * 8 + r) * DH + tx * 8 + c] = acc[r][c];
}

__global__ __launch_bounds__(256) void nstate_reduce_kernel(const float* __restrict__ state,
                                                            float* __restrict__ outNS)
{
    int idx = blockIdx.x * 256 + threadIdx.x;
    int h = idx >> 14;
    float s = __expf(g_A[h * SQ + SQ - 1]) * state[idx];
    int de = idx & 16383;
    #pragma unroll
    for (int c = 0; c < 16; c++) s += g_nsp[(size_t)(h * 16 + c) * DH * DH + de];
    outNS[idx] = s;
}

// ---------------- group norm ----------------
__global__ __launch_bounds__(256) void gnorm_kernel(const float* __restrict__ gw,
                                                    const float* __restrict__ gb)
{
    int warp = (blockIdx.x * 256 + threadIdx.x) >> 5;
    int lane = threadIdx.x & 31;
    int i = warp >> 4, h = warp & 15;
    float* p = g_ret + (size_t)i * DM + h * DH;
    float v[4], s = 0.f;
    #pragma unroll
    for (int c = 0; c < 4; c++) { v[c] = p[lane + 32 * c]; s += v[c]; }
    #pragma unroll
    for (int o = 16; o; o >>= 1) s += __shfl_xor_sync(0xffffffffu, s, o);
    float mu = s * (1.f / 128.f), q = 0.f;
    #pragma unroll
    for (int c = 0; c < 4; c++) { float d = v[c] - mu; q = fmaf(d, d, q); }
    #pragma unroll
    for (int o = 16; o; o >>= 1) q += __shfl_xor_sync(0xffffffffu, q, o);
    float rs = rsqrtf(q * (1.f / 128.f) + 1e-5f);
    #pragma unroll
    for (int c = 0; c < 4; c++) {
        int ch = h * DH + lane + 32 * c;
        p[lane + 32 * c] = (v[c] - mu) * rs * gw[ch] + gb[ch];
    }
}

// ---------------- swish ----------------
__global__ __launch_bounds__(256) void swish_kernel()
{
    int idx = blockIdx.x * 256 + threadIdx.x;
    float g = g_u[idx];
    g_u[idx] = g / (1.f + __expf(-g)) * g_ret[idx];
}

extern "C" void kernel_launch(void* const* d_in, const int* in_sizes, int n_in,
                              void* d_out, int out_size)
{
    const float* x     = (const float*)d_in[0];
    const float* state = (const float*)d_in[1];
    const float* Wqkv  = (const float*)d_in[2];
    const float* Wa    = (const float*)d_in[3];
    const float* ba    = (const float*)d_in[4];
    const float* ab    = (const float*)d_in[5];
    const float* gw    = (const float*)d_in[6];
    const float* gb    = (const float*)d_in[7];
    const float* Wout  = (const float*)d_in[8];
    const float* Wgate = (const float*)d_in[9];
    const int*   offp  = (n_in > 10) ? (const int*)d_in[10] : nullptr;

    float* out   = (float*)d_out;
    float* outNS = out + (size_t)SQ * DM;

    float *qkv_p, *ret_p, *u_p;
    cudaGetSymbolAddress((void**)&qkv_p, g_qkv);
    cudaGetSymbolAddress((void**)&ret_p, g_ret);
    cudaGetSymbolAddress((void**)&u_p,   g_u);
    __nv_bfloat16 *xh,*xl,*Wqh,*Wql,*Wgh,*Wgl,*Woh,*Wol,*rh,*rl,*uh,*ul;
    cudaGetSymbolAddress((void**)&xh,  g_xh);  cudaGetSymbolAddress((void**)&xl,  g_xl);
    cudaGetSymbolAddress((void**)&Wqh, g_Wqh); cudaGetSymbolAddress((void**)&Wql, g_Wql);
    cudaGetSymbolAddress((void**)&Wgh, g_Wgh); cudaGetSymbolAddress((void**)&Wgl, g_Wgl);
    cudaGetSymbolAddress((void**)&Woh, g_Woh); cudaGetSymbolAddress((void**)&Wol, g_Wol);
    cudaGetSymbolAddress((void**)&rh,  g_rh);  cudaGetSymbolAddress((void**)&rl,  g_rl);
    cudaGetSymbolAddress((void**)&uh,  g_uh);  cudaGetSymbolAddress((void**)&ul,  g_ul);

    const int RET_SMEM = (2 * 128 * SPAD + 128 * SSPAD + 3 * 128) * 4;
    cudaFuncSetAttribute(retention_kernel,
                         cudaFuncAttributeMaxDynamicSharedMemorySize, RET_SMEM);
    const int TG_SMEM = 65536;
    cudaFuncSetAttribute(tgemm,
                         cudaFuncAttributeMaxDynamicSharedMemorySize, TG_SMEM);

    split_kernel<<<SQ * DM / 1024, 256>>>(x, xh, xl);
    split_kernel<<<TDM * DM / 1024, 256>>>(Wqkv, Wqh, Wql);
    split_kernel<<<DM * DM / 1024, 256>>>(Wgate, Wgh, Wgl);
    split_kernel<<<DM * DM / 1024, 256>>>(Wout, Woh, Wol);

    tgemm<<<dim3(TDM/128, SQ/128), 256, TG_SMEM>>>(xh, xl, Wqh, Wql, qkv_p, TDM, DM);

    alpha_kernel<<<NH * SQ / 8, 256>>>(x, Wa, ba, ab);
    cumsum_kernel<<<NH, 256>>>();
    xpos_kernel<<<SQ, 64>>>(offp);
    retention_kernel<<<dim3(SQ/128, NH), 256, RET_SMEM>>>(state);
    nstate_partial_kernel<<<dim3(16, NH), 256>>>();
    nstate_reduce_kernel<<<NH * DH * DH / 256, 256>>>(state, outNS);
    gnorm_kernel<<<SQ * NH / 8, 256>>>(gw, gb);

    split_kernel<<<SQ * DM / 1024, 256>>>(ret_p, rh, rl);
    tgemm<<<dim3(DM/128, SQ/128), 256, TG_SMEM>>>(rh, rl, Wgh, Wgl, u_p, DM, DM);
    swish_kernel<<<SQ * DM / 256, 256>>>();
    split_kernel<<<SQ * DM / 1024, 256>>>(u_p, uh, ul);
    tgemm<<<dim3(DM/128, SQ/128), 256, TG_SMEM>>>(uh, ul, Woh, Wol, out, DM, DM);
}

// round 10
// speedup vs baseline: 1.8911x; 1.2982x over previous
#include <cuda_runtime.h>
#include <cuda_bf16.h>
#include <cstdint>

#define SQ   2048
#define DM   2048
#define NH   16
#define DH   128
#define TDM  6144
#define SPAD 132

// fp32 scratch
__device__ float g_qkv[SQ * TDM];
__device__ float g_a[NH * SQ];
__device__ float g_A[NH * SQ];
__device__ float g_ret[SQ * DM];
__device__ float g_u[SQ * DM];
__device__ float g_nsp[NH * 16 * DH * DH];
// bf16 split scratch
__device__ __nv_bfloat16 g_xh[SQ*DM],  g_xl[SQ*DM];
__device__ __nv_bfloat16 g_Wqh[TDM*DM], g_Wql[TDM*DM];
__device__ __nv_bfloat16 g_Wgh[DM*DM], g_Wgl[DM*DM];
__device__ __nv_bfloat16 g_Woh[DM*DM], g_Wol[DM*DM];
__device__ __nv_bfloat16 g_rh[SQ*DM],  g_rl[SQ*DM];
__device__ __nv_bfloat16 g_uh[SQ*DM],  g_ul[SQ*DM];
__device__ __nv_bfloat16 g_qkvh[SQ*TDM], g_qkvl[SQ*TDM];

// ---------------- PTX helpers (sm_80-family, valid on bare sm_103) ----------------
__device__ __forceinline__ uint32_t smem_u32(const void* p) {
    uint32_t a;
    asm("{ .reg .u64 t; cvta.to.shared.u64 t, %1; cvt.u32.u64 %0, t; }" : "=r"(a) : "l"(p));
    return a;
}
__device__ __forceinline__ void ldsm4(uint32_t& r0, uint32_t& r1, uint32_t& r2, uint32_t& r3,
                                      uint32_t addr) {
    asm volatile("ldmatrix.sync.aligned.m8n8.x4.shared.b16 {%0,%1,%2,%3}, [%4];"
                 : "=r"(r0), "=r"(r1), "=r"(r2), "=r"(r3) : "r"(addr));
}
__device__ __forceinline__ void ldsm4t(uint32_t& r0, uint32_t& r1, uint32_t& r2, uint32_t& r3,
                                       uint32_t addr) {
    asm volatile("ldmatrix.sync.aligned.m8n8.x4.trans.shared.b16 {%0,%1,%2,%3}, [%4];"
                 : "=r"(r0), "=r"(r1), "=r"(r2), "=r"(r3) : "r"(addr));
}
__device__ __forceinline__ void mma16816(float* c, uint32_t a0, uint32_t a1, uint32_t a2,
                                         uint32_t a3, uint32_t b0, uint32_t b1) {
    asm volatile("mma.sync.aligned.m16n8k16.row.col.f32.bf16.bf16.f32 "
                 "{%0,%1,%2,%3}, {%4,%5,%6,%7}, {%8,%9}, {%0,%1,%2,%3};"
                 : "+f"(c[0]), "+f"(c[1]), "+f"(c[2]), "+f"(c[3])
                 : "r"(a0), "r"(a1), "r"(a2), "r"(a3), "r"(b0), "r"(b1));
}
__device__ __forceinline__ uint32_t packbf(float x, float y) {
    __nv_bfloat162 p; p.x = __float2bfloat16(x); p.y = __float2bfloat16(y);
    return *(uint32_t*)&p;
}
__device__ __forceinline__ float bhi(float v) {
    return __bfloat162float(__float2bfloat16(v));
}
// swizzled byte offset inside a 128x128 bf16 tile (256B rows, 16B units)
__device__ __forceinline__ int swoff(int row, int u) {
    return row * 256 + (((u & 8) | ((u ^ row) & 7)) << 4);
}

// ---------------- split fp32 -> (hi, lo) bf16 ----------------
__global__ __launch_bounds__(256) void split_kernel(const float* __restrict__ s,
                                                    __nv_bfloat16* __restrict__ h,
                                                    __nv_bfloat16* __restrict__ l)
{
    int i = blockIdx.x * 256 + threadIdx.x;
    float4 v = ((const float4*)s)[i];
    float h0 = bhi(v.x), h1 = bhi(v.y), h2 = bhi(v.z), h3 = bhi(v.w);
    ((uint32_t*)h)[2*i]   = packbf(v.x, v.y);
    ((uint32_t*)h)[2*i+1] = packbf(v.z, v.w);
    ((uint32_t*)l)[2*i]   = packbf(v.x - h0, v.y - h1);
    ((uint32_t*)l)[2*i+1] = packbf(v.z - h2, v.w - h3);
}

// ---------------- HMMA split-bf16 GEMM: C[M,N] = A[M,K] @ B[N,K]^T ----------------
__global__ __launch_bounds__(256, 2) void tgemm(const __nv_bfloat16* __restrict__ Ah,
                                                const __nv_bfloat16* __restrict__ Al,
                                                const __nv_bfloat16* __restrict__ Bh,
                                                const __nv_bfloat16* __restrict__ Bl,
                                                float* __restrict__ C, int N, int K)
{
    extern __shared__ char smem[];   // 4 tiles x 16 KB: Ah, Al, Bh, Bl
    const int tid  = threadIdx.x;
    const int wid  = tid >> 5, lane = tid & 31;
    const int mw   = wid & 3, nw = wid >> 2;
    const int bm   = blockIdx.y * 128, bn = blockIdx.x * 128;
    const uint32_t sbase = smem_u32(smem);

    const int rA = mw * 32 + (lane & 15);
    const int uA = lane >> 4;
    const int rB = nw * 64 + (lane & 7) + ((lane & 16) ? 8 : 0);
    const int uB = (lane >> 3) & 1;

    const __nv_bfloat16* src[4] = { Ah + (size_t)bm * K, Al + (size_t)bm * K,
                                    Bh + (size_t)bn * K, Bl + (size_t)bn * K };
    const int lm = tid >> 3;
    const int lc = tid & 7;

    float acc[2][8][4] = {};
    const int nchunk = K >> 6;

    for (int kc = 0; kc < nchunk; kc++) {
        #pragma unroll
        for (int t = 0; t < 16; t++) {
            const int tile = t >> 2;
            const int m = (t & 3) * 32 + lm;
            uint4 v = *(const uint4*)(src[tile] + (size_t)m * K + kc * 64 + lc * 8);
            *(uint4*)(smem + tile * 16384 + m * 128 + ((lc ^ (m & 7)) << 4)) = v;
        }
        __syncthreads();

        #pragma unroll
        for (int p = 0; p < 3; p++) {
            const uint32_t tA = sbase + ((p == 2) ? 16384 : 0);
            const uint32_t tB = sbase + ((p == 1) ? 49152 : 32768);
            #pragma unroll
            for (int k16 = 0; k16 < 4; k16++) {
                uint32_t a[2][4];
                #pragma unroll
                for (int t = 0; t < 2; t++) {
                    const int row = rA + t * 16;
                    ldsm4(a[t][0], a[t][1], a[t][2], a[t][3],
                          tA + row * 128 + (((2 * k16 + uA) ^ (row & 7)) << 4));
                }
                uint32_t b[8][2];
                #pragma unroll
                for (int j = 0; j < 4; j++) {
                    const int row = rB + j * 16;
                    uint32_t r0, r1, r2, r3;
                    ldsm4(r0, r1, r2, r3,
                          tB + row * 128 + (((2 * k16 + uB) ^ (row & 7)) << 4));
                    b[2*j][0] = r0; b[2*j][1] = r1;
                    b[2*j+1][0] = r2; b[2*j+1][1] = r3;
                }
                #pragma unroll
                for (int t = 0; t < 2; t++)
                    #pragma unroll
                    for (int s = 0; s < 8; s++)
                        mma16816(acc[t][s], a[t][0], a[t][1], a[t][2], a[t][3],
                                 b[s][0], b[s][1]);
            }
        }
        __syncthreads();
    }

    float* Cw = C + (size_t)(bm + mw * 32 + (lane >> 2)) * N + bn + nw * 64 + (lane & 3) * 2;
    #pragma unroll
    for (int t = 0; t < 2; t++)
        #pragma unroll
        for (int s = 0; s < 8; s++) {
            *(float2*)(Cw + (size_t)(t * 16)     * N + s * 8) = make_float2(acc[t][s][0], acc[t][s][1]);
            *(float2*)(Cw + (size_t)(t * 16 + 8) * N + s * 8) = make_float2(acc[t][s][2], acc[t][s][3]);
        }
}

// ---------------- alpha ----------------
__global__ __launch_bounds__(256) void alpha_kernel(const float* __restrict__ x,
                                                    const float* __restrict__ Wa,
                                                    const float* __restrict__ ba,
                                                    const float* __restrict__ ab)
{
    int warp = (blockIdx.x * 256 + threadIdx.x) >> 5;
    int lane = threadIdx.x & 31;
    int h = warp >> 11, i = warp & 2047;
    const float* xr = x + (size_t)i * DM;
    const float* wr = Wa + (size_t)h * DM;
    float s = 0.f;
    #pragma unroll 8
    for (int t = lane; t < DM; t += 32) s = fmaf(xr[t], wr[t], s);
    #pragma unroll
    for (int o = 16; o; o >>= 1) s += __shfl_xor_sync(0xffffffffu, s, o);
    if (lane == 0) {
        float sig = 1.f / (1.f + __expf(-(s + ba[h])));
        g_a[h * SQ + i] = ab[h] * 8.f * sig;
    }
}

// ---------------- cumsum ----------------
__global__ __launch_bounds__(256) void cumsum_kernel()
{
    int h = blockIdx.x, t = threadIdx.x;
    __shared__ float tot[256];
    float v[8], run = 0.f;
    #pragma unroll
    for (int c = 0; c < 8; c++) { run += g_a[h * SQ + t * 8 + c]; v[c] = run; }
    tot[t] = run;
    __syncthreads();
    for (int off = 1; off < 256; off <<= 1) {
        float add = (t >= off) ? tot[t - off] : 0.f;
        __syncthreads();
        tot[t] += add;
        __syncthreads();
    }
    float base = (t > 0) ? tot[t - 1] : 0.f;
    #pragma unroll
    for (int c = 0; c < 8; c++) g_A[h * SQ + t * 8 + c] = v[c] + base;
}

// ---------------- xpos: rotate q,k; write fp32 + split bf16 q,k,v ----------------
__global__ __launch_bounds__(64) void xpos_kernel(const int* __restrict__ offp)
{
    int i = blockIdx.x, j = threadIdx.x;
    float pos = (float)(i + (offp ? *offp : 0));
    float ps  = pos * (1.f / 512.f);
    float freq = exp2f((float)j * (-13.287712379549449f / 64.f));
    float ang  = pos * freq;
    float sn = sinf(ang), cs = cosf(ang);
    float zeta = ((float)(2 * j) + 51.2f) * (1.f / 179.2f);
    float e = log2f(zeta) * ps;
    float scq = exp2f(e), sck0 = exp2f(-e);

    #pragma unroll 4
    for (int h = 0; h < NH; h++) {
        float sck = sck0 * (1.f - __expf(g_a[h * SQ + i]));
        size_t base = (size_t)i * TDM + h * DH;
        float* qp = g_qkv + base;
        float* kp = qp + DM;
        float* vp = qp + 2 * DM;
        float q1 = qp[j], q2 = qp[j + 64];
        float k1 = kp[j], k2 = kp[j + 64];
        float qa = (q1 * cs - q2 * sn) * scq;
        float qb = (q2 * cs + q1 * sn) * scq;
        float ka = (k1 * cs - k2 * sn) * sck;
        float kb = (k2 * cs + k1 * sn) * sck;
        qp[j] = qa; qp[j + 64] = qb;
        kp[j] = ka; kp[j + 64] = kb;
        float va = vp[j], vb = vp[j + 64];
        __nv_bfloat16* ph = g_qkvh + base;
        __nv_bfloat16* pl = g_qkvl + base;
        ph[j]      = __float2bfloat16(qa); pl[j]      = __float2bfloat16(qa - bhi(qa));
        ph[j + 64] = __float2bfloat16(qb); pl[j + 64] = __float2bfloat16(qb - bhi(qb));
        ph[DM + j]      = __float2bfloat16(ka); pl[DM + j]      = __float2bfloat16(ka - bhi(ka));
        ph[DM + j + 64] = __float2bfloat16(kb); pl[DM + j + 64] = __float2bfloat16(kb - bhi(kb));
        ph[2*DM + j]      = __float2bfloat16(va); pl[2*DM + j]      = __float2bfloat16(va - bhi(va));
        ph[2*DM + j + 64] = __float2bfloat16(vb); pl[2*DM + j + 64] = __float2bfloat16(vb - bhi(vb));
    }
}

// ---------------- HMMA retention ----------------
// smem: Qh(32K) Ql(32K) Bh(32K) Bl(32K) + sEi/sFj/sE0
#define R_QH 0
#define R_QL 32768
#define R_BH 65536
#define R_BL 98304
#define R_EI 131072
#define R_FJ 131584
#define R_E0 132096
#define R_SMEM 132608

__device__ __forceinline__ void load_tile_split(char* sm, int dh, int dl,
                                                const __nv_bfloat16* srch,
                                                const __nv_bfloat16* srcl,
                                                int tid)
{
    int r = tid >> 1, half = tid & 1;
    const __nv_bfloat16* sh = srch + (size_t)r * TDM + half * 64;
    const __nv_bfloat16* sl = srcl + (size_t)r * TDM + half * 64;
    #pragma unroll
    for (int c = 0; c < 8; c++) {
        int u = half * 8 + c;
        int off = swoff(r, u);
        *(uint4*)(sm + dh + off) = *(const uint4*)(sh + c * 8);
        *(uint4*)(sm + dl + off) = *(const uint4*)(sl + c * 8);
    }
}

__global__ __launch_bounds__(256) void retention_hmma(const float* __restrict__ state)
{
    extern __shared__ char sm[];
    float* sEi = (float*)(sm + R_EI);
    float* sFj = (float*)(sm + R_FJ);
    float* sE0 = (float*)(sm + R_E0);

    const int h = blockIdx.y, bi = 15 - blockIdx.x;
    const int gi0 = bi * 128;
    const int tid = threadIdx.x;
    const int w = tid >> 5, lane = tid & 31;
    const uint32_t sb = smem_u32(sm);

    // Q tiles (pre-split bf16)
    load_tile_split(sm, R_QH, R_QL,
                    g_qkvh + (size_t)gi0 * TDM + h * DH,
                    g_qkvl + (size_t)gi0 * TDM + h * DH, tid);

    const float Aref = g_A[h * SQ + gi0];
    const bool do_state = (Aref > -87.f);
    if (do_state) {  // split state fp32 -> Bh/Bl
        int r = tid >> 1, half = tid & 1;
        const float* sp = state + (size_t)h * DH * DH + (size_t)r * DH + half * 64;
        #pragma unroll
        for (int c = 0; c < 8; c++) {
            int u = half * 8 + c;
            float4 f0 = *(const float4*)(sp + c * 8);
            float4 f1 = *(const float4*)(sp + c * 8 + 4);
            uint4 hv, lv;
            hv.x = packbf(f0.x, f0.y); hv.y = packbf(f0.z, f0.w);
            hv.z = packbf(f1.x, f1.y); hv.w = packbf(f1.z, f1.w);
            lv.x = packbf(f0.x - bhi(f0.x), f0.y - bhi(f0.y));
            lv.y = packbf(f0.z - bhi(f0.z), f0.w - bhi(f0.w));
            lv.z = packbf(f1.x - bhi(f1.x), f1.y - bhi(f1.y));
            lv.w = packbf(f1.z - bhi(f1.z), f1.w - bhi(f1.w));
            int off = swoff(r, u);
            *(uint4*)(sm + R_BH + off) = hv;
            *(uint4*)(sm + R_BL + off) = lv;
        }
    }
    if (tid < 128) {
        float Ai = g_A[h * SQ + gi0 + tid];
        sEi[tid] = __expf(Ai - Aref);
        sE0[tid] = __expf(Ai);
    }
    __syncthreads();

    float out[16][4] = {};
    const int rA = w * 16 + (lane & 15);
    const int uA = lane >> 4;
    const int tr = (lane & 7) + (((lane >> 3) & 1) << 3);   // trans-B row
    const int tu = (lane >> 4) & 1;                          // trans-B unit
    const int kr = (lane & 7) + ((lane & 16) ? 8 : 0);       // non-trans B row
    const int ku = (lane >> 3) & 1;
    const int row0 = w * 16 + (lane >> 2);

    if (do_state) {  // out = Q @ state (3-pass), then scale rows by exp(A_i)
        #pragma unroll
        for (int k16 = 0; k16 < 8; k16++) {
            uint32_t ah[4], al[4];
            int aoff = swoff(rA, 2 * k16 + uA);
            ldsm4(ah[0], ah[1], ah[2], ah[3], sb + R_QH + aoff);
            ldsm4(al[0], al[1], al[2], al[3], sb + R_QL + aoff);
            #pragma unroll
            for (int en = 0; en < 8; en++) {
                int off = swoff(16 * k16 + tr, 2 * en + tu);
                uint32_t b0, b1, b2, b3;
                ldsm4t(b0, b1, b2, b3, sb + R_BH + off);
                mma16816(out[2*en],   ah[0], ah[1], ah[2], ah[3], b0, b1);
                mma16816(out[2*en+1], ah[0], ah[1], ah[2], ah[3], b2, b3);
                mma16816(out[2*en],   al[0], al[1], al[2], al[3], b0, b1);
                mma16816(out[2*en+1], al[0], al[1], al[2], al[3], b2, b3);
                ldsm4t(b0, b1, b2, b3, sb + R_BL + off);
                mma16816(out[2*en],   ah[0], ah[1], ah[2], ah[3], b0, b1);
                mma16816(out[2*en+1], ah[0], ah[1], ah[2], ah[3], b2, b3);
            }
        }
        float e0a = sE0[row0], e0b = sE0[row0 + 8];
        #pragma unroll
        for (int t = 0; t < 16; t++) {
            out[t][0] *= e0a; out[t][1] *= e0a;
            out[t][2] *= e0b; out[t][3] *= e0b;
        }
    }

    for (int bj = bi; bj >= 0; bj--) {
        const int gj0 = bj * 128;
        if (Aref - g_A[h * SQ + gj0 + 127] < -80.f) break;
        __syncthreads();   // prior consumers of B tiles done
        load_tile_split(sm, R_BH, R_BL,
                        g_qkvh + (size_t)gj0 * TDM + DM + h * DH,
                        g_qkvl + (size_t)gj0 * TDM + DM + h * DH, tid);   // K
        if (tid < 128) sFj[tid] = __expf(Aref - g_A[h * SQ + gj0 + tid]);
        __syncthreads();

        // S = Q K^T (3-pass)
        float s[16][4] = {};
        #pragma unroll
        for (int k16 = 0; k16 < 8; k16++) {
            uint32_t ah[4], al[4];
            int aoff = swoff(rA, 2 * k16 + uA);
            ldsm4(ah[0], ah[1], ah[2], ah[3], sb + R_QH + aoff);
            ldsm4(al[0], al[1], al[2], al[3], sb + R_QL + aoff);
            #pragma unroll
            for (int jn = 0; jn < 8; jn++) {
                int off = swoff(16 * jn + kr, 2 * k16 + ku);
                uint32_t b0, b1, b2, b3;
                ldsm4(b0, b1, b2, b3, sb + R_BH + off);
                mma16816(s[2*jn],   ah[0], ah[1], ah[2], ah[3], b0, b1);
                mma16816(s[2*jn+1], ah[0], ah[1], ah[2], ah[3], b2, b3);
                mma16816(s[2*jn],   al[0], al[1], al[2], al[3], b0, b1);
                mma16816(s[2*jn+1], al[0], al[1], al[2], al[3], b2, b3);
                ldsm4(b0, b1, b2, b3, sb + R_BL + off);
                mma16816(s[2*jn],   ah[0], ah[1], ah[2], ah[3], b0, b1);
                mma16816(s[2*jn+1], ah[0], ah[1], ah[2], ah[3], b2, b3);
            }
        }
        // decay + mask (fp32, in registers)
        {
            float ea = sEi[row0], eb = sEi[row0 + 8];
            bool diag = (bj == bi);
            #pragma unroll
            for (int t = 0; t < 16; t++) {
                int c0 = 8 * t + (lane & 3) * 2;
                float f0 = sFj[c0], f1 = sFj[c0 + 1];
                s[t][0] *= ea * f0; s[t][1] *= ea * f1;
                s[t][2] *= eb * f0; s[t][3] *= eb * f1;
                if (diag) {
                    if (c0     > row0)     s[t][0] = 0.f;
                    if (c0 + 1 > row0)     s[t][1] = 0.f;
                    if (c0     > row0 + 8) s[t][2] = 0.f;
                    if (c0 + 1 > row0 + 8) s[t][3] = 0.f;
                }
            }
        }
        __syncthreads();   // K reads done
        load_tile_split(sm, R_BH, R_BL,
                        g_qkvh + (size_t)gj0 * TDM + 2 * DM + h * DH,
                        g_qkvl + (size_t)gj0 * TDM + 2 * DM + h * DH, tid);  // V
        __syncthreads();

        // out += S @ V (3-pass: Sh.Vh, Sl.Vh, Sh.Vl); S fragments reused as A
        #pragma unroll
        for (int kk = 0; kk < 8; kk++) {
            const int t0 = 2 * kk, t1 = 2 * kk + 1;
            uint32_t ah[4], al[4];
            ah[0] = packbf(s[t0][0], s[t0][1]);
            ah[1] = packbf(s[t0][2], s[t0][3]);
            ah[2] = packbf(s[t1][0], s[t1][1]);
            ah[3] = packbf(s[t1][2], s[t1][3]);
            al[0] = packbf(s[t0][0] - bhi(s[t0][0]), s[t0][1] - bhi(s[t0][1]));
            al[1] = packbf(s[t0][2] - bhi(s[t0][2]), s[t0][3] - bhi(s[t0][3]));
            al[2] = packbf(s[t1][0] - bhi(s[t1][0]), s[t1][1] - bhi(s[t1][1]));
            al[3] = packbf(s[t1][2] - bhi(s[t1][2]), s[t1][3] - bhi(s[t1][3]));
            #pragma unroll
            for (int en = 0; en < 8; en++) {
                int off = swoff(16 * kk + tr, 2 * en + tu);
                uint32_t b0, b1, b2, b3;
                ldsm4t(b0, b1, b2, b3, sb + R_BH + off);
                mma16816(out[2*en],   ah[0], ah[1], ah[2], ah[3], b0, b1);
                mma16816(out[2*en+1], ah[0], ah[1], ah[2], ah[3], b2, b3);
                mma16816(out[2*en],   al[0], al[1], al[2], al[3], b0, b1);
                mma16816(out[2*en+1], al[0], al[1], al[2], al[3], b2, b3);
                ldsm4t(b0, b1, b2, b3, sb + R_BL + off);
                mma16816(out[2*en],   ah[0], ah[1], ah[2], ah[3], b0, b1);
                mma16816(out[2*en+1], ah[0], ah[1], ah[2], ah[3], b2, b3);
            }
        }
    }

    #pragma unroll
    for (int t = 0; t < 16; t++) {
        int c0 = 8 * t + (lane & 3) * 2;
        float* p = g_ret + (size_t)(gi0 + row0) * DM + h * DH + c0;
        *(float2*)p = make_float2(out[t][0], out[t][1]);
        *(float2*)(p + (size_t)8 * DM) = make_float2(out[t][2], out[t][3]);
    }
}

// ---------------- new_state ----------------
__global__ __launch_bounds__(256) void nstate_partial_kernel()
{
    const int ch = blockIdx.x, h = blockIdx.y;
    const int gi0 = ch * 128;
    const int tid = threadIdx.x;
    const int tx = tid & 15, ty = tid >> 4;
    float* out = g_nsp + (size_t)(h * 16 + ch) * DH * DH;

    float Alast = g_A[h * SQ + SQ - 1];
    if (Alast - g_A[h * SQ + gi0 + 127] < -80.f) {
        for (int idx = tid; idx < DH * DH; idx += 256) out[idx] = 0.f;
        return;
    }
    __shared__ float sK[16][SPAD];
    __shared__ float sV[16][SPAD];
    __shared__ float w[128];
    if (tid < 128) w[tid] = __expf(Alast - g_A[h * SQ + gi0 + tid]);
    __syncthreads();

    float acc[8][8] = {};
    for (int it = 0; it < 8; it++) {
        int i0 = gi0 + it * 16;
        #pragma unroll
        for (int q = 0; q < 2; q++) {
            int f = tid + 256 * q;
            int ir = f >> 5, d4 = (f & 31) * 4;
            float wi = w[it * 16 + ir];
            float4 kv = *(const float4*)(g_qkv + (size_t)(i0 + ir) * TDM + DM + h * DH + d4);
            float4 vv = *(const float4*)(g_qkv + (size_t)(i0 + ir) * TDM + 2 * DM + h * DH + d4);
            sK[ir][d4+0] = kv.x * wi; sK[ir][d4+1] = kv.y * wi;
            sK[ir][d4+2] = kv.z * wi; sK[ir][d4+3] = kv.w * wi;
            *(float4*)(&sV[ir][d4]) = vv;
        }
        __syncthreads();
        #pragma unroll
        for (int i = 0; i < 16; i++) {
            float4 a0 = *(const float4*)(&sK[i][ty*8]);
            float4 a1 = *(const float4*)(&sK[i][ty*8+4]);
            float4 b0 = *(const float4*)(&sV[i][tx*8]);
            float4 b1 = *(const float4*)(&sV[i][tx*8+4]);
            float av[8] = {a0.x,a0.y,a0.z,a0.w,a1.x,a1.y,a1.z,a1.w};
            float bv[8] = {b0.x,b0.y,b0.z,b0.w,b1.x,b1.y,b1.z,b1.w};
            #pragma unroll
            for (int r = 0; r < 8; r++)
                #pragma unroll
                for (int c = 0; c < 8; c++)
                    acc[r][c] = fmaf(av[r], bv[c], acc[r][c]);
        }
        __syncthreads();
    }
    #pragma unroll
    for (int r = 0; r < 8; r++)
        #pragma unroll
        for (int c = 0; c < 8; c++)
            out[(ty * 8 + r) * DH + tx * 8 + c] = acc[r][c];
}

__global__ __launch_bounds__(256) void nstate_reduce_kernel(const float* __restrict__ state,
                                                            float* __restrict__ outNS)
{
    int idx = blockIdx.x * 256 + threadIdx.x;
    int h = idx >> 14;
    float s = __expf(g_A[h * SQ + SQ - 1]) * state[idx];
    int de = idx & 16383;
    #pragma unroll
    for (int c = 0; c < 16; c++) s += g_nsp[(size_t)(h * 16 + c) * DH * DH + de];
    outNS[idx] = s;
}

// ---------------- group norm ----------------
__global__ __launch_bounds__(256) void gnorm_kernel(const float* __restrict__ gw,
                                                    const float* __restrict__ gb)
{
    int warp = (blockIdx.x * 256 + threadIdx.x) >> 5;
    int lane = threadIdx.x & 31;
    int i = warp >> 4, h = warp & 15;
    float* p = g_ret + (size_t)i * DM + h * DH;
    float v[4], s = 0.f;
    #pragma unroll
    for (int c = 0; c < 4; c++) { v[c] = p[lane + 32 * c]; s += v[c]; }
    #pragma unroll
    for (int o = 16; o; o >>= 1) s += __shfl_xor_sync(0xffffffffu, s, o);
    float mu = s * (1.f / 128.f), q = 0.f;
    #pragma unroll
    for (int c = 0; c < 4; c++) { float d = v[c] - mu; q = fmaf(d, d, q); }
    #pragma unroll
    for (int o = 16; o; o >>= 1) q += __shfl_xor_sync(0xffffffffu, q, o);
    float rs = rsqrtf(q * (1.f / 128.f) + 1e-5f);
    #pragma unroll
    for (int c = 0; c < 4; c++) {
        int ch = h * DH + lane + 32 * c;
        p[lane + 32 * c] = (v[c] - mu) * rs * gw[ch] + gb[ch];
    }
}

// ---------------- swish ----------------
__global__ __launch_bounds__(256) void swish_kernel()
{
    int idx = blockIdx.x * 256 + threadIdx.x;
    float g = g_u[idx];
    g_u[idx] = g / (1.f + __expf(-g)) * g_ret[idx];
}

extern "C" void kernel_launch(void* const* d_in, const int* in_sizes, int n_in,
                              void* d_out, int out_size)
{
    const float* x     = (const float*)d_in[0];
    const float* state = (const float*)d_in[1];
    const float* Wqkv  = (const float*)d_in[2];
    const float* Wa    = (const float*)d_in[3];
    const float* ba    = (const float*)d_in[4];
    const float* ab    = (const float*)d_in[5];
    const float* gw    = (const float*)d_in[6];
    const float* gb    = (const float*)d_in[7];
    const float* Wout  = (const float*)d_in[8];
    const float* Wgate = (const float*)d_in[9];
    const int*   offp  = (n_in > 10) ? (const int*)d_in[10] : nullptr;

    float* out   = (float*)d_out;
    float* outNS = out + (size_t)SQ * DM;

    float *qkv_p, *ret_p, *u_p;
    cudaGetSymbolAddress((void**)&qkv_p, g_qkv);
    cudaGetSymbolAddress((void**)&ret_p, g_ret);
    cudaGetSymbolAddress((void**)&u_p,   g_u);
    __nv_bfloat16 *xh,*xl,*Wqh,*Wql,*Wgh,*Wgl,*Woh,*Wol,*rh,*rl,*uh,*ul;
    cudaGetSymbolAddress((void**)&xh,  g_xh);  cudaGetSymbolAddress((void**)&xl,  g_xl);
    cudaGetSymbolAddress((void**)&Wqh, g_Wqh); cudaGetSymbolAddress((void**)&Wql, g_Wql);
    cudaGetSymbolAddress((void**)&Wgh, g_Wgh); cudaGetSymbolAddress((void**)&Wgl, g_Wgl);
    cudaGetSymbolAddress((void**)&Woh, g_Woh); cudaGetSymbolAddress((void**)&Wol, g_Wol);
    cudaGetSymbolAddress((void**)&rh,  g_rh);  cudaGetSymbolAddress((void**)&rl,  g_rl);
    cudaGetSymbolAddress((void**)&uh,  g_uh);  cudaGetSymbolAddress((void**)&ul,  g_ul);

    const int TG_SMEM = 65536;
    cudaFuncSetAttribute(tgemm, cudaFuncAttributeMaxDynamicSharedMemorySize, TG_SMEM);
    cudaFuncSetAttribute(retention_hmma, cudaFuncAttributeMaxDynamicSharedMemorySize, R_SMEM);

    split_kernel<<<SQ * DM / 1024, 256>>>(x, xh, xl);
    split_kernel<<<TDM * DM / 1024, 256>>>(Wqkv, Wqh, Wql);
    split_kernel<<<DM * DM / 1024, 256>>>(Wgate, Wgh, Wgl);
    split_kernel<<<DM * DM / 1024, 256>>>(Wout, Woh, Wol);

    tgemm<<<dim3(TDM/128, SQ/128), 256, TG_SMEM>>>(xh, xl, Wqh, Wql, qkv_p, TDM, DM);

    alpha_kernel<<<NH * SQ / 8, 256>>>(x, Wa, ba, ab);
    cumsum_kernel<<<NH, 256>>>();
    xpos_kernel<<<SQ, 64>>>(offp);
    retention_hmma<<<dim3(16, NH), 256, R_SMEM>>>(state);
    nstate_partial_kernel<<<dim3(16, NH), 256>>>();
    nstate_reduce_kernel<<<NH * DH * DH / 256, 256>>>(state, outNS);
    gnorm_kernel<<<SQ * NH / 8, 256>>>(gw, gb);

    split_kernel<<<SQ * DM / 1024, 256>>>(ret_p, rh, rl);
    tgemm<<<dim3(DM/128, SQ/128), 256, TG_SMEM>>>(rh, rl, Wgh, Wgl, u_p, DM, DM);
    swish_kernel<<<SQ * DM / 256, 256>>>();
    split_kernel<<<SQ * DM / 1024, 256>>>(u_p, uh, ul);
    tgemm<<<dim3(DM/128, SQ/128), 256, TG_SMEM>>>(uh, ul, Woh, Wol, out, DM, DM);
}

// round 11
// speedup vs baseline: 2.4727x; 1.3075x over previous
#include <cuda_runtime.h>
#include <cuda_bf16.h>
#include <cstdint>

#define SQ   2048
#define DM   2048
#define NH   16
#define DH   128
#define TDM  6144
#define SPAD 132

// fp32 scratch
__device__ float g_qkv[SQ * TDM];
__device__ float g_a[NH * SQ];
__device__ float g_A[NH * SQ];
__device__ float g_ret[SQ * DM];
__device__ float g_u[SQ * DM];
__device__ float g_nsp[NH * 16 * DH * DH];
// bf16 split scratch
__device__ __nv_bfloat16 g_xh[SQ*DM],  g_xl[SQ*DM];
__device__ __nv_bfloat16 g_Wqh[TDM*DM], g_Wql[TDM*DM];
__device__ __nv_bfloat16 g_Wgh[DM*DM], g_Wgl[DM*DM];
__device__ __nv_bfloat16 g_Woh[DM*DM], g_Wol[DM*DM];
__device__ __nv_bfloat16 g_rh[SQ*DM],  g_rl[SQ*DM];
__device__ __nv_bfloat16 g_uh[SQ*DM],  g_ul[SQ*DM];
__device__ __nv_bfloat16 g_qkvh[SQ*TDM], g_qkvl[SQ*TDM];

// ---------------- PTX helpers (sm_80-family, valid on bare sm_103) ----------------
__device__ __forceinline__ uint32_t smem_u32(const void* p) {
    uint32_t a;
    asm("{ .reg .u64 t; cvta.to.shared.u64 t, %1; cvt.u32.u64 %0, t; }" : "=r"(a) : "l"(p));
    return a;
}
__device__ __forceinline__ void ldsm4(uint32_t& r0, uint32_t& r1, uint32_t& r2, uint32_t& r3,
                                      uint32_t addr) {
    asm volatile("ldmatrix.sync.aligned.m8n8.x4.shared.b16 {%0,%1,%2,%3}, [%4];"
                 : "=r"(r0), "=r"(r1), "=r"(r2), "=r"(r3) : "r"(addr));
}
__device__ __forceinline__ void ldsm4t(uint32_t& r0, uint32_t& r1, uint32_t& r2, uint32_t& r3,
                                       uint32_t addr) {
    asm volatile("ldmatrix.sync.aligned.m8n8.x4.trans.shared.b16 {%0,%1,%2,%3}, [%4];"
                 : "=r"(r0), "=r"(r1), "=r"(r2), "=r"(r3) : "r"(addr));
}
__device__ __forceinline__ void mma16816(float* c, uint32_t a0, uint32_t a1, uint32_t a2,
                                         uint32_t a3, uint32_t b0, uint32_t b1) {
    asm volatile("mma.sync.aligned.m16n8k16.row.col.f32.bf16.bf16.f32 "
                 "{%0,%1,%2,%3}, {%4,%5,%6,%7}, {%8,%9}, {%0,%1,%2,%3};"
                 : "+f"(c[0]), "+f"(c[1]), "+f"(c[2]), "+f"(c[3])
                 : "r"(a0), "r"(a1), "r"(a2), "r"(a3), "r"(b0), "r"(b1));
}
__device__ __forceinline__ uint32_t packbf(float x, float y) {
    __nv_bfloat162 p; p.x = __float2bfloat16(x); p.y = __float2bfloat16(y);
    return *(uint32_t*)&p;
}
__device__ __forceinline__ float bhi(float v) {
    return __bfloat162float(__float2bfloat16(v));
}
// swizzled byte offset inside a 128x128 bf16 tile (256B rows, 16B units)
__device__ __forceinline__ int swoff(int row, int u) {
    return row * 256 + (((u & 8) | ((u ^ row) & 7)) << 4);
}

// ---------------- split fp32 -> (hi, lo) bf16 ----------------
__global__ __launch_bounds__(256) void split_kernel(const float* __restrict__ s,
                                                    __nv_bfloat16* __restrict__ h,
                                                    __nv_bfloat16* __restrict__ l)
{
    int i = blockIdx.x * 256 + threadIdx.x;
    float4 v = ((const float4*)s)[i];
    float h0 = bhi(v.x), h1 = bhi(v.y), h2 = bhi(v.z), h3 = bhi(v.w);
    ((uint32_t*)h)[2*i]   = packbf(v.x, v.y);
    ((uint32_t*)h)[2*i+1] = packbf(v.z, v.w);
    ((uint32_t*)l)[2*i]   = packbf(v.x - h0, v.y - h1);
    ((uint32_t*)l)[2*i+1] = packbf(v.z - h2, v.w - h3);
}

// ---------------- pipelined HMMA split-bf16 GEMM: C[M,N] = A[M,K] @ B[N,K]^T ----------------
// 128x128 CTA tile, K-chunk 64, 2-stage cp.async double buffer (2x4x16KB smem),
// 8 warps = 4x2 warp grid, warp tile 32x64. 3 passes: Ah*Bh, Ah*Bl, Al*Bh.
__global__ __launch_bounds__(256) void tgemm(const __nv_bfloat16* __restrict__ Ah,
                                             const __nv_bfloat16* __restrict__ Al,
                                             const __nv_bfloat16* __restrict__ Bh,
                                             const __nv_bfloat16* __restrict__ Bl,
                                             float* __restrict__ C, int N, int K)
{
    extern __shared__ char smem[];   // 2 stages x 4 tiles x 16 KB
    const int tid  = threadIdx.x;
    const int wid  = tid >> 5, lane = tid & 31;
    const int mw   = wid & 3, nw = wid >> 2;
    const int bm   = blockIdx.y * 128, bn = blockIdx.x * 128;
    const uint32_t sbase = smem_u32(smem);

    const int rA = mw * 32 + (lane & 15);
    const int uA = lane >> 4;
    const int rB = nw * 64 + (lane & 7) + ((lane & 16) ? 8 : 0);
    const int uB = (lane >> 3) & 1;

    const __nv_bfloat16* src[4] = { Ah + (size_t)bm * K, Al + (size_t)bm * K,
                                    Bh + (size_t)bn * K, Bl + (size_t)bn * K };
    const int lm = tid >> 3;
    const int lc = tid & 7;

    const int nchunk = K >> 6;

    auto issue = [&](int kc, int st) {
        #pragma unroll
        for (int t = 0; t < 16; t++) {
            const int tile = t >> 2;
            const int m = (t & 3) * 32 + lm;
            const __nv_bfloat16* gsrc = src[tile] + (size_t)m * K + kc * 64 + lc * 8;
            uint32_t dst = sbase + st * 65536 + tile * 16384 + m * 128 + ((lc ^ (m & 7)) << 4);
            asm volatile("cp.async.cg.shared.global [%0], [%1], 16;" :: "r"(dst), "l"(gsrc));
        }
        asm volatile("cp.async.commit_group;" ::: "memory");
    };

    float acc[2][8][4] = {};

    issue(0, 0);
    issue(1, 1);

    for (int kc = 0; kc < nchunk; kc++) {
        const int st = kc & 1;
        asm volatile("cp.async.wait_group 1;" ::: "memory");
        __syncthreads();

        const uint32_t stb = sbase + st * 65536;
        #pragma unroll
        for (int p = 0; p < 3; p++) {
            const uint32_t tA = stb + ((p == 2) ? 16384 : 0);
            const uint32_t tB = stb + ((p == 1) ? 49152 : 32768);
            #pragma unroll
            for (int k16 = 0; k16 < 4; k16++) {
                uint32_t a[2][4];
                #pragma unroll
                for (int t = 0; t < 2; t++) {
                    const int row = rA + t * 16;
                    ldsm4(a[t][0], a[t][1], a[t][2], a[t][3],
                          tA + row * 128 + (((2 * k16 + uA) ^ (row & 7)) << 4));
                }
                uint32_t b[8][2];
                #pragma unroll
                for (int j = 0; j < 4; j++) {
                    const int row = rB + j * 16;
                    uint32_t r0, r1, r2, r3;
                    ldsm4(r0, r1, r2, r3,
                          tB + row * 128 + (((2 * k16 + uB) ^ (row & 7)) << 4));
                    b[2*j][0] = r0; b[2*j][1] = r1;
                    b[2*j+1][0] = r2; b[2*j+1][1] = r3;
                }
                #pragma unroll
                for (int t = 0; t < 2; t++)
                    #pragma unroll
                    for (int s = 0; s < 8; s++)
                        mma16816(acc[t][s], a[t][0], a[t][1], a[t][2], a[t][3],
                                 b[s][0], b[s][1]);
            }
        }
        __syncthreads();
        if (kc + 2 < nchunk) issue(kc + 2, st);
        else asm volatile("cp.async.commit_group;" ::: "memory");
    }

    float* Cw = C + (size_t)(bm + mw * 32 + (lane >> 2)) * N + bn + nw * 64 + (lane & 3) * 2;
    #pragma unroll
    for (int t = 0; t < 2; t++)
        #pragma unroll
        for (int s = 0; s < 8; s++) {
            *(float2*)(Cw + (size_t)(t * 16)     * N + s * 8) = make_float2(acc[t][s][0], acc[t][s][1]);
            *(float2*)(Cw + (size_t)(t * 16 + 8) * N + s * 8) = make_float2(acc[t][s][2], acc[t][s][3]);
        }
}

// ---------------- alpha ----------------
__global__ __launch_bounds__(256) void alpha_kernel(const float* __restrict__ x,
                                                    const float* __restrict__ Wa,
                                                    const float* __restrict__ ba,
                                                    const float* __restrict__ ab)
{
    int warp = (blockIdx.x * 256 + threadIdx.x) >> 5;
    int lane = threadIdx.x & 31;
    int h = warp >> 11, i = warp & 2047;
    const float* xr = x + (size_t)i * DM;
    const float* wr = Wa + (size_t)h * DM;
    float s = 0.f;
    #pragma unroll 8
    for (int t = lane; t < DM; t += 32) s = fmaf(xr[t], wr[t], s);
    #pragma unroll
    for (int o = 16; o; o >>= 1) s += __shfl_xor_sync(0xffffffffu, s, o);
    if (lane == 0) {
        float sig = 1.f / (1.f + __expf(-(s + ba[h])));
        g_a[h * SQ + i] = ab[h] * 8.f * sig;
    }
}

// ---------------- cumsum ----------------
__global__ __launch_bounds__(256) void cumsum_kernel()
{
    int h = blockIdx.x, t = threadIdx.x;
    __shared__ float tot[256];
    float v[8], run = 0.f;
    #pragma unroll
    for (int c = 0; c < 8; c++) { run += g_a[h * SQ + t * 8 + c]; v[c] = run; }
    tot[t] = run;
    __syncthreads();
    for (int off = 1; off < 256; off <<= 1) {
        float add = (t >= off) ? tot[t - off] : 0.f;
        __syncthreads();
        tot[t] += add;
        __syncthreads();
    }
    float base = (t > 0) ? tot[t - 1] : 0.f;
    #pragma unroll
    for (int c = 0; c < 8; c++) g_A[h * SQ + t * 8 + c] = v[c] + base;
}

// ---------------- xpos: rotate q,k; write fp32 + split bf16 q,k,v ----------------
__global__ __launch_bounds__(64) void xpos_kernel(const int* __restrict__ offp)
{
    int i = blockIdx.x, j = threadIdx.x;
    float pos = (float)(i + (offp ? *offp : 0));
    float ps  = pos * (1.f / 512.f);
    float freq = exp2f((float)j * (-13.287712379549449f / 64.f));
    float ang  = pos * freq;
    float sn = sinf(ang), cs = cosf(ang);
    float zeta = ((float)(2 * j) + 51.2f) * (1.f / 179.2f);
    float e = log2f(zeta) * ps;
    float scq = exp2f(e), sck0 = exp2f(-e);

    #pragma unroll 4
    for (int h = 0; h < NH; h++) {
        float sck = sck0 * (1.f - __expf(g_a[h * SQ + i]));
        size_t base = (size_t)i * TDM + h * DH;
        float* qp = g_qkv + base;
        float* kp = qp + DM;
        float* vp = qp + 2 * DM;
        float q1 = qp[j], q2 = qp[j + 64];
        float k1 = kp[j], k2 = kp[j + 64];
        float qa = (q1 * cs - q2 * sn) * scq;
        float qb = (q2 * cs + q1 * sn) * scq;
        float ka = (k1 * cs - k2 * sn) * sck;
        float kb = (k2 * cs + k1 * sn) * sck;
        qp[j] = qa; qp[j + 64] = qb;
        kp[j] = ka; kp[j + 64] = kb;
        float va = vp[j], vb = vp[j + 64];
        __nv_bfloat16* ph = g_qkvh + base;
        __nv_bfloat16* pl = g_qkvl + base;
        ph[j]      = __float2bfloat16(qa); pl[j]      = __float2bfloat16(qa - bhi(qa));
        ph[j + 64] = __float2bfloat16(qb); pl[j + 64] = __float2bfloat16(qb - bhi(qb));
        ph[DM + j]      = __float2bfloat16(ka); pl[DM + j]      = __float2bfloat16(ka - bhi(ka));
        ph[DM + j + 64] = __float2bfloat16(kb); pl[DM + j + 64] = __float2bfloat16(kb - bhi(kb));
        ph[2*DM + j]      = __float2bfloat16(va); pl[2*DM + j]      = __float2bfloat16(va - bhi(va));
        ph[2*DM + j + 64] = __float2bfloat16(vb); pl[2*DM + j + 64] = __float2bfloat16(vb - bhi(vb));
    }
}

// ---------------- HMMA retention ----------------
#define R_QH 0
#define R_QL 32768
#define R_BH 65536
#define R_BL 98304
#define R_EI 131072
#define R_FJ 131584
#define R_E0 132096
#define R_SMEM 132608

__device__ __forceinline__ void load_tile_split(char* sm, int dh, int dl,
                                                const __nv_bfloat16* srch,
                                                const __nv_bfloat16* srcl,
                                                int tid)
{
    int r = tid >> 1, half = tid & 1;
    const __nv_bfloat16* sh = srch + (size_t)r * TDM + half * 64;
    const __nv_bfloat16* sl = srcl + (size_t)r * TDM + half * 64;
    #pragma unroll
    for (int c = 0; c < 8; c++) {
        int u = half * 8 + c;
        int off = swoff(r, u);
        *(uint4*)(sm + dh + off) = *(const uint4*)(sh + c * 8);
        *(uint4*)(sm + dl + off) = *(const uint4*)(sl + c * 8);
    }
}

__global__ __launch_bounds__(256) void retention_hmma(const float* __restrict__ state)
{
    extern __shared__ char sm[];
    float* sEi = (float*)(sm + R_EI);
    float* sFj = (float*)(sm + R_FJ);
    float* sE0 = (float*)(sm + R_E0);

    const int h = blockIdx.y, bi = 15 - blockIdx.x;
    const int gi0 = bi * 128;
    const int tid = threadIdx.x;
    const int w = tid >> 5, lane = tid & 31;
    const uint32_t sb = smem_u32(sm);

    load_tile_split(sm, R_QH, R_QL,
                    g_qkvh + (size_t)gi0 * TDM + h * DH,
                    g_qkvl + (size_t)gi0 * TDM + h * DH, tid);

    const float Aref = g_A[h * SQ + gi0];
    const bool do_state = (Aref > -87.f);
    if (do_state) {
        int r = tid >> 1, half = tid & 1;
        const float* sp = state + (size_t)h * DH * DH + (size_t)r * DH + half * 64;
        #pragma unroll
        for (int c = 0; c < 8; c++) {
            int u = half * 8 + c;
            float4 f0 = *(const float4*)(sp + c * 8);
            float4 f1 = *(const float4*)(sp + c * 8 + 4);
            uint4 hv, lv;
            hv.x = packbf(f0.x, f0.y); hv.y = packbf(f0.z, f0.w);
            hv.z = packbf(f1.x, f1.y); hv.w = packbf(f1.z, f1.w);
            lv.x = packbf(f0.x - bhi(f0.x), f0.y - bhi(f0.y));
            lv.y = packbf(f0.z - bhi(f0.z), f0.w - bhi(f0.w));
            lv.z = packbf(f1.x - bhi(f1.x), f1.y - bhi(f1.y));
            lv.w = packbf(f1.z - bhi(f1.z), f1.w - bhi(f1.w));
            int off = swoff(r, u);
            *(uint4*)(sm + R_BH + off) = hv;
            *(uint4*)(sm + R_BL + off) = lv;
        }
    }
    if (tid < 128) {
        float Ai = g_A[h * SQ + gi0 + tid];
        sEi[tid] = __expf(Ai - Aref);
        sE0[tid] = __expf(Ai);
    }
    __syncthreads();

    float out[16][4] = {};
    const int rA = w * 16 + (lane & 15);
    const int uA = lane >> 4;
    const int tr = (lane & 7) + (((lane >> 3) & 1) << 3);
    const int tu = (lane >> 4) & 1;
    const int kr = (lane & 7) + ((lane & 16) ? 8 : 0);
    const int ku = (lane >> 3) & 1;
    const int row0 = w * 16 + (lane >> 2);

    if (do_state) {
        #pragma unroll
        for (int k16 = 0; k16 < 8; k16++) {
            uint32_t ah[4], al[4];
            int aoff = swoff(rA, 2 * k16 + uA);
            ldsm4(ah[0], ah[1], ah[2], ah[3], sb + R_QH + aoff);
            ldsm4(al[0], al[1], al[2], al[3], sb + R_QL + aoff);
            #pragma unroll
            for (int en = 0; en < 8; en++) {
                int off = swoff(16 * k16 + tr, 2 * en + tu);
                uint32_t b0, b1, b2, b3;
                ldsm4t(b0, b1, b2, b3, sb + R_BH + off);
                mma16816(out[2*en],   ah[0], ah[1], ah[2], ah[3], b0, b1);
                mma16816(out[2*en+1], ah[0], ah[1], ah[2], ah[3], b2, b3);
                mma16816(out[2*en],   al[0], al[1], al[2], al[3], b0, b1);
                mma16816(out[2*en+1], al[0], al[1], al[2], al[3], b2, b3);
                ldsm4t(b0, b1, b2, b3, sb + R_BL + off);
                mma16816(out[2*en],   ah[0], ah[1], ah[2], ah[3], b0, b1);
                mma16816(out[2*en+1], ah[0], ah[1], ah[2], ah[3], b2, b3);
            }
        }
        float e0a = sE0[row0], e0b = sE0[row0 + 8];
        #pragma unroll
        for (int t = 0; t < 16; t++) {
            out[t][0] *= e0a; out[t][1] *= e0a;
            out[t][2] *= e0b; out[t][3] *= e0b;
        }
    }

    for (int bj = bi; bj >= 0; bj--) {
        const int gj0 = bj * 128;
        if (Aref - g_A[h * SQ + gj0 + 127] < -80.f) break;
        __syncthreads();
        load_tile_split(sm, R_BH, R_BL,
                        g_qkvh + (size_t)gj0 * TDM + DM + h * DH,
                        g_qkvl + (size_t)gj0 * TDM + DM + h * DH, tid);   // K
        if (tid < 128) sFj[tid] = __expf(Aref - g_A[h * SQ + gj0 + tid]);
        __syncthreads();

        float s[16][4] = {};
        #pragma unroll
        for (int k16 = 0; k16 < 8; k16++) {
            uint32_t ah[4], al[4];
            int aoff = swoff(rA, 2 * k16 + uA);
            ldsm4(ah[0], ah[1], ah[2], ah[3], sb + R_QH + aoff);
            ldsm4(al[0], al[1], al[2], al[3], sb + R_QL + aoff);
            #pragma unroll
            for (int jn = 0; jn < 8; jn++) {
                int off = swoff(16 * jn + kr, 2 * k16 + ku);
                uint32_t b0, b1, b2, b3;
                ldsm4(b0, b1, b2, b3, sb + R_BH + off);
                mma16816(s[2*jn],   ah[0], ah[1], ah[2], ah[3], b0, b1);
                mma16816(s[2*jn+1], ah[0], ah[1], ah[2], ah[3], b2, b3);
                mma16816(s[2*jn],   al[0], al[1], al[2], al[3], b0, b1);
                mma16816(s[2*jn+1], al[0], al[1], al[2], al[3], b2, b3);
                ldsm4(b0, b1, b2, b3, sb + R_BL + off);
                mma16816(s[2*jn],   ah[0], ah[1], ah[2], ah[3], b0, b1);
                mma16816(s[2*jn+1], ah[0], ah[1], ah[2], ah[3], b2, b3);
            }
        }
        {
            float ea = sEi[row0], eb = sEi[row0 + 8];
            bool diag = (bj == bi);
            #pragma unroll
            for (int t = 0; t < 16; t++) {
                int c0 = 8 * t + (lane & 3) * 2;
                float f0 = sFj[c0], f1 = sFj[c0 + 1];
                s[t][0] *= ea * f0; s[t][1] *= ea * f1;
                s[t][2] *= eb * f0; s[t][3] *= eb * f1;
                if (diag) {
                    if (c0     > row0)     s[t][0] = 0.f;
                    if (c0 + 1 > row0)     s[t][1] = 0.f;
                    if (c0     > row0 + 8) s[t][2] = 0.f;
                    if (c0 + 1 > row0 + 8) s[t][3] = 0.f;
                }
            }
        }
        __syncthreads();
        load_tile_split(sm, R_BH, R_BL,
                        g_qkvh + (size_t)gj0 * TDM + 2 * DM + h * DH,
                        g_qkvl + (size_t)gj0 * TDM + 2 * DM + h * DH, tid);  // V
        __syncthreads();

        #pragma unroll
        for (int kk = 0; kk < 8; kk++) {
            const int t0 = 2 * kk, t1 = 2 * kk + 1;
            uint32_t ah[4], al[4];
            ah[0] = packbf(s[t0][0], s[t0][1]);
            ah[1] = packbf(s[t0][2], s[t0][3]);
            ah[2] = packbf(s[t1][0], s[t1][1]);
            ah[3] = packbf(s[t1][2], s[t1][3]);
            al[0] = packbf(s[t0][0] - bhi(s[t0][0]), s[t0][1] - bhi(s[t0][1]));
            al[1] = packbf(s[t0][2] - bhi(s[t0][2]), s[t0][3] - bhi(s[t0][3]));
            al[2] = packbf(s[t1][0] - bhi(s[t1][0]), s[t1][1] - bhi(s[t1][1]));
            al[3] = packbf(s[t1][2] - bhi(s[t1][2]), s[t1][3] - bhi(s[t1][3]));
            #pragma unroll
            for (int en = 0; en < 8; en++) {
                int off = swoff(16 * kk + tr, 2 * en + tu);
                uint32_t b0, b1, b2, b3;
                ldsm4t(b0, b1, b2, b3, sb + R_BH + off);
                mma16816(out[2*en],   ah[0], ah[1], ah[2], ah[3], b0, b1);
                mma16816(out[2*en+1], ah[0], ah[1], ah[2], ah[3], b2, b3);
                mma16816(out[2*en],   al[0], al[1], al[2], al[3], b0, b1);
                mma16816(out[2*en+1], al[0], al[1], al[2], al[3], b2, b3);
                ldsm4t(b0, b1, b2, b3, sb + R_BL + off);
                mma16816(out[2*en],   ah[0], ah[1], ah[2], ah[3], b0, b1);
                mma16816(out[2*en+1], ah[0], ah[1], ah[2], ah[3], b2, b3);
            }
        }
    }

    #pragma unroll
    for (int t = 0; t < 16; t++) {
        int c0 = 8 * t + (lane & 3) * 2;
        float* p = g_ret + (size_t)(gi0 + row0) * DM + h * DH + c0;
        *(float2*)p = make_float2(out[t][0], out[t][1]);
        *(float2*)(p + (size_t)8 * DM) = make_float2(out[t][2], out[t][3]);
    }
}

// ---------------- new_state ----------------
__global__ __launch_bounds__(256) void nstate_partial_kernel()
{
    const int ch = blockIdx.x, h = blockIdx.y;
    const int gi0 = ch * 128;
    const int tid = threadIdx.x;
    const int tx = tid & 15, ty = tid >> 4;
    float* out = g_nsp + (size_t)(h * 16 + ch) * DH * DH;

    float Alast = g_A[h * SQ + SQ - 1];
    if (Alast - g_A[h * SQ + gi0 + 127] < -80.f) {
        for (int idx = tid; idx < DH * DH; idx += 256) out[idx] = 0.f;
        return;
    }
    __shared__ float sK[16][SPAD];
    __shared__ float sV[16][SPAD];
    __shared__ float w[128];
    if (tid < 128) w[tid] = __expf(Alast - g_A[h * SQ + gi0 + tid]);
    __syncthreads();

    float acc[8][8] = {};
    for (int it = 0; it < 8; it++) {
        int i0 = gi0 + it * 16;
        #pragma unroll
        for (int q = 0; q < 2; q++) {
            int f = tid + 256 * q;
            int ir = f >> 5, d4 = (f & 31) * 4;
            float wi = w[it * 16 + ir];
            float4 kv = *(const float4*)(g_qkv + (size_t)(i0 + ir) * TDM + DM + h * DH + d4);
            float4 vv = *(const float4*)(g_qkv + (size_t)(i0 + ir) * TDM + 2 * DM + h * DH + d4);
            sK[ir][d4+0] = kv.x * wi; sK[ir][d4+1] = kv.y * wi;
            sK[ir][d4+2] = kv.z * wi; sK[ir][d4+3] = kv.w * wi;
            *(float4*)(&sV[ir][d4]) = vv;
        }
        __syncthreads();
        #pragma unroll
        for (int i = 0; i < 16; i++) {
            float4 a0 = *(const float4*)(&sK[i][ty*8]);
            float4 a1 = *(const float4*)(&sK[i][ty*8+4]);
            float4 b0 = *(const float4*)(&sV[i][tx*8]);
            float4 b1 = *(const float4*)(&sV[i][tx*8+4]);
            float av[8] = {a0.x,a0.y,a0.z,a0.w,a1.x,a1.y,a1.z,a1.w};
            float bv[8] = {b0.x,b0.y,b0.z,b0.w,b1.x,b1.y,b1.z,b1.w};
            #pragma unroll
            for (int r = 0; r < 8; r++)
                #pragma unroll
                for (int c = 0; c < 8; c++)
                    acc[r][c] = fmaf(av[r], bv[c], acc[r][c]);
        }
        __syncthreads();
    }
    #pragma unroll
    for (int r = 0; r < 8; r++)
        #pragma unroll
        for (int c = 0; c < 8; c++)
            out[(ty * 8 + r) * DH + tx * 8 + c] = acc[r][c];
}

__global__ __launch_bounds__(256) void nstate_reduce_kernel(const float* __restrict__ state,
                                                            float* __restrict__ outNS)
{
    int idx = blockIdx.x * 256 + threadIdx.x;
    int h = idx >> 14;
    float s = __expf(g_A[h * SQ + SQ - 1]) * state[idx];
    int de = idx & 16383;
    #pragma unroll
    for (int c = 0; c < 16; c++) s += g_nsp[(size_t)(h * 16 + c) * DH * DH + de];
    outNS[idx] = s;
}

// ---------------- group norm (writes fp32 g_ret + bf16 split rh/rl) ----------------
__global__ __launch_bounds__(256) void gnorm_kernel(const float* __restrict__ gw,
                                                    const float* __restrict__ gb)
{
    int warp = (blockIdx.x * 256 + threadIdx.x) >> 5;
    int lane = threadIdx.x & 31;
    int i = warp >> 4, h = warp & 15;
    float* p = g_ret + (size_t)i * DM + h * DH;
    float v[4], s = 0.f;
    #pragma unroll
    for (int c = 0; c < 4; c++) { v[c] = p[lane + 32 * c]; s += v[c]; }
    #pragma unroll
    for (int o = 16; o; o >>= 1) s += __shfl_xor_sync(0xffffffffu, s, o);
    float mu = s * (1.f / 128.f), q = 0.f;
    #pragma unroll
    for (int c = 0; c < 4; c++) { float d = v[c] - mu; q = fmaf(d, d, q); }
    #pragma unroll
    for (int o = 16; o; o >>= 1) q += __shfl_xor_sync(0xffffffffu, q, o);
    float rs = rsqrtf(q * (1.f / 128.f) + 1e-5f);
    #pragma unroll
    for (int c = 0; c < 4; c++) {
        int ch = h * DH + lane + 32 * c;
        float val = (v[c] - mu) * rs * gw[ch] + gb[ch];
        p[lane + 32 * c] = val;
        size_t gi = (size_t)i * DM + ch;
        g_rh[gi] = __float2bfloat16(val);
        g_rl[gi] = __float2bfloat16(val - bhi(val));
    }
}

// ---------------- swish: uh/ul = split(swish(u) * ret) ----------------
__global__ __launch_bounds__(256) void swish_kernel()
{
    int i = blockIdx.x * 256 + threadIdx.x;
    float4 g = ((const float4*)g_u)[i];
    float4 r = ((const float4*)g_ret)[i];
    float v0 = g.x / (1.f + __expf(-g.x)) * r.x;
    float v1 = g.y / (1.f + __expf(-g.y)) * r.y;
    float v2 = g.z / (1.f + __expf(-g.z)) * r.z;
    float v3 = g.w / (1.f + __expf(-g.w)) * r.w;
    ((uint32_t*)g_uh)[2*i]   = packbf(v0, v1);
    ((uint32_t*)g_uh)[2*i+1] = packbf(v2, v3);
    ((uint32_t*)g_ul)[2*i]   = packbf(v0 - bhi(v0), v1 - bhi(v1));
    ((uint32_t*)g_ul)[2*i+1] = packbf(v2 - bhi(v2), v3 - bhi(v3));
}

extern "C" void kernel_launch(void* const* d_in, const int* in_sizes, int n_in,
                              void* d_out, int out_size)
{
    const float* x     = (const float*)d_in[0];
    const float* state = (const float*)d_in[1];
    const float* Wqkv  = (const float*)d_in[2];
    const float* Wa    = (const float*)d_in[3];
    const float* ba    = (const float*)d_in[4];
    const float* ab    = (const float*)d_in[5];
    const float* gw    = (const float*)d_in[6];
    const float* gb    = (const float*)d_in[7];
    const float* Wout  = (const float*)d_in[8];
    const float* Wgate = (const float*)d_in[9];
    const int*   offp  = (n_in > 10) ? (const int*)d_in[10] : nullptr;

    float* out   = (float*)d_out;
    float* outNS = out + (size_t)SQ * DM;

    float *qkv_p, *u_p;
    cudaGetSymbolAddress((void**)&qkv_p, g_qkv);
    cudaGetSymbolAddress((void**)&u_p,   g_u);
    __nv_bfloat16 *xh,*xl,*Wqh,*Wql,*Wgh,*Wgl,*Woh,*Wol,*rh,*rl,*uh,*ul;
    cudaGetSymbolAddress((void**)&xh,  g_xh);  cudaGetSymbolAddress((void**)&xl,  g_xl);
    cudaGetSymbolAddress((void**)&Wqh, g_Wqh); cudaGetSymbolAddress((void**)&Wql, g_Wql);
    cudaGetSymbolAddress((void**)&Wgh, g_Wgh); cudaGetSymbolAddress((void**)&Wgl, g_Wgl);
    cudaGetSymbolAddress((void**)&Woh, g_Woh); cudaGetSymbolAddress((void**)&Wol, g_Wol);
    cudaGetSymbolAddress((void**)&rh,  g_rh);  cudaGetSymbolAddress((void**)&rl,  g_rl);
    cudaGetSymbolAddress((void**)&uh,  g_uh);  cudaGetSymbolAddress((void**)&ul,  g_ul);

    const int TG_SMEM = 131072;
    cudaFuncSetAttribute(tgemm, cudaFuncAttributeMaxDynamicSharedMemorySize, TG_SMEM);
    cudaFuncSetAttribute(retention_hmma, cudaFuncAttributeMaxDynamicSharedMemorySize, R_SMEM);

    split_kernel<<<SQ * DM / 1024, 256>>>(x, xh, xl);
    split_kernel<<<TDM * DM / 1024, 256>>>(Wqkv, Wqh, Wql);
    split_kernel<<<DM * DM / 1024, 256>>>(Wgate, Wgh, Wgl);
    split_kernel<<<DM * DM / 1024, 256>>>(Wout, Woh, Wol);

    tgemm<<<dim3(TDM/128, SQ/128), 256, TG_SMEM>>>(xh, xl, Wqh, Wql, qkv_p, TDM, DM);

    alpha_kernel<<<NH * SQ / 8, 256>>>(x, Wa, ba, ab);
    cumsum_kernel<<<NH, 256>>>();
    xpos_kernel<<<SQ, 64>>>(offp);
    retention_hmma<<<dim3(16, NH), 256, R_SMEM>>>(state);
    nstate_partial_kernel<<<dim3(16, NH), 256>>>();
    nstate_reduce_kernel<<<NH * DH * DH / 256, 256>>>(state, outNS);
    gnorm_kernel<<<SQ * NH / 8, 256>>>(gw, gb);

    tgemm<<<dim3(DM/128, SQ/128), 256, TG_SMEM>>>(rh, rl, Wgh, Wgl, u_p, DM, DM);
    swish_kernel<<<SQ * DM / 1024, 256>>>();
    tgemm<<<dim3(DM/128, SQ/128), 256, TG_SMEM>>>(uh, ul, Woh, Wol, out, DM, DM);
}

// round 12
// speedup vs baseline: 2.5209x; 1.0195x over previous
#include <cuda_runtime.h>
#include <cuda_bf16.h>
#include <cstdint>

#define SQ   2048
#define DM   2048
#define NH   16
#define DH   128
#define TDM  6144
#define SPAD 132

// fp32 scratch
__device__ float g_qkv[SQ * TDM];
__device__ float g_a[NH * SQ];
__device__ float g_A[NH * SQ];
__device__ float g_ret[SQ * DM];
__device__ float g_u[SQ * DM];
__device__ float g_nsp[NH * 16 * DH * DH];
// bf16 split scratch
__device__ __nv_bfloat16 g_xh[SQ*DM],  g_xl[SQ*DM];
__device__ __nv_bfloat16 g_Wqh[TDM*DM], g_Wql[TDM*DM];
__device__ __nv_bfloat16 g_Wgh[DM*DM], g_Wgl[DM*DM];
__device__ __nv_bfloat16 g_Woh[DM*DM], g_Wol[DM*DM];
__device__ __nv_bfloat16 g_rh[SQ*DM],  g_rl[SQ*DM];
__device__ __nv_bfloat16 g_uh[SQ*DM],  g_ul[SQ*DM];
__device__ __nv_bfloat16 g_qkvh[SQ*TDM], g_qkvl[SQ*TDM];

// ---------------- PTX helpers (sm_80-family, valid on bare sm_103) ----------------
__device__ __forceinline__ uint32_t smem_u32(const void* p) {
    uint32_t a;
    asm("{ .reg .u64 t; cvta.to.shared.u64 t, %1; cvt.u32.u64 %0, t; }" : "=r"(a) : "l"(p));
    return a;
}
__device__ __forceinline__ void ldsm4(uint32_t& r0, uint32_t& r1, uint32_t& r2, uint32_t& r3,
                                      uint32_t addr) {
    asm volatile("ldmatrix.sync.aligned.m8n8.x4.shared.b16 {%0,%1,%2,%3}, [%4];"
                 : "=r"(r0), "=r"(r1), "=r"(r2), "=r"(r3) : "r"(addr));
}
__device__ __forceinline__ void ldsm4t(uint32_t& r0, uint32_t& r1, uint32_t& r2, uint32_t& r3,
                                       uint32_t addr) {
    asm volatile("ldmatrix.sync.aligned.m8n8.x4.trans.shared.b16 {%0,%1,%2,%3}, [%4];"
                 : "=r"(r0), "=r"(r1), "=r"(r2), "=r"(r3) : "r"(addr));
}
__device__ __forceinline__ void mma16816(float* c, uint32_t a0, uint32_t a1, uint32_t a2,
                                         uint32_t a3, uint32_t b0, uint32_t b1) {
    asm volatile("mma.sync.aligned.m16n8k16.row.col.f32.bf16.bf16.f32 "
                 "{%0,%1,%2,%3}, {%4,%5,%6,%7}, {%8,%9}, {%0,%1,%2,%3};"
                 : "+f"(c[0]), "+f"(c[1]), "+f"(c[2]), "+f"(c[3])
                 : "r"(a0), "r"(a1), "r"(a2), "r"(a3), "r"(b0), "r"(b1));
}
__device__ __forceinline__ uint32_t packbf(float x, float y) {
    __nv_bfloat162 p; p.x = __float2bfloat16(x); p.y = __float2bfloat16(y);
    return *(uint32_t*)&p;
}
__device__ __forceinline__ float bhi(float v) {
    return __bfloat162float(__float2bfloat16(v));
}
// swizzled byte offset inside a 128x128 bf16 tile (256B rows, 16B units)
__device__ __forceinline__ int swoff(int row, int u) {
    return row * 256 + (((u & 8) | ((u ^ row) & 7)) << 4);
}

// ---------------- split fp32 -> (hi, lo) bf16 ----------------
__global__ __launch_bounds__(256) void split_kernel(const float* __restrict__ s,
                                                    __nv_bfloat16* __restrict__ h,
                                                    __nv_bfloat16* __restrict__ l)
{
    int i = blockIdx.x * 256 + threadIdx.x;
    float4 v = ((const float4*)s)[i];
    float h0 = bhi(v.x), h1 = bhi(v.y), h2 = bhi(v.z), h3 = bhi(v.w);
    ((uint32_t*)h)[2*i]   = packbf(v.x, v.y);
    ((uint32_t*)h)[2*i+1] = packbf(v.z, v.w);
    ((uint32_t*)l)[2*i]   = packbf(v.x - h0, v.y - h1);
    ((uint32_t*)l)[2*i+1] = packbf(v.z - h2, v.w - h3);
}

// ---------------- pipelined HMMA split-bf16 GEMM (3-stage cp.async) ----------------
__global__ __launch_bounds__(256) void tgemm(const __nv_bfloat16* __restrict__ Ah,
                                             const __nv_bfloat16* __restrict__ Al,
                                             const __nv_bfloat16* __restrict__ Bh,
                                             const __nv_bfloat16* __restrict__ Bl,
                                             float* __restrict__ C, int N, int K)
{
    extern __shared__ char smem[];   // 3 stages x 4 tiles x 16 KB
    const int tid  = threadIdx.x;
    const int wid  = tid >> 5, lane = tid & 31;
    const int mw   = wid & 3, nw = wid >> 2;
    const int bm   = blockIdx.y * 128, bn = blockIdx.x * 128;
    const uint32_t sbase = smem_u32(smem);

    const int rA = mw * 32 + (lane & 15);
    const int uA = lane >> 4;
    const int rB = nw * 64 + (lane & 7) + ((lane & 16) ? 8 : 0);
    const int uB = (lane >> 3) & 1;

    const __nv_bfloat16* src[4] = { Ah + (size_t)bm * K, Al + (size_t)bm * K,
                                    Bh + (size_t)bn * K, Bl + (size_t)bn * K };
    const int lm = tid >> 3;
    const int lc = tid & 7;

    const int nchunk = K >> 6;

    auto issue = [&](int kc, int st) {
        #pragma unroll
        for (int t = 0; t < 16; t++) {
            const int tile = t >> 2;
            const int m = (t & 3) * 32 + lm;
            const __nv_bfloat16* gsrc = src[tile] + (size_t)m * K + kc * 64 + lc * 8;
            uint32_t dst = sbase + st * 65536 + tile * 16384 + m * 128 + ((lc ^ (m & 7)) << 4);
            asm volatile("cp.async.cg.shared.global [%0], [%1], 16;" :: "r"(dst), "l"(gsrc));
        }
        asm volatile("cp.async.commit_group;" ::: "memory");
    };

    float acc[2][8][4] = {};

    issue(0, 0);
    issue(1, 1);
    issue(2, 2);

    int st = 0;
    for (int kc = 0; kc < nchunk; kc++) {
        asm volatile("cp.async.wait_group 2;" ::: "memory");
        __syncthreads();

        const uint32_t stb = sbase + st * 65536;
        #pragma unroll
        for (int p = 0; p < 3; p++) {
            const uint32_t tA = stb + ((p == 2) ? 16384 : 0);
            const uint32_t tB = stb + ((p == 1) ? 49152 : 32768);
            #pragma unroll
            for (int k16 = 0; k16 < 4; k16++) {
                uint32_t a[2][4];
                #pragma unroll
                for (int t = 0; t < 2; t++) {
                    const int row = rA + t * 16;
                    ldsm4(a[t][0], a[t][1], a[t][2], a[t][3],
                          tA + row * 128 + (((2 * k16 + uA) ^ (row & 7)) << 4));
                }
                uint32_t b[8][2];
                #pragma unroll
                for (int j = 0; j < 4; j++) {
                    const int row = rB + j * 16;
                    uint32_t r0, r1, r2, r3;
                    ldsm4(r0, r1, r2, r3,
                          tB + row * 128 + (((2 * k16 + uB) ^ (row & 7)) << 4));
                    b[2*j][0] = r0; b[2*j][1] = r1;
                    b[2*j+1][0] = r2; b[2*j+1][1] = r3;
                }
                #pragma unroll
                for (int t = 0; t < 2; t++)
                    #pragma unroll
                    for (int s = 0; s < 8; s++)
                        mma16816(acc[t][s], a[t][0], a[t][1], a[t][2], a[t][3],
                                 b[s][0], b[s][1]);
            }
        }
        __syncthreads();
        if (kc + 3 < nchunk) issue(kc + 3, st);
        else asm volatile("cp.async.commit_group;" ::: "memory");
        st = (st == 2) ? 0 : st + 1;
    }

    float* Cw = C + (size_t)(bm + mw * 32 + (lane >> 2)) * N + bn + nw * 64 + (lane & 3) * 2;
    #pragma unroll
    for (int t = 0; t < 2; t++)
        #pragma unroll
        for (int s = 0; s < 8; s++) {
            *(float2*)(Cw + (size_t)(t * 16)     * N + s * 8) = make_float2(acc[t][s][0], acc[t][s][1]);
            *(float2*)(Cw + (size_t)(t * 16 + 8) * N + s * 8) = make_float2(acc[t][s][2], acc[t][s][3]);
        }
}

// ---------------- alpha: one block per row, x staged in smem ----------------
__global__ __launch_bounds__(256) void alpha_kernel(const float* __restrict__ x,
                                                    const float* __restrict__ Wa,
                                                    const float* __restrict__ ba,
                                                    const float* __restrict__ ab)
{
    __shared__ float sx[DM];
    const int i = blockIdx.x;
    const int tid = threadIdx.x;
    #pragma unroll
    for (int t = 0; t < 2; t++) {
        int idx = (tid + t * 256) * 4;
        *(float4*)&sx[idx] = *(const float4*)(x + (size_t)i * DM + idx);
    }
    __syncthreads();
    const int w = tid >> 5, lane = tid & 31;
    #pragma unroll
    for (int hh = 0; hh < 2; hh++) {
        int h = w * 2 + hh;
        const float* wr = Wa + (size_t)h * DM;
        float s = 0.f;
        #pragma unroll 8
        for (int t = lane; t < DM; t += 32) s = fmaf(sx[t], wr[t], s);
        #pragma unroll
        for (int o = 16; o; o >>= 1) s += __shfl_xor_sync(0xffffffffu, s, o);
        if (lane == 0) {
            float sig = 1.f / (1.f + __expf(-(s + ba[h])));
            g_a[h * SQ + i] = ab[h] * 8.f * sig;
        }
    }
}

// ---------------- cumsum ----------------
__global__ __launch_bounds__(256) void cumsum_kernel()
{
    int h = blockIdx.x, t = threadIdx.x;
    __shared__ float tot[256];
    float v[8], run = 0.f;
    #pragma unroll
    for (int c = 0; c < 8; c++) { run += g_a[h * SQ + t * 8 + c]; v[c] = run; }
    tot[t] = run;
    __syncthreads();
    for (int off = 1; off < 256; off <<= 1) {
        float add = (t >= off) ? tot[t - off] : 0.f;
        __syncthreads();
        tot[t] += add;
        __syncthreads();
    }
    float base = (t > 0) ? tot[t - 1] : 0.f;
    #pragma unroll
    for (int c = 0; c < 8; c++) g_A[h * SQ + t * 8 + c] = v[c] + base;
}

// ---------------- xpos: rotate q,k; write fp32 + split bf16 q,k,v ----------------
__global__ __launch_bounds__(64) void xpos_kernel(const int* __restrict__ offp)
{
    int i = blockIdx.x, j = threadIdx.x;
    float pos = (float)(i + (offp ? *offp : 0));
    float ps  = pos * (1.f / 512.f);
    float freq = exp2f((float)j * (-13.287712379549449f / 64.f));
    float ang  = pos * freq;
    float sn = sinf(ang), cs = cosf(ang);
    float zeta = ((float)(2 * j) + 51.2f) * (1.f / 179.2f);
    float e = log2f(zeta) * ps;
    float scq = exp2f(e), sck0 = exp2f(-e);

    #pragma unroll 4
    for (int h = 0; h < NH; h++) {
        float sck = sck0 * (1.f - __expf(g_a[h * SQ + i]));
        size_t base = (size_t)i * TDM + h * DH;
        float* qp = g_qkv + base;
        float* kp = qp + DM;
        float* vp = qp + 2 * DM;
        float q1 = qp[j], q2 = qp[j + 64];
        float k1 = kp[j], k2 = kp[j + 64];
        float qa = (q1 * cs - q2 * sn) * scq;
        float qb = (q2 * cs + q1 * sn) * scq;
        float ka = (k1 * cs - k2 * sn) * sck;
        float kb = (k2 * cs + k1 * sn) * sck;
        qp[j] = qa; qp[j + 64] = qb;
        kp[j] = ka; kp[j + 64] = kb;
        float va = vp[j], vb = vp[j + 64];
        __nv_bfloat16* ph = g_qkvh + base;
        __nv_bfloat16* pl = g_qkvl + base;
        ph[j]      = __float2bfloat16(qa); pl[j]      = __float2bfloat16(qa - bhi(qa));
        ph[j + 64] = __float2bfloat16(qb); pl[j + 64] = __float2bfloat16(qb - bhi(qb));
        ph[DM + j]      = __float2bfloat16(ka); pl[DM + j]      = __float2bfloat16(ka - bhi(ka));
        ph[DM + j + 64] = __float2bfloat16(kb); pl[DM + j + 64] = __float2bfloat16(kb - bhi(kb));
        ph[2*DM + j]      = __float2bfloat16(va); pl[2*DM + j]      = __float2bfloat16(va - bhi(va));
        ph[2*DM + j + 64] = __float2bfloat16(vb); pl[2*DM + j + 64] = __float2bfloat16(vb - bhi(vb));
    }
}

// ---------------- HMMA retention (cp.async K/V pipeline) ----------------
#define R_QH 0
#define R_QL 32768
#define R_KH 65536
#define R_KL 98304
#define R_VH 131072
#define R_VL 163840
#define R_EI 196608
#define R_FJ 197120
#define R_E0 197632
#define R_SMEM 198144

__device__ __forceinline__ void load_tile_split(char* sm, int dh, int dl,
                                                const __nv_bfloat16* srch,
                                                const __nv_bfloat16* srcl,
                                                int tid)
{
    int r = tid >> 1, half = tid & 1;
    const __nv_bfloat16* sh = srch + (size_t)r * TDM + half * 64;
    const __nv_bfloat16* sl = srcl + (size_t)r * TDM + half * 64;
    #pragma unroll
    for (int c = 0; c < 8; c++) {
        int u = half * 8 + c;
        int off = swoff(r, u);
        *(uint4*)(sm + dh + off) = *(const uint4*)(sh + c * 8);
        *(uint4*)(sm + dl + off) = *(const uint4*)(sl + c * 8);
    }
}

__global__ __launch_bounds__(256) void retention_hmma(const float* __restrict__ state)
{
    extern __shared__ char sm[];
    float* sEi = (float*)(sm + R_EI);
    float* sFj = (float*)(sm + R_FJ);
    float* sE0 = (float*)(sm + R_E0);

    const int h = blockIdx.y, bi = 15 - blockIdx.x;
    const int gi0 = bi * 128;
    const int tid = threadIdx.x;
    const int w = tid >> 5, lane = tid & 31;
    const uint32_t sb = smem_u32(sm);
    const int r_ = tid >> 1, half_ = tid & 1;

    auto issue_tile = [&](int dh, int dl, const __nv_bfloat16* srch,
                          const __nv_bfloat16* srcl) {
        const __nv_bfloat16* shp = srch + (size_t)r_ * TDM + half_ * 64;
        const __nv_bfloat16* slp = srcl + (size_t)r_ * TDM + half_ * 64;
        #pragma unroll
        for (int c = 0; c < 8; c++) {
            int u = half_ * 8 + c;
            int off = swoff(r_, u);
            asm volatile("cp.async.cg.shared.global [%0], [%1], 16;"
                         :: "r"(sb + dh + off), "l"(shp + c * 8));
            asm volatile("cp.async.cg.shared.global [%0], [%1], 16;"
                         :: "r"(sb + dl + off), "l"(slp + c * 8));
        }
        asm volatile("cp.async.commit_group;" ::: "memory");
    };

    // Q tiles (direct stores)
    load_tile_split(sm, R_QH, R_QL,
                    g_qkvh + (size_t)gi0 * TDM + h * DH,
                    g_qkvl + (size_t)gi0 * TDM + h * DH, tid);

    // K(bi) in flight while we do the state term
    issue_tile(R_KH, R_KL,
               g_qkvh + (size_t)gi0 * TDM + DM + h * DH,
               g_qkvl + (size_t)gi0 * TDM + DM + h * DH);

    const float Aref = g_A[h * SQ + gi0];
    const bool do_state = (Aref > -87.f);
    if (do_state) {   // split state fp32 -> V buffers
        const float* sp = state + (size_t)h * DH * DH + (size_t)r_ * DH + half_ * 64;
        #pragma unroll
        for (int c = 0; c < 8; c++) {
            int u = half_ * 8 + c;
            float4 f0 = *(const float4*)(sp + c * 8);
            float4 f1 = *(const float4*)(sp + c * 8 + 4);
            uint4 hv, lv;
            hv.x = packbf(f0.x, f0.y); hv.y = packbf(f0.z, f0.w);
            hv.z = packbf(f1.x, f1.y); hv.w = packbf(f1.z, f1.w);
            lv.x = packbf(f0.x - bhi(f0.x), f0.y - bhi(f0.y));
            lv.y = packbf(f0.z - bhi(f0.z), f0.w - bhi(f0.w));
            lv.z = packbf(f1.x - bhi(f1.x), f1.y - bhi(f1.y));
            lv.w = packbf(f1.z - bhi(f1.z), f1.w - bhi(f1.w));
            int off = swoff(r_, u);
            *(uint4*)(sm + R_VH + off) = hv;
            *(uint4*)(sm + R_VL + off) = lv;
        }
    }
    if (tid < 128) {
        float Ai = g_A[h * SQ + gi0 + tid];
        sEi[tid] = __expf(Ai - Aref);
        sE0[tid] = __expf(Ai);
    }
    __syncthreads();

    float out[16][4] = {};
    const int rA = w * 16 + (lane & 15);
    const int uA = lane >> 4;
    const int tr = (lane & 7) + (((lane >> 3) & 1) << 3);
    const int tu = (lane >> 4) & 1;
    const int kr = (lane & 7) + ((lane & 16) ? 8 : 0);
    const int ku = (lane >> 3) & 1;
    const int row0 = w * 16 + (lane >> 2);

    if (do_state) {   // out = Q @ state (3-pass), state lives in V buffers
        #pragma unroll
        for (int k16 = 0; k16 < 8; k16++) {
            uint32_t ah[4], al[4];
            int aoff = swoff(rA, 2 * k16 + uA);
            ldsm4(ah[0], ah[1], ah[2], ah[3], sb + R_QH + aoff);
            ldsm4(al[0], al[1], al[2], al[3], sb + R_QL + aoff);
            #pragma unroll
            for (int en = 0; en < 8; en++) {
                int off = swoff(16 * k16 + tr, 2 * en + tu);
                uint32_t b0, b1, b2, b3;
                ldsm4t(b0, b1, b2, b3, sb + R_VH + off);
                mma16816(out[2*en],   ah[0], ah[1], ah[2], ah[3], b0, b1);
                mma16816(out[2*en+1], ah[0], ah[1], ah[2], ah[3], b2, b3);
                mma16816(out[2*en],   al[0], al[1], al[2], al[3], b0, b1);
                mma16816(out[2*en+1], al[0], al[1], al[2], al[3], b2, b3);
                ldsm4t(b0, b1, b2, b3, sb + R_VL + off);
                mma16816(out[2*en],   ah[0], ah[1], ah[2], ah[3], b0, b1);
                mma16816(out[2*en+1], ah[0], ah[1], ah[2], ah[3], b2, b3);
            }
        }
        float e0a = sE0[row0], e0b = sE0[row0 + 8];
        #pragma unroll
        for (int t = 0; t < 16; t++) {
            out[t][0] *= e0a; out[t][1] *= e0a;
            out[t][2] *= e0b; out[t][3] *= e0b;
        }
    }
    __syncthreads();   // V buffers free (state reads done)
    issue_tile(R_VH, R_VL,
               g_qkvh + (size_t)gi0 * TDM + 2 * DM + h * DH,
               g_qkvl + (size_t)gi0 * TDM + 2 * DM + h * DH);   // V(bi)

    int bj = bi;
    for (;;) {
        const int gj0 = bj * 128;
        asm volatile("cp.async.wait_group 1;" ::: "memory");    // K(bj) ready
        if (tid < 128) sFj[tid] = __expf(Aref - g_A[h * SQ + gj0 + tid]);
        __syncthreads();

        // S = Q K^T (3-pass)
        float s[16][4] = {};
        #pragma unroll
        for (int k16 = 0; k16 < 8; k16++) {
            uint32_t ah[4], al[4];
            int aoff = swoff(rA, 2 * k16 + uA);
            ldsm4(ah[0], ah[1], ah[2], ah[3], sb + R_QH + aoff);
            ldsm4(al[0], al[1], al[2], al[3], sb + R_QL + aoff);
            #pragma unroll
            for (int jn = 0; jn < 8; jn++) {
                int off = swoff(16 * jn + kr, 2 * k16 + ku);
                uint32_t b0, b1, b2, b3;
                ldsm4(b0, b1, b2, b3, sb + R_KH + off);
                mma16816(s[2*jn],   ah[0], ah[1], ah[2], ah[3], b0, b1);
                mma16816(s[2*jn+1], ah[0], ah[1], ah[2], ah[3], b2, b3);
                mma16816(s[2*jn],   al[0], al[1], al[2], al[3], b0, b1);
                mma16816(s[2*jn+1], al[0], al[1], al[2], al[3], b2, b3);
                ldsm4(b0, b1, b2, b3, sb + R_KL + off);
                mma16816(s[2*jn],   ah[0], ah[1], ah[2], ah[3], b0, b1);
                mma16816(s[2*jn+1], ah[0], ah[1], ah[2], ah[3], b2, b3);
            }
        }
        __syncthreads();   // K buffers free

        const bool next_ok = (bj > 0) && (Aref - g_A[h * SQ + gj0 - 1] >= -80.f);
        if (next_ok) {
            issue_tile(R_KH, R_KL,
                       g_qkvh + (size_t)(gj0 - 128) * TDM + DM + h * DH,
                       g_qkvl + (size_t)(gj0 - 128) * TDM + DM + h * DH);  // K(bj-1)
        } else {
            asm volatile("cp.async.commit_group;" ::: "memory");
        }

        // decay + mask while V(bj) finishes
        {
            float ea = sEi[row0], eb = sEi[row0 + 8];
            bool diag = (bj == bi);
            #pragma unroll
            for (int t = 0; t < 16; t++) {
                int c0 = 8 * t + (lane & 3) * 2;
                float f0 = sFj[c0], f1 = sFj[c0 + 1];
                s[t][0] *= ea * f0; s[t][1] *= ea * f1;
                s[t][2] *= eb * f0; s[t][3] *= eb * f1;
                if (diag) {
                    if (c0     > row0)     s[t][0] = 0.f;
                    if (c0 + 1 > row0)     s[t][1] = 0.f;
                    if (c0     > row0 + 8) s[t][2] = 0.f;
                    if (c0 + 1 > row0 + 8) s[t][3] = 0.f;
                }
            }
        }
        asm volatile("cp.async.wait_group 1;" ::: "memory");    // V(bj) ready
        __syncthreads();

        // out += S @ V (3-pass); S fragments reused as A operands
        #pragma unroll
        for (int kk = 0; kk < 8; kk++) {
            const int t0 = 2 * kk, t1 = 2 * kk + 1;
            uint32_t ah[4], al[4];
            ah[0] = packbf(s[t0][0], s[t0][1]);
            ah[1] = packbf(s[t0][2], s[t0][3]);
            ah[2] = packbf(s[t1][0], s[t1][1]);
            ah[3] = packbf(s[t1][2], s[t1][3]);
            al[0] = packbf(s[t0][0] - bhi(s[t0][0]), s[t0][1] - bhi(s[t0][1]));
            al[1] = packbf(s[t0][2] - bhi(s[t0][2]), s[t0][3] - bhi(s[t0][3]));
            al[2] = packbf(s[t1][0] - bhi(s[t1][0]), s[t1][1] - bhi(s[t1][1]));
            al[3] = packbf(s[t1][2] - bhi(s[t1][2]), s[t1][3] - bhi(s[t1][3]));
            #pragma unroll
            for (int en = 0; en < 8; en++) {
                int off = swoff(16 * kk + tr, 2 * en + tu);
                uint32_t b0, b1, b2, b3;
                ldsm4t(b0, b1, b2, b3, sb + R_VH + off);
                mma16816(out[2*en],   ah[0], ah[1], ah[2], ah[3], b0, b1);
                mma16816(out[2*en+1], ah[0], ah[1], ah[2], ah[3], b2, b3);
                mma16816(out[2*en],   al[0], al[1], al[2], al[3], b0, b1);
                mma16816(out[2*en+1], al[0], al[1], al[2], al[3], b2, b3);
                ldsm4t(b0, b1, b2, b3, sb + R_VL + off);
                mma16816(out[2*en],   ah[0], ah[1], ah[2], ah[3], b0, b1);
                mma16816(out[2*en+1], ah[0], ah[1], ah[2], ah[3], b2, b3);
            }
        }

        if (!next_ok) break;
        __syncthreads();   // V buffers free
        issue_tile(R_VH, R_VL,
                   g_qkvh + (size_t)(gj0 - 128) * TDM + 2 * DM + h * DH,
                   g_qkvl + (size_t)(gj0 - 128) * TDM + 2 * DM + h * DH);  // V(bj-1)
        bj--;
    }
    asm volatile("cp.async.wait_group 0;" ::: "memory");

    #pragma unroll
    for (int t = 0; t < 16; t++) {
        int c0 = 8 * t + (lane & 3) * 2;
        float* p = g_ret + (size_t)(gi0 + row0) * DM + h * DH + c0;
        *(float2*)p = make_float2(out[t][0], out[t][1]);
        *(float2*)(p + (size_t)8 * DM) = make_float2(out[t][2], out[t][3]);
    }
}

// ---------------- new_state ----------------
__global__ __launch_bounds__(256) void nstate_partial_kernel()
{
    const int ch = blockIdx.x, h = blockIdx.y;
    const int gi0 = ch * 128;
    const int tid = threadIdx.x;
    const int tx = tid & 15, ty = tid >> 4;
    float* out = g_nsp + (size_t)(h * 16 + ch) * DH * DH;

    float Alast = g_A[h * SQ + SQ - 1];
    if (Alast - g_A[h * SQ + gi0 + 127] < -80.f) {
        for (int idx = tid; idx < DH * DH; idx += 256) out[idx] = 0.f;
        return;
    }
    __shared__ float sK[16][SPAD];
    __shared__ float sV[16][SPAD];
    __shared__ float w[128];
    if (tid < 128) w[tid] = __expf(Alast - g_A[h * SQ + gi0 + tid]);
    __syncthreads();

    float acc[8][8] = {};
    for (int it = 0; it < 8; it++) {
        int i0 = gi0 + it * 16;
        #pragma unroll
        for (int q = 0; q < 2; q++) {
            int f = tid + 256 * q;
            int ir = f >> 5, d4 = (f & 31) * 4;
            float wi = w[it * 16 + ir];
            float4 kv = *(const float4*)(g_qkv + (size_t)(i0 + ir) * TDM + DM + h * DH + d4);
            float4 vv = *(const float4*)(g_qkv + (size_t)(i0 + ir) * TDM + 2 * DM + h * DH + d4);
            sK[ir][d4+0] = kv.x * wi; sK[ir][d4+1] = kv.y * wi;
            sK[ir][d4+2] = kv.z * wi; sK[ir][d4+3] = kv.w * wi;
            *(float4*)(&sV[ir][d4]) = vv;
        }
        __syncthreads();
        #pragma unroll
        for (int i = 0; i < 16; i++) {
            float4 a0 = *(const float4*)(&sK[i][ty*8]);
            float4 a1 = *(const float4*)(&sK[i][ty*8+4]);
            float4 b0 = *(const float4*)(&sV[i][tx*8]);
            float4 b1 = *(const float4*)(&sV[i][tx*8+4]);
            float av[8] = {a0.x,a0.y,a0.z,a0.w,a1.x,a1.y,a1.z,a1.w};
            float bv[8] = {b0.x,b0.y,b0.z,b0.w,b1.x,b1.y,b1.z,b1.w};
            #pragma unroll
            for (int r = 0; r < 8; r++)
                #pragma unroll
                for (int c = 0; c < 8; c++)
                    acc[r][c] = fmaf(av[r], bv[c], acc[r][c]);
        }
        __syncthreads();
    }
    #pragma unroll
    for (int r = 0; r < 8; r++)
        #pragma unroll
        for (int c = 0; c < 8; c++)
            out[(ty * 8 + r) * DH + tx * 8 + c] = acc[r][c];
}

__global__ __launch_bounds__(256) void nstate_reduce_kernel(const float* __restrict__ state,
                                                            float* __restrict__ outNS)
{
    int idx = blockIdx.x * 256 + threadIdx.x;
    int h = idx >> 14;
    float s = __expf(g_A[h * SQ + SQ - 1]) * state[idx];
    int de = idx & 16383;
    #pragma unroll
    for (int c = 0; c < 16; c++) s += g_nsp[(size_t)(h * 16 + c) * DH * DH + de];
    outNS[idx] = s;
}

// ---------------- group norm (writes fp32 g_ret + bf16 split rh/rl) ----------------
__global__ __launch_bounds__(256) void gnorm_kernel(const float* __restrict__ gw,
                                                    const float* __restrict__ gb)
{
    int warp = (blockIdx.x * 256 + threadIdx.x) >> 5;
    int lane = threadIdx.x & 31;
    int i = warp >> 4, h = warp & 15;
    float* p = g_ret + (size_t)i * DM + h * DH;
    float v[4], s = 0.f;
    #pragma unroll
    for (int c = 0; c < 4; c++) { v[c] = p[lane + 32 * c]; s += v[c]; }
    #pragma unroll
    for (int o = 16; o; o >>= 1) s += __shfl_xor_sync(0xffffffffu, s, o);
    float mu = s * (1.f / 128.f), q = 0.f;
    #pragma unroll
    for (int c = 0; c < 4; c++) { float d = v[c] - mu; q = fmaf(d, d, q); }
    #pragma unroll
    for (int o = 16; o; o >>= 1) q += __shfl_xor_sync(0xffffffffu, q, o);
    float rs = rsqrtf(q * (1.f / 128.f) + 1e-5f);
    #pragma unroll
    for (int c = 0; c < 4; c++) {
        int ch = h * DH + lane + 32 * c;
        float val = (v[c] - mu) * rs * gw[ch] + gb[ch];
        p[lane + 32 * c] = val;
        size_t gi = (size_t)i * DM + ch;
        g_rh[gi] = __float2bfloat16(val);
        g_rl[gi] = __float2bfloat16(val - bhi(val));
    }
}

// ---------------- swish: uh/ul = split(swish(u) * ret) ----------------
__global__ __launch_bounds__(256) void swish_kernel()
{
    int i = blockIdx.x * 256 + threadIdx.x;
    float4 g = ((const float4*)g_u)[i];
    float4 r = ((const float4*)g_ret)[i];
    float v0 = g.x / (1.f + __expf(-g.x)) * r.x;
    float v1 = g.y / (1.f + __expf(-g.y)) * r.y;
    float v2 = g.z / (1.f + __expf(-g.z)) * r.z;
    float v3 = g.w / (1.f + __expf(-g.w)) * r.w;
    ((uint32_t*)g_uh)[2*i]   = packbf(v0, v1);
    ((uint32_t*)g_uh)[2*i+1] = packbf(v2, v3);
    ((uint32_t*)g_ul)[2*i]   = packbf(v0 - bhi(v0), v1 - bhi(v1));
    ((uint32_t*)g_ul)[2*i+1] = packbf(v2 - bhi(v2), v3 - bhi(v3));
}

extern "C" void kernel_launch(void* const* d_in, const int* in_sizes, int n_in,
                              void* d_out, int out_size)
{
    const float* x     = (const float*)d_in[0];
    const float* state = (const float*)d_in[1];
    const float* Wqkv  = (const float*)d_in[2];
    const float* Wa    = (const float*)d_in[3];
    const float* ba    = (const float*)d_in[4];
    const float* ab    = (const float*)d_in[5];
    const float* gw    = (const float*)d_in[6];
    const float* gb    = (const float*)d_in[7];
    const float* Wout  = (const float*)d_in[8];
    const float* Wgate = (const float*)d_in[9];
    const int*   offp  = (n_in > 10) ? (const int*)d_in[10] : nullptr;

    float* out   = (float*)d_out;
    float* outNS = out + (size_t)SQ * DM;

    float *qkv_p, *u_p;
    cudaGetSymbolAddress((void**)&qkv_p, g_qkv);
    cudaGetSymbolAddress((void**)&u_p,   g_u);
    __nv_bfloat16 *xh,*xl,*Wqh,*Wql,*Wgh,*Wgl,*Woh,*Wol,*rh,*rl,*uh,*ul;
    cudaGetSymbolAddress((void**)&xh,  g_xh);  cudaGetSymbolAddress((void**)&xl,  g_xl);
    cudaGetSymbolAddress((void**)&Wqh, g_Wqh); cudaGetSymbolAddress((void**)&Wql, g_Wql);
    cudaGetSymbolAddress((void**)&Wgh, g_Wgh); cudaGetSymbolAddress((void**)&Wgl, g_Wgl);
    cudaGetSymbolAddress((void**)&Woh, g_Woh); cudaGetSymbolAddress((void**)&Wol, g_Wol);
    cudaGetSymbolAddress((void**)&rh,  g_rh);  cudaGetSymbolAddress((void**)&rl,  g_rl);
    cudaGetSymbolAddress((void**)&uh,  g_uh);  cudaGetSymbolAddress((void**)&ul,  g_ul);

    const int TG_SMEM = 196608;
    cudaFuncSetAttribute(tgemm, cudaFuncAttributeMaxDynamicSharedMemorySize, TG_SMEM);
    cudaFuncSetAttribute(retention_hmma, cudaFuncAttributeMaxDynamicSharedMemorySize, R_SMEM);

    split_kernel<<<SQ * DM / 1024, 256>>>(x, xh, xl);
    split_kernel<<<TDM * DM / 1024, 256>>>(Wqkv, Wqh, Wql);
    split_kernel<<<DM * DM / 1024, 256>>>(Wgate, Wgh, Wgl);
    split_kernel<<<DM * DM / 1024, 256>>>(Wout, Woh, Wol);

    tgemm<<<dim3(TDM/128, SQ/128), 256, TG_SMEM>>>(xh, xl, Wqh, Wql, qkv_p, TDM, DM);

    alpha_kernel<<<SQ, 256>>>(x, Wa, ba, ab);
    cumsum_kernel<<<NH, 256>>>();
    xpos_kernel<<<SQ, 64>>>(offp);
    retention_hmma<<<dim3(16, NH), 256, R_SMEM>>>(state);
    nstate_partial_kernel<<<dim3(16, NH), 256>>>();
    nstate_reduce_kernel<<<NH * DH * DH / 256, 256>>>(state, outNS);
    gnorm_kernel<<<SQ * NH / 8, 256>>>(gw, gb);

    tgemm<<<dim3(DM/128, SQ/128), 256, TG_SMEM>>>(rh, rl, Wgh, Wgl, u_p, DM, DM);
    swish_kernel<<<SQ * DM / 1024, 256>>>();
    tgemm<<<dim3(DM/128, SQ/128), 256, TG_SMEM>>>(uh, ul, Woh, Wol, out, DM, DM);
}

// round 13
// speedup vs baseline: 2.5442x; 1.0092x over previous
#include <cuda_runtime.h>
#include <cuda_fp16.h>
#include <cstdint>

#define SQ   2048
#define DM   2048
#define NH   16
#define DH   128
#define TDM  6144
#define SPAD 132

// fp32 scratch
__device__ float g_qkv[SQ * TDM];
__device__ float g_a[NH * SQ];
__device__ float g_A[NH * SQ];
__device__ float g_ret[SQ * DM];
__device__ float g_u[SQ * DM];
__device__ float g_nsp[NH * 16 * DH * DH];
// fp16 split scratch (hi + lo residual)
__device__ __half g_xh[SQ*DM],  g_xl[SQ*DM];
__device__ __half g_Wqh[TDM*DM], g_Wql[TDM*DM];
__device__ __half g_Wgh[DM*DM], g_Wgl[DM*DM];
__device__ __half g_Woh[DM*DM], g_Wol[DM*DM];
__device__ __half g_rh[SQ*DM],  g_rl[SQ*DM];
__device__ __half g_uh[SQ*DM],  g_ul[SQ*DM];
__device__ __half g_qkvh[SQ*TDM], g_qkvl[SQ*TDM];

// ---------------- PTX helpers (sm_80-family, valid on bare sm_103) ----------------
__device__ __forceinline__ uint32_t smem_u32(const void* p) {
    uint32_t a;
    asm("{ .reg .u64 t; cvta.to.shared.u64 t, %1; cvt.u32.u64 %0, t; }" : "=r"(a) : "l"(p));
    return a;
}
__device__ __forceinline__ void ldsm4(uint32_t& r0, uint32_t& r1, uint32_t& r2, uint32_t& r3,
                                      uint32_t addr) {
    asm volatile("ldmatrix.sync.aligned.m8n8.x4.shared.b16 {%0,%1,%2,%3}, [%4];"
                 : "=r"(r0), "=r"(r1), "=r"(r2), "=r"(r3) : "r"(addr));
}
__device__ __forceinline__ void ldsm4t(uint32_t& r0, uint32_t& r1, uint32_t& r2, uint32_t& r3,
                                       uint32_t addr) {
    asm volatile("ldmatrix.sync.aligned.m8n8.x4.trans.shared.b16 {%0,%1,%2,%3}, [%4];"
                 : "=r"(r0), "=r"(r1), "=r"(r2), "=r"(r3) : "r"(addr));
}
// fp16 x fp16 -> fp32 accum (main pass)
__device__ __forceinline__ void mma_f32(float* c, uint32_t a0, uint32_t a1, uint32_t a2,
                                        uint32_t a3, uint32_t b0, uint32_t b1) {
    asm volatile("mma.sync.aligned.m16n8k16.row.col.f32.f16.f16.f32 "
                 "{%0,%1,%2,%3}, {%4,%5,%6,%7}, {%8,%9}, {%0,%1,%2,%3};"
                 : "+f"(c[0]), "+f"(c[1]), "+f"(c[2]), "+f"(c[3])
                 : "r"(a0), "r"(a1), "r"(a2), "r"(a3), "r"(b0), "r"(b1));
}
// fp16 x fp16 -> fp16 accum (correction passes, 2x-rate candidate)
__device__ __forceinline__ void mma_f16(uint32_t* c, uint32_t a0, uint32_t a1, uint32_t a2,
                                        uint32_t a3, uint32_t b0, uint32_t b1) {
    asm volatile("mma.sync.aligned.m16n8k16.row.col.f16.f16.f16.f16 "
                 "{%0,%1}, {%2,%3,%4,%5}, {%6,%7}, {%0,%1};"
                 : "+r"(c[0]), "+r"(c[1])
                 : "r"(a0), "r"(a1), "r"(a2), "r"(a3), "r"(b0), "r"(b1));
}
__device__ __forceinline__ uint32_t packh(float x, float y) {
    __half2 p = __floats2half2_rn(x, y);
    return *(uint32_t*)&p;
}
__device__ __forceinline__ float h16(float v) {
    return __half2float(__float2half_rn(v));
}
// fold f16 accumulator pair into 4 floats
__device__ __forceinline__ void fold16(float* c, uint32_t* c16) {
    float2 l01 = __half22float2(*(__half2*)&c16[0]);
    float2 l23 = __half22float2(*(__half2*)&c16[1]);
    c[0] += l01.x; c[1] += l01.y; c[2] += l23.x; c[3] += l23.y;
    c16[0] = 0u; c16[1] = 0u;
}
// swizzled byte offset inside a 128x128 fp16 tile (256B rows, 16B units)
__device__ __forceinline__ int swoff(int row, int u) {
    return row * 256 + (((u & 8) | ((u ^ row) & 7)) << 4);
}

// ---------------- split fp32 -> (hi, lo) fp16 ----------------
__global__ __launch_bounds__(256) void split_kernel(const float* __restrict__ s,
                                                    __half* __restrict__ h,
                                                    __half* __restrict__ l)
{
    int i = blockIdx.x * 256 + threadIdx.x;
    float4 v = ((const float4*)s)[i];
    float h0 = h16(v.x), h1 = h16(v.y), h2 = h16(v.z), h3 = h16(v.w);
    ((uint32_t*)h)[2*i]   = packh(v.x, v.y);
    ((uint32_t*)h)[2*i+1] = packh(v.z, v.w);
    ((uint32_t*)l)[2*i]   = packh(v.x - h0, v.y - h1);
    ((uint32_t*)l)[2*i+1] = packh(v.z - h2, v.w - h3);
}

// ---------------- pipelined HMMA split-fp16 GEMM (3-stage cp.async) ----------------
__global__ __launch_bounds__(256) void tgemm(const __half* __restrict__ Ah,
                                             const __half* __restrict__ Al,
                                             const __half* __restrict__ Bh,
                                             const __half* __restrict__ Bl,
                                             float* __restrict__ C, int N, int K)
{
    extern __shared__ char smem[];   // 3 stages x 4 tiles x 16 KB
    const int tid  = threadIdx.x;
    const int wid  = tid >> 5, lane = tid & 31;
    const int mw   = wid & 3, nw = wid >> 2;
    const int bm   = blockIdx.y * 128, bn = blockIdx.x * 128;
    const uint32_t sbase = smem_u32(smem);

    const int rA = mw * 32 + (lane & 15);
    const int uA = lane >> 4;
    const int rB = nw * 64 + (lane & 7) + ((lane & 16) ? 8 : 0);
    const int uB = (lane >> 3) & 1;

    const __half* src[4] = { Ah + (size_t)bm * K, Al + (size_t)bm * K,
                             Bh + (size_t)bn * K, Bl + (size_t)bn * K };
    const int lm = tid >> 3;
    const int lc = tid & 7;

    const int nchunk = K >> 6;

    auto issue = [&](int kc, int st) {
        #pragma unroll
        for (int t = 0; t < 16; t++) {
            const int tile = t >> 2;
            const int m = (t & 3) * 32 + lm;
            const __half* gsrc = src[tile] + (size_t)m * K + kc * 64 + lc * 8;
            uint32_t dst = sbase + st * 65536 + tile * 16384 + m * 128 + ((lc ^ (m & 7)) << 4);
            asm volatile("cp.async.cg.shared.global [%0], [%1], 16;" :: "r"(dst), "l"(gsrc));
        }
        asm volatile("cp.async.commit_group;" ::: "memory");
    };

    float acc[2][8][4] = {};
    uint32_t acc16[2][8][2] = {};

    issue(0, 0);
    issue(1, 1);
    issue(2, 2);

    int st = 0;
    for (int kc = 0; kc < nchunk; kc++) {
        asm volatile("cp.async.wait_group 2;" ::: "memory");
        __syncthreads();

        const uint32_t stb = sbase + st * 65536;
        #pragma unroll
        for (int p = 0; p < 3; p++) {
            const uint32_t tA = stb + ((p == 2) ? 16384 : 0);
            const uint32_t tB = stb + ((p == 1) ? 49152 : 32768);
            #pragma unroll
            for (int k16 = 0; k16 < 4; k16++) {
                uint32_t a[2][4];
                #pragma unroll
                for (int t = 0; t < 2; t++) {
                    const int row = rA + t * 16;
                    ldsm4(a[t][0], a[t][1], a[t][2], a[t][3],
                          tA + row * 128 + (((2 * k16 + uA) ^ (row & 7)) << 4));
                }
                uint32_t b[8][2];
                #pragma unroll
                for (int j = 0; j < 4; j++) {
                    const int row = rB + j * 16;
                    uint32_t r0, r1, r2, r3;
                    ldsm4(r0, r1, r2, r3,
                          tB + row * 128 + (((2 * k16 + uB) ^ (row & 7)) << 4));
                    b[2*j][0] = r0; b[2*j][1] = r1;
                    b[2*j+1][0] = r2; b[2*j+1][1] = r3;
                }
                if (p == 0) {
                    #pragma unroll
                    for (int t = 0; t < 2; t++)
                        #pragma unroll
                        for (int s = 0; s < 8; s++)
                            mma_f32(acc[t][s], a[t][0], a[t][1], a[t][2], a[t][3],
                                    b[s][0], b[s][1]);
                } else {
                    #pragma unroll
                    for (int t = 0; t < 2; t++)
                        #pragma unroll
                        for (int s = 0; s < 8; s++)
                            mma_f16(acc16[t][s], a[t][0], a[t][1], a[t][2], a[t][3],
                                    b[s][0], b[s][1]);
                }
            }
        }
        // fold f16 corrections into fp32 accumulators (per chunk)
        #pragma unroll
        for (int t = 0; t < 2; t++)
            #pragma unroll
            for (int s = 0; s < 8; s++)
                fold16(acc[t][s], acc16[t][s]);
        __syncthreads();
        if (kc + 3 < nchunk) issue(kc + 3, st);
        else asm volatile("cp.async.commit_group;" ::: "memory");
        st = (st == 2) ? 0 : st + 1;
    }

    float* Cw = C + (size_t)(bm + mw * 32 + (lane >> 2)) * N + bn + nw * 64 + (lane & 3) * 2;
    #pragma unroll
    for (int t = 0; t < 2; t++)
        #pragma unroll
        for (int s = 0; s < 8; s++) {
            *(float2*)(Cw + (size_t)(t * 16)     * N + s * 8) = make_float2(acc[t][s][0], acc[t][s][1]);
            *(float2*)(Cw + (size_t)(t * 16 + 8) * N + s * 8) = make_float2(acc[t][s][2], acc[t][s][3]);
        }
}

// ---------------- alpha: one block per row, x staged in smem ----------------
__global__ __launch_bounds__(256) void alpha_kernel(const float* __restrict__ x,
                                                    const float* __restrict__ Wa,
                                                    const float* __restrict__ ba,
                                                    const float* __restrict__ ab)
{
    __shared__ float sx[DM];
    const int i = blockIdx.x;
    const int tid = threadIdx.x;
    #pragma unroll
    for (int t = 0; t < 2; t++) {
        int idx = (tid + t * 256) * 4;
        *(float4*)&sx[idx] = *(const float4*)(x + (size_t)i * DM + idx);
    }
    __syncthreads();
    const int w = tid >> 5, lane = tid & 31;
    #pragma unroll
    for (int hh = 0; hh < 2; hh++) {
        int h = w * 2 + hh;
        const float* wr = Wa + (size_t)h * DM;
        float s = 0.f;
        #pragma unroll 8
        for (int t = lane; t < DM; t += 32) s = fmaf(sx[t], wr[t], s);
        #pragma unroll
        for (int o = 16; o; o >>= 1) s += __shfl_xor_sync(0xffffffffu, s, o);
        if (lane == 0) {
            float sig = 1.f / (1.f + __expf(-(s + ba[h])));
            g_a[h * SQ + i] = ab[h] * 8.f * sig;
        }
    }
}

// ---------------- cumsum ----------------
__global__ __launch_bounds__(256) void cumsum_kernel()
{
    int h = blockIdx.x, t = threadIdx.x;
    __shared__ float tot[256];
    float v[8], run = 0.f;
    #pragma unroll
    for (int c = 0; c < 8; c++) { run += g_a[h * SQ + t * 8 + c]; v[c] = run; }
    tot[t] = run;
    __syncthreads();
    for (int off = 1; off < 256; off <<= 1) {
        float add = (t >= off) ? tot[t - off] : 0.f;
        __syncthreads();
        tot[t] += add;
        __syncthreads();
    }
    float base = (t > 0) ? tot[t - 1] : 0.f;
    #pragma unroll
    for (int c = 0; c < 8; c++) g_A[h * SQ + t * 8 + c] = v[c] + base;
}

// ---------------- xpos: rotate q,k; write fp32 + split fp16 q,k,v ----------------
__global__ __launch_bounds__(64) void xpos_kernel(const int* __restrict__ offp)
{
    int i = blockIdx.x, j = threadIdx.x;
    float pos = (float)(i + (offp ? *offp : 0));
    float ps  = pos * (1.f / 512.f);
    float freq = exp2f((float)j * (-13.287712379549449f / 64.f));
    float ang  = pos * freq;
    float sn = sinf(ang), cs = cosf(ang);
    float zeta = ((float)(2 * j) + 51.2f) * (1.f / 179.2f);
    float e = log2f(zeta) * ps;
    float scq = exp2f(e), sck0 = exp2f(-e);

    #pragma unroll 4
    for (int h = 0; h < NH; h++) {
        float sck = sck0 * (1.f - __expf(g_a[h * SQ + i]));
        size_t base = (size_t)i * TDM + h * DH;
        float* qp = g_qkv + base;
        float* kp = qp + DM;
        float* vp = qp + 2 * DM;
        float q1 = qp[j], q2 = qp[j + 64];
        float k1 = kp[j], k2 = kp[j + 64];
        float qa = (q1 * cs - q2 * sn) * scq;
        float qb = (q2 * cs + q1 * sn) * scq;
        float ka = (k1 * cs - k2 * sn) * sck;
        float kb = (k2 * cs + k1 * sn) * sck;
        qp[j] = qa; qp[j + 64] = qb;
        kp[j] = ka; kp[j + 64] = kb;
        float va = vp[j], vb = vp[j + 64];
        __half* ph = g_qkvh + base;
        __half* pl = g_qkvl + base;
        ph[j]      = __float2half_rn(qa); pl[j]      = __float2half_rn(qa - h16(qa));
        ph[j + 64] = __float2half_rn(qb); pl[j + 64] = __float2half_rn(qb - h16(qb));
        ph[DM + j]      = __float2half_rn(ka); pl[DM + j]      = __float2half_rn(ka - h16(ka));
        ph[DM + j + 64] = __float2half_rn(kb); pl[DM + j + 64] = __float2half_rn(kb - h16(kb));
        ph[2*DM + j]      = __float2half_rn(va); pl[2*DM + j]      = __float2half_rn(va - h16(va));
        ph[2*DM + j + 64] = __float2half_rn(vb); pl[2*DM + j + 64] = __float2half_rn(vb - h16(vb));
    }
}

// ---------------- HMMA retention (cp.async K/V pipeline, hybrid f16 accum) ----------------
#define R_QH 0
#define R_QL 32768
#define R_KH 65536
#define R_KL 98304
#define R_VH 131072
#define R_VL 163840
#define R_EI 196608
#define R_FJ 197120
#define R_E0 197632
#define R_SMEM 198144

__device__ __forceinline__ void load_tile_split(char* sm, int dh, int dl,
                                                const __half* srch,
                                                const __half* srcl,
                                                int tid)
{
    int r = tid >> 1, half = tid & 1;
    const __half* sh = srch + (size_t)r * TDM + half * 64;
    const __half* sl = srcl + (size_t)r * TDM + half * 64;
    #pragma unroll
    for (int c = 0; c < 8; c++) {
        int u = half * 8 + c;
        int off = swoff(r, u);
        *(uint4*)(sm + dh + off) = *(const uint4*)(sh + c * 8);
        *(uint4*)(sm + dl + off) = *(const uint4*)(sl + c * 8);
    }
}

__global__ __launch_bounds__(256) void retention_hmma(const float* __restrict__ state)
{
    extern __shared__ char sm[];
    float* sEi = (float*)(sm + R_EI);
    float* sFj = (float*)(sm + R_FJ);
    float* sE0 = (float*)(sm + R_E0);

    const int h = blockIdx.y, bi = 15 - blockIdx.x;
    const int gi0 = bi * 128;
    const int tid = threadIdx.x;
    const int w = tid >> 5, lane = tid & 31;
    const uint32_t sb = smem_u32(sm);
    const int r_ = tid >> 1, half_ = tid & 1;

    auto issue_tile = [&](int dh, int dl, const __half* srch, const __half* srcl) {
        const __half* shp = srch + (size_t)r_ * TDM + half_ * 64;
        const __half* slp = srcl + (size_t)r_ * TDM + half_ * 64;
        #pragma unroll
        for (int c = 0; c < 8; c++) {
            int u = half_ * 8 + c;
            int off = swoff(r_, u);
            asm volatile("cp.async.cg.shared.global [%0], [%1], 16;"
                         :: "r"(sb + dh + off), "l"(shp + c * 8));
            asm volatile("cp.async.cg.shared.global [%0], [%1], 16;"
                         :: "r"(sb + dl + off), "l"(slp + c * 8));
        }
        asm volatile("cp.async.commit_group;" ::: "memory");
    };

    load_tile_split(sm, R_QH, R_QL,
                    g_qkvh + (size_t)gi0 * TDM + h * DH,
                    g_qkvl + (size_t)gi0 * TDM + h * DH, tid);

    issue_tile(R_KH, R_KL,
               g_qkvh + (size_t)gi0 * TDM + DM + h * DH,
               g_qkvl + (size_t)gi0 * TDM + DM + h * DH);

    const float Aref = g_A[h * SQ + gi0];
    const bool do_state = (Aref > -87.f);
    if (do_state) {   // split state fp32 -> V buffers
        const float* sp = state + (size_t)h * DH * DH + (size_t)r_ * DH + half_ * 64;
        #pragma unroll
        for (int c = 0; c < 8; c++) {
            int u = half_ * 8 + c;
            float4 f0 = *(const float4*)(sp + c * 8);
            float4 f1 = *(const float4*)(sp + c * 8 + 4);
            uint4 hv, lv;
            hv.x = packh(f0.x, f0.y); hv.y = packh(f0.z, f0.w);
            hv.z = packh(f1.x, f1.y); hv.w = packh(f1.z, f1.w);
            lv.x = packh(f0.x - h16(f0.x), f0.y - h16(f0.y));
            lv.y = packh(f0.z - h16(f0.z), f0.w - h16(f0.w));
            lv.z = packh(f1.x - h16(f1.x), f1.y - h16(f1.y));
            lv.w = packh(f1.z - h16(f1.z), f1.w - h16(f1.w));
            int off = swoff(r_, u);
            *(uint4*)(sm + R_VH + off) = hv;
            *(uint4*)(sm + R_VL + off) = lv;
        }
    }
    if (tid < 128) {
        float Ai = g_A[h * SQ + gi0 + tid];
        sEi[tid] = __expf(Ai - Aref);
        sE0[tid] = __expf(Ai);
    }
    __syncthreads();

    float out[16][4] = {};
    uint32_t out16[16][2] = {};
    const int rA = w * 16 + (lane & 15);
    const int uA = lane >> 4;
    const int tr = (lane & 7) + (((lane >> 3) & 1) << 3);
    const int tu = (lane >> 4) & 1;
    const int kr = (lane & 7) + ((lane & 16) ? 8 : 0);
    const int ku = (lane >> 3) & 1;
    const int row0 = w * 16 + (lane >> 2);

    if (do_state) {   // out = Q @ state (hybrid 3-pass), state in V buffers
        #pragma unroll
        for (int k16 = 0; k16 < 8; k16++) {
            uint32_t ah[4], al[4];
            int aoff = swoff(rA, 2 * k16 + uA);
            ldsm4(ah[0], ah[1], ah[2], ah[3], sb + R_QH + aoff);
            ldsm4(al[0], al[1], al[2], al[3], sb + R_QL + aoff);
            #pragma unroll
            for (int en = 0; en < 8; en++) {
                int off = swoff(16 * k16 + tr, 2 * en + tu);
                uint32_t b0, b1, b2, b3;
                ldsm4t(b0, b1, b2, b3, sb + R_VH + off);
                mma_f32(out[2*en],   ah[0], ah[1], ah[2], ah[3], b0, b1);
                mma_f32(out[2*en+1], ah[0], ah[1], ah[2], ah[3], b2, b3);
                mma_f16(out16[2*en],   al[0], al[1], al[2], al[3], b0, b1);
                mma_f16(out16[2*en+1], al[0], al[1], al[2], al[3], b2, b3);
                ldsm4t(b0, b1, b2, b3, sb + R_VL + off);
                mma_f16(out16[2*en],   ah[0], ah[1], ah[2], ah[3], b0, b1);
                mma_f16(out16[2*en+1], ah[0], ah[1], ah[2], ah[3], b2, b3);
            }
        }
        float e0a = sE0[row0], e0b = sE0[row0 + 8];
        #pragma unroll
        for (int t = 0; t < 16; t++) {
            fold16(out[t], out16[t]);
            out[t][0] *= e0a; out[t][1] *= e0a;
            out[t][2] *= e0b; out[t][3] *= e0b;
        }
    }
    __syncthreads();
    issue_tile(R_VH, R_VL,
               g_qkvh + (size_t)gi0 * TDM + 2 * DM + h * DH,
               g_qkvl + (size_t)gi0 * TDM + 2 * DM + h * DH);   // V(bi)

    int bj = bi;
    for (;;) {
        const int gj0 = bj * 128;
        asm volatile("cp.async.wait_group 1;" ::: "memory");    // K(bj) ready
        if (tid < 128) sFj[tid] = __expf(Aref - g_A[h * SQ + gj0 + tid]);
        __syncthreads();

        // S = Q K^T (hybrid 3-pass)
        float s[16][4] = {};
        uint32_t s16[16][2] = {};
        #pragma unroll
        for (int k16 = 0; k16 < 8; k16++) {
            uint32_t ah[4], al[4];
            int aoff = swoff(rA, 2 * k16 + uA);
            ldsm4(ah[0], ah[1], ah[2], ah[3], sb + R_QH + aoff);
            ldsm4(al[0], al[1], al[2], al[3], sb + R_QL + aoff);
            #pragma unroll
            for (int jn = 0; jn < 8; jn++) {
                int off = swoff(16 * jn + kr, 2 * k16 + ku);
                uint32_t b0, b1, b2, b3;
                ldsm4(b0, b1, b2, b3, sb + R_KH + off);
                mma_f32(s[2*jn],   ah[0], ah[1], ah[2], ah[3], b0, b1);
                mma_f32(s[2*jn+1], ah[0], ah[1], ah[2], ah[3], b2, b3);
                mma_f16(s16[2*jn],   al[0], al[1], al[2], al[3], b0, b1);
                mma_f16(s16[2*jn+1], al[0], al[1], al[2], al[3], b2, b3);
                ldsm4(b0, b1, b2, b3, sb + R_KL + off);
                mma_f16(s16[2*jn],   ah[0], ah[1], ah[2], ah[3], b0, b1);
                mma_f16(s16[2*jn+1], ah[0], ah[1], ah[2], ah[3], b2, b3);
            }
        }
        __syncthreads();   // K buffers free

        const bool next_ok = (bj > 0) && (Aref - g_A[h * SQ + gj0 - 1] >= -80.f);
        if (next_ok) {
            issue_tile(R_KH, R_KL,
                       g_qkvh + (size_t)(gj0 - 128) * TDM + DM + h * DH,
                       g_qkvl + (size_t)(gj0 - 128) * TDM + DM + h * DH);  // K(bj-1)
        } else {
            asm volatile("cp.async.commit_group;" ::: "memory");
        }

        // fold corrections + decay + mask while V(bj) finishes
        {
            float ea = sEi[row0], eb = sEi[row0 + 8];
            bool diag = (bj == bi);
            #pragma unroll
            for (int t = 0; t < 16; t++) {
                fold16(s[t], s16[t]);
                int c0 = 8 * t + (lane & 3) * 2;
                float f0 = sFj[c0], f1 = sFj[c0 + 1];
                s[t][0] *= ea * f0; s[t][1] *= ea * f1;
                s[t][2] *= eb * f0; s[t][3] *= eb * f1;
                if (diag) {
                    if (c0     > row0)     s[t][0] = 0.f;
                    if (c0 + 1 > row0)     s[t][1] = 0.f;
                    if (c0     > row0 + 8) s[t][2] = 0.f;
                    if (c0 + 1 > row0 + 8) s[t][3] = 0.f;
                }
            }
        }
        asm volatile("cp.async.wait_group 1;" ::: "memory");    // V(bj) ready
        __syncthreads();

        // out += S @ V (hybrid 3-pass); S fragments reused as A operands
        #pragma unroll
        for (int kk = 0; kk < 8; kk++) {
            const int t0 = 2 * kk, t1 = 2 * kk + 1;
            uint32_t ah[4], al[4];
            ah[0] = packh(s[t0][0], s[t0][1]);
            ah[1] = packh(s[t0][2], s[t0][3]);
            ah[2] = packh(s[t1][0], s[t1][1]);
            ah[3] = packh(s[t1][2], s[t1][3]);
            al[0] = packh(s[t0][0] - h16(s[t0][0]), s[t0][1] - h16(s[t0][1]));
            al[1] = packh(s[t0][2] - h16(s[t0][2]), s[t0][3] - h16(s[t0][3]));
            al[2] = packh(s[t1][0] - h16(s[t1][0]), s[t1][1] - h16(s[t1][1]));
            al[3] = packh(s[t1][2] - h16(s[t1][2]), s[t1][3] - h16(s[t1][3]));
            #pragma unroll
            for (int en = 0; en < 8; en++) {
                int off = swoff(16 * kk + tr, 2 * en + tu);
                uint32_t b0, b1, b2, b3;
                ldsm4t(b0, b1, b2, b3, sb + R_VH + off);
                mma_f32(out[2*en],   ah[0], ah[1], ah[2], ah[3], b0, b1);
                mma_f32(out[2*en+1], ah[0], ah[1], ah[2], ah[3], b2, b3);
                mma_f16(out16[2*en],   al[0], al[1], al[2], al[3], b0, b1);
                mma_f16(out16[2*en+1], al[0], al[1], al[2], al[3], b2, b3);
                ldsm4t(b0, b1, b2, b3, sb + R_VL + off);
                mma_f16(out16[2*en],   ah[0], ah[1], ah[2], ah[3], b0, b1);
                mma_f16(out16[2*en+1], ah[0], ah[1], ah[2], ah[3], b2, b3);
            }
        }
        // fold S@V corrections per block (keeps f16 accum error bounded)
        #pragma unroll
        for (int t = 0; t < 16; t++) fold16(out[t], out16[t]);

        if (!next_ok) break;
        __syncthreads();   // V buffers free
        issue_tile(R_VH, R_VL,
                   g_qkvh + (size_t)(gj0 - 128) * TDM + 2 * DM + h * DH,
                   g_qkvl + (size_t)(gj0 - 128) * TDM + 2 * DM + h * DH);  // V(bj-1)
        bj--;
    }
    asm volatile("cp.async.wait_group 0;" ::: "memory");

    #pragma unroll
    for (int t = 0; t < 16; t++) {
        int c0 = 8 * t + (lane & 3) * 2;
        float* p = g_ret + (size_t)(gi0 + row0) * DM + h * DH + c0;
        *(float2*)p = make_float2(out[t][0], out[t][1]);
        *(float2*)(p + (size_t)8 * DM) = make_float2(out[t][2], out[t][3]);
    }
}

// ---------------- new_state ----------------
__global__ __launch_bounds__(256) void nstate_partial_kernel()
{
    const int ch = blockIdx.x, h = blockIdx.y;
    const int gi0 = ch * 128;
    const int tid = threadIdx.x;
    const int tx = tid & 15, ty = tid >> 4;
    float* out = g_nsp + (size_t)(h * 16 + ch) * DH * DH;

    float Alast = g_A[h * SQ + SQ - 1];
    if (Alast - g_A[h * SQ + gi0 + 127] < -80.f) {
        for (int idx = tid; idx < DH * DH; idx += 256) out[idx] = 0.f;
        return;
    }
    __shared__ float sK[16][SPAD];
    __shared__ float sV[16][SPAD];
    __shared__ float w[128];
    if (tid < 128) w[tid] = __expf(Alast - g_A[h * SQ + gi0 + tid]);
    __syncthreads();

    float acc[8][8] = {};
    for (int it = 0; it < 8; it++) {
        int i0 = gi0 + it * 16;
        #pragma unroll
        for (int q = 0; q < 2; q++) {
            int f = tid + 256 * q;
            int ir = f >> 5, d4 = (f & 31) * 4;
            float wi = w[it * 16 + ir];
            float4 kv = *(const float4*)(g_qkv + (size_t)(i0 + ir) * TDM + DM + h * DH + d4);
            float4 vv = *(const float4*)(g_qkv + (size_t)(i0 + ir) * TDM + 2 * DM + h * DH + d4);
            sK[ir][d4+0] = kv.x * wi; sK[ir][d4+1] = kv.y * wi;
            sK[ir][d4+2] = kv.z * wi; sK[ir][d4+3] = kv.w * wi;
            *(float4*)(&sV[ir][d4]) = vv;
        }
        __syncthreads();
        #pragma unroll
        for (int i = 0; i < 16; i++) {
            float4 a0 = *(const float4*)(&sK[i][ty*8]);
            float4 a1 = *(const float4*)(&sK[i][ty*8+4]);
            float4 b0 = *(const float4*)(&sV[i][tx*8]);
            float4 b1 = *(const float4*)(&sV[i][tx*8+4]);
            float av[8] = {a0.x,a0.y,a0.z,a0.w,a1.x,a1.y,a1.z,a1.w};
            float bv[8] = {b0.x,b0.y,b0.z,b0.w,b1.x,b1.y,b1.z,b1.w};
            #pragma unroll
            for (int r = 0; r < 8; r++)
                #pragma unroll
                for (int c = 0; c < 8; c++)
                    acc[r][c] = fmaf(av[r], bv[c], acc[r][c]);
        }
        __syncthreads();
    }
    #pragma unroll
    for (int r = 0; r < 8; r++)
        #pragma unroll
        for (int c = 0; c < 8; c++)
            out[(ty * 8 + r) * DH + tx * 8 + c] = acc[r][c];
}

__global__ __launch_bounds__(256) void nstate_reduce_kernel(const float* __restrict__ state,
                                                            float* __restrict__ outNS)
{
    int idx = blockIdx.x * 256 + threadIdx.x;
    int h = idx >> 14;
    float s = __expf(g_A[h * SQ + SQ - 1]) * state[idx];
    int de = idx & 16383;
    #pragma unroll
    for (int c = 0; c < 16; c++) s += g_nsp[(size_t)(h * 16 + c) * DH * DH + de];
    outNS[idx] = s;
}

// ---------------- group norm (writes fp32 g_ret + fp16 split rh/rl) ----------------
__global__ __launch_bounds__(256) void gnorm_kernel(const float* __restrict__ gw,
                                                    const float* __restrict__ gb)
{
    int warp = (blockIdx.x * 256 + threadIdx.x) >> 5;
    int lane = threadIdx.x & 31;
    int i = warp >> 4, h = warp & 15;
    float* p = g_ret + (size_t)i * DM + h * DH;
    float v[4], s = 0.f;
    #pragma unroll
    for (int c = 0; c < 4; c++) { v[c] = p[lane + 32 * c]; s += v[c]; }
    #pragma unroll
    for (int o = 16; o; o >>= 1) s += __shfl_xor_sync(0xffffffffu, s, o);
    float mu = s * (1.f / 128.f), q = 0.f;
    #pragma unroll
    for (int c = 0; c < 4; c++) { float d = v[c] - mu; q = fmaf(d, d, q); }
    #pragma unroll
    for (int o = 16; o; o >>= 1) q += __shfl_xor_sync(0xffffffffu, q, o);
    float rs = rsqrtf(q * (1.f / 128.f) + 1e-5f);
    #pragma unroll
    for (int c = 0; c < 4; c++) {
        int ch = h * DH + lane + 32 * c;
        float val = (v[c] - mu) * rs * gw[ch] + gb[ch];
        p[lane + 32 * c] = val;
        size_t gi = (size_t)i * DM + ch;
        g_rh[gi] = __float2half_rn(val);
        g_rl[gi] = __float2half_rn(val - h16(val));
    }
}

// ---------------- swish: uh/ul = split(swish(u) * ret) ----------------
__global__ __launch_bounds__(256) void swish_kernel()
{
    int i = blockIdx.x * 256 + threadIdx.x;
    float4 g = ((const float4*)g_u)[i];
    float4 r = ((const float4*)g_ret)[i];
    float v0 = g.x / (1.f + __expf(-g.x)) * r.x;
    float v1 = g.y / (1.f + __expf(-g.y)) * r.y;
    float v2 = g.z / (1.f + __expf(-g.z)) * r.z;
    float v3 = g.w / (1.f + __expf(-g.w)) * r.w;
    ((uint32_t*)g_uh)[2*i]   = packh(v0, v1);
    ((uint32_t*)g_uh)[2*i+1] = packh(v2, v3);
    ((uint32_t*)g_ul)[2*i]   = packh(v0 - h16(v0), v1 - h16(v1));
    ((uint32_t*)g_ul)[2*i+1] = packh(v2 - h16(v2), v3 - h16(v3));
}

extern "C" void kernel_launch(void* const* d_in, const int* in_sizes, int n_in,
                              void* d_out, int out_size)
{
    const float* x     = (const float*)d_in[0];
    const float* state = (const float*)d_in[1];
    const float* Wqkv  = (const float*)d_in[2];
    const float* Wa    = (const float*)d_in[3];
    const float* ba    = (const float*)d_in[4];
    const float* ab    = (const float*)d_in[5];
    const float* gw    = (const float*)d_in[6];
    const float* gb    = (const float*)d_in[7];
    const float* Wout  = (const float*)d_in[8];
    const float* Wgate = (const float*)d_in[9];
    const int*   offp  = (n_in > 10) ? (const int*)d_in[10] : nullptr;

    float* out   = (float*)d_out;
    float* outNS = out + (size_t)SQ * DM;

    float *qkv_p, *u_p;
    cudaGetSymbolAddress((void**)&qkv_p, g_qkv);
    cudaGetSymbolAddress((void**)&u_p,   g_u);
    __half *xh,*xl,*Wqh,*Wql,*Wgh,*Wgl,*Woh,*Wol,*rh,*rl,*uh,*ul;
    cudaGetSymbolAddress((void**)&xh,  g_xh);  cudaGetSymbolAddress((void**)&xl,  g_xl);
    cudaGetSymbolAddress((void**)&Wqh, g_Wqh); cudaGetSymbolAddress((void**)&Wql, g_Wql);
    cudaGetSymbolAddress((void**)&Wgh, g_Wgh); cudaGetSymbolAddress((void**)&Wgl, g_Wgl);
    cudaGetSymbolAddress((void**)&Woh, g_Woh); cudaGetSymbolAddress((void**)&Wol, g_Wol);
    cudaGetSymbolAddress((void**)&rh,  g_rh);  cudaGetSymbolAddress((void**)&rl,  g_rl);
    cudaGetSymbolAddress((void**)&uh,  g_uh);  cudaGetSymbolAddress((void**)&ul,  g_ul);

    const int TG_SMEM = 196608;
    cudaFuncSetAttribute(tgemm, cudaFuncAttributeMaxDynamicSharedMemorySize, TG_SMEM);
    cudaFuncSetAttribute(retention_hmma, cudaFuncAttributeMaxDynamicSharedMemorySize, R_SMEM);

    split_kernel<<<SQ * DM / 1024, 256>>>(x, xh, xl);
    split_kernel<<<TDM * DM / 1024, 256>>>(Wqkv, Wqh, Wql);
    split_kernel<<<DM * DM / 1024, 256>>>(Wgate, Wgh, Wgl);
    split_kernel<<<DM * DM / 1024, 256>>>(Wout, Woh, Wol);

    tgemm<<<dim3(TDM/128, SQ/128), 256, TG_SMEM>>>(xh, xl, Wqh, Wql, qkv_p, TDM, DM);

    alpha_kernel<<<SQ, 256>>>(x, Wa, ba, ab);
    cumsum_kernel<<<NH, 256>>>();
    xpos_kernel<<<SQ, 64>>>(offp);
    retention_hmma<<<dim3(16, NH), 256, R_SMEM>>>(state);
    nstate_partial_kernel<<<dim3(16, NH), 256>>>();
    nstate_reduce_kernel<<<NH * DH * DH / 256, 256>>>(state, outNS);
    gnorm_kernel<<<SQ * NH / 8, 256>>>(gw, gb);

    tgemm<<<dim3(DM/128, SQ/128), 256, TG_SMEM>>>(rh, rl, Wgh, Wgl, u_p, DM, DM);
    swish_kernel<<<SQ * DM / 1024, 256>>>();
    tgemm<<<dim3(DM/128, SQ/128), 256, TG_SMEM>>>(uh, ul, Woh, Wol, out, DM, DM);
}

// round 14
// speedup vs baseline: 3.5667x; 1.4019x over previous
#include <cuda_runtime.h>
#include <cuda_fp16.h>
#include <cstdint>

#define SQ   2048
#define DM   2048
#define NH   16
#define DH   128
#define TDM  6144
#define SPAD 132

// fp32 scratch
__device__ float g_qkv[SQ * TDM];
__device__ float g_a[NH * SQ];
__device__ float g_A[NH * SQ];
__device__ float g_ret[SQ * DM];
__device__ float g_u[SQ * DM];
__device__ float g_nsp[NH * 16 * DH * DH];
// fp16 scratch: activations hi-only; weights + k/v hi+lo
__device__ __half g_xh[SQ*DM];
__device__ __half g_Wqh[TDM*DM], g_Wql[TDM*DM];
__device__ __half g_Wgh[DM*DM], g_Wgl[DM*DM];
__device__ __half g_Woh[DM*DM], g_Wol[DM*DM];
__device__ __half g_rh[SQ*DM];
__device__ __half g_uh[SQ*DM];
__device__ __half g_qkvh[SQ*TDM], g_qkvl[SQ*TDM];

// ---------------- PTX helpers (sm_80-family, valid on bare sm_103) ----------------
__device__ __forceinline__ uint32_t smem_u32(const void* p) {
    uint32_t a;
    asm("{ .reg .u64 t; cvta.to.shared.u64 t, %1; cvt.u32.u64 %0, t; }" : "=r"(a) : "l"(p));
    return a;
}
__device__ __forceinline__ void ldsm4(uint32_t& r0, uint32_t& r1, uint32_t& r2, uint32_t& r3,
                                      uint32_t addr) {
    asm volatile("ldmatrix.sync.aligned.m8n8.x4.shared.b16 {%0,%1,%2,%3}, [%4];"
                 : "=r"(r0), "=r"(r1), "=r"(r2), "=r"(r3) : "r"(addr));
}
__device__ __forceinline__ void ldsm4t(uint32_t& r0, uint32_t& r1, uint32_t& r2, uint32_t& r3,
                                       uint32_t addr) {
    asm volatile("ldmatrix.sync.aligned.m8n8.x4.trans.shared.b16 {%0,%1,%2,%3}, [%4];"
                 : "=r"(r0), "=r"(r1), "=r"(r2), "=r"(r3) : "r"(addr));
}
__device__ __forceinline__ void mma_f32(float* c, uint32_t a0, uint32_t a1, uint32_t a2,
                                        uint32_t a3, uint32_t b0, uint32_t b1) {
    asm volatile("mma.sync.aligned.m16n8k16.row.col.f32.f16.f16.f32 "
                 "{%0,%1,%2,%3}, {%4,%5,%6,%7}, {%8,%9}, {%0,%1,%2,%3};"
                 : "+f"(c[0]), "+f"(c[1]), "+f"(c[2]), "+f"(c[3])
                 : "r"(a0), "r"(a1), "r"(a2), "r"(a3), "r"(b0), "r"(b1));
}
__device__ __forceinline__ uint32_t packh(float x, float y) {
    __half2 p = __floats2half2_rn(x, y);
    return *(uint32_t*)&p;
}
__device__ __forceinline__ float h16(float v) {
    return __half2float(__float2half_rn(v));
}
// swizzled byte offset inside a 128x128 fp16 tile (256B rows, 16B units)
__device__ __forceinline__ int swoff(int row, int u) {
    return row * 256 + (((u & 8) | ((u ^ row) & 7)) << 4);
}

// ---------------- splits ----------------
__global__ __launch_bounds__(256) void split_kernel(const float* __restrict__ s,
                                                    __half* __restrict__ h,
                                                    __half* __restrict__ l)
{
    int i = blockIdx.x * 256 + threadIdx.x;
    float4 v = ((const float4*)s)[i];
    float h0 = h16(v.x), h1 = h16(v.y), h2 = h16(v.z), h3 = h16(v.w);
    ((uint32_t*)h)[2*i]   = packh(v.x, v.y);
    ((uint32_t*)h)[2*i+1] = packh(v.z, v.w);
    ((uint32_t*)l)[2*i]   = packh(v.x - h0, v.y - h1);
    ((uint32_t*)l)[2*i+1] = packh(v.z - h2, v.w - h3);
}
__global__ __launch_bounds__(256) void split_hi_kernel(const float* __restrict__ s,
                                                       __half* __restrict__ h)
{
    int i = blockIdx.x * 256 + threadIdx.x;
    float4 v = ((const float4*)s)[i];
    ((uint32_t*)h)[2*i]   = packh(v.x, v.y);
    ((uint32_t*)h)[2*i+1] = packh(v.z, v.w);
}

// ---------------- 2-pass HMMA GEMM: C = A(hi) @ (Bh+Bl)^T, 3-stage cp.async ----------------
__global__ __launch_bounds__(256) void tgemm(const __half* __restrict__ Ah,
                                             const __half* __restrict__ Bh,
                                             const __half* __restrict__ Bl,
                                             float* __restrict__ C, int N, int K)
{
    extern __shared__ char smem[];   // 3 stages x 3 tiles x 16 KB
    const int tid  = threadIdx.x;
    const int wid  = tid >> 5, lane = tid & 31;
    const int mw   = wid & 3, nw = wid >> 2;
    const int bm   = blockIdx.y * 128, bn = blockIdx.x * 128;
    const uint32_t sbase = smem_u32(smem);

    const int rA = mw * 32 + (lane & 15);
    const int uA = lane >> 4;
    const int rB = nw * 64 + (lane & 7) + ((lane & 16) ? 8 : 0);
    const int uB = (lane >> 3) & 1;

    const __half* src[3] = { Ah + (size_t)bm * K, Bh + (size_t)bn * K, Bl + (size_t)bn * K };
    const int lm = tid >> 3;
    const int lc = tid & 7;

    const int nchunk = K >> 6;

    auto issue = [&](int kc, int st) {
        #pragma unroll
        for (int t = 0; t < 12; t++) {
            const int tile = t >> 2;
            const int m = (t & 3) * 32 + lm;
            const __half* gsrc = src[tile] + (size_t)m * K + kc * 64 + lc * 8;
            uint32_t dst = sbase + st * 49152 + tile * 16384 + m * 128 + ((lc ^ (m & 7)) << 4);
            asm volatile("cp.async.cg.shared.global [%0], [%1], 16;" :: "r"(dst), "l"(gsrc));
        }
        asm volatile("cp.async.commit_group;" ::: "memory");
    };

    float acc[2][8][4] = {};

    issue(0, 0);
    issue(1, 1);
    issue(2, 2);

    int st = 0;
    for (int kc = 0; kc < nchunk; kc++) {
        asm volatile("cp.async.wait_group 2;" ::: "memory");
        __syncthreads();

        const uint32_t stb = sbase + st * 49152;
        #pragma unroll
        for (int p = 0; p < 2; p++) {
            const uint32_t tA = stb;
            const uint32_t tB = stb + 16384 + p * 16384;
            #pragma unroll
            for (int k16 = 0; k16 < 4; k16++) {
                uint32_t a[2][4];
                #pragma unroll
                for (int t = 0; t < 2; t++) {
                    const int row = rA + t * 16;
                    ldsm4(a[t][0], a[t][1], a[t][2], a[t][3],
                          tA + row * 128 + (((2 * k16 + uA) ^ (row & 7)) << 4));
                }
                uint32_t b[8][2];
                #pragma unroll
                for (int j = 0; j < 4; j++) {
                    const int row = rB + j * 16;
                    uint32_t r0, r1, r2, r3;
                    ldsm4(r0, r1, r2, r3,
                          tB + row * 128 + (((2 * k16 + uB) ^ (row & 7)) << 4));
                    b[2*j][0] = r0; b[2*j][1] = r1;
                    b[2*j+1][0] = r2; b[2*j+1][1] = r3;
                }
                #pragma unroll
                for (int t = 0; t < 2; t++)
                    #pragma unroll
                    for (int s = 0; s < 8; s++)
                        mma_f32(acc[t][s], a[t][0], a[t][1], a[t][2], a[t][3],
                                b[s][0], b[s][1]);
            }
        }
        __syncthreads();
        if (kc + 3 < nchunk) issue(kc + 3, st);
        else asm volatile("cp.async.commit_group;" ::: "memory");
        st = (st == 2) ? 0 : st + 1;
    }

    float* Cw = C + (size_t)(bm + mw * 32 + (lane >> 2)) * N + bn + nw * 64 + (lane & 3) * 2;
    #pragma unroll
    for (int t = 0; t < 2; t++)
        #pragma unroll
        for (int s = 0; s < 8; s++) {
            *(float2*)(Cw + (size_t)(t * 16)     * N + s * 8) = make_float2(acc[t][s][0], acc[t][s][1]);
            *(float2*)(Cw + (size_t)(t * 16 + 8) * N + s * 8) = make_float2(acc[t][s][2], acc[t][s][3]);
        }
}

// ---------------- alpha: one block per row, x staged in smem ----------------
__global__ __launch_bounds__(256) void alpha_kernel(const float* __restrict__ x,
                                                    const float* __restrict__ Wa,
                                                    const float* __restrict__ ba,
                                                    const float* __restrict__ ab)
{
    __shared__ float sx[DM];
    const int i = blockIdx.x;
    const int tid = threadIdx.x;
    #pragma unroll
    for (int t = 0; t < 2; t++) {
        int idx = (tid + t * 256) * 4;
        *(float4*)&sx[idx] = *(const float4*)(x + (size_t)i * DM + idx);
    }
    __syncthreads();
    const int w = tid >> 5, lane = tid & 31;
    #pragma unroll
    for (int hh = 0; hh < 2; hh++) {
        int h = w * 2 + hh;
        const float* wr = Wa + (size_t)h * DM;
        float s = 0.f;
        #pragma unroll 8
        for (int t = lane; t < DM; t += 32) s = fmaf(sx[t], wr[t], s);
        #pragma unroll
        for (int o = 16; o; o >>= 1) s += __shfl_xor_sync(0xffffffffu, s, o);
        if (lane == 0) {
            float sig = 1.f / (1.f + __expf(-(s + ba[h])));
            g_a[h * SQ + i] = ab[h] * 8.f * sig;
        }
    }
}

// ---------------- cumsum ----------------
__global__ __launch_bounds__(256) void cumsum_kernel()
{
    int h = blockIdx.x, t = threadIdx.x;
    __shared__ float tot[256];
    float v[8], run = 0.f;
    #pragma unroll
    for (int c = 0; c < 8; c++) { run += g_a[h * SQ + t * 8 + c]; v[c] = run; }
    tot[t] = run;
    __syncthreads();
    for (int off = 1; off < 256; off <<= 1) {
        float add = (t >= off) ? tot[t - off] : 0.f;
        __syncthreads();
        tot[t] += add;
        __syncthreads();
    }
    float base = (t > 0) ? tot[t - 1] : 0.f;
    #pragma unroll
    for (int c = 0; c < 8; c++) g_A[h * SQ + t * 8 + c] = v[c] + base;
}

// ---------------- xpos: rotate q,k; q hi-only, k/v hi+lo fp16 ----------------
__global__ __launch_bounds__(64) void xpos_kernel(const int* __restrict__ offp)
{
    int i = blockIdx.x, j = threadIdx.x;
    float pos = (float)(i + (offp ? *offp : 0));
    float ps  = pos * (1.f / 512.f);
    float freq = exp2f((float)j * (-13.287712379549449f / 64.f));
    float ang  = pos * freq;
    float sn = sinf(ang), cs = cosf(ang);
    float zeta = ((float)(2 * j) + 51.2f) * (1.f / 179.2f);
    float e = log2f(zeta) * ps;
    float scq = exp2f(e), sck0 = exp2f(-e);

    #pragma unroll 4
    for (int h = 0; h < NH; h++) {
        float sck = sck0 * (1.f - __expf(g_a[h * SQ + i]));
        size_t base = (size_t)i * TDM + h * DH;
        float* qp = g_qkv + base;
        float* kp = qp + DM;
        float* vp = qp + 2 * DM;
        float q1 = qp[j], q2 = qp[j + 64];
        float k1 = kp[j], k2 = kp[j + 64];
        float qa = (q1 * cs - q2 * sn) * scq;
        float qb = (q2 * cs + q1 * sn) * scq;
        float ka = (k1 * cs - k2 * sn) * sck;
        float kb = (k2 * cs + k1 * sn) * sck;
        qp[j] = qa; qp[j + 64] = qb;
        kp[j] = ka; kp[j + 64] = kb;
        float va = vp[j], vb = vp[j + 64];
        __half* ph = g_qkvh + base;
        __half* pl = g_qkvl + base;
        ph[j]      = __float2half_rn(qa);
        ph[j + 64] = __float2half_rn(qb);
        ph[DM + j]      = __float2half_rn(ka); pl[DM + j]      = __float2half_rn(ka - h16(ka));
        ph[DM + j + 64] = __float2half_rn(kb); pl[DM + j + 64] = __float2half_rn(kb - h16(kb));
        ph[2*DM + j]      = __float2half_rn(va); pl[2*DM + j]      = __float2half_rn(va - h16(va));
        ph[2*DM + j + 64] = __float2half_rn(vb); pl[2*DM + j + 64] = __float2half_rn(vb - h16(vb));
    }
}

// ---------------- HMMA retention (cp.async K/V pipeline, Q/S hi-only) ----------------
#define R_QH 0
#define R_KH 32768
#define R_KL 65536
#define R_VH 98304
#define R_VL 131072
#define R_EI 163840
#define R_FJ 164352
#define R_E0 164864
#define R_SMEM 165376

__device__ __forceinline__ void load_tile_hi(char* sm, int dh,
                                             const __half* srch, int tid)
{
    int r = tid >> 1, half = tid & 1;
    const __half* sh = srch + (size_t)r * TDM + half * 64;
    #pragma unroll
    for (int c = 0; c < 8; c++) {
        int u = half * 8 + c;
        *(uint4*)(sm + dh + swoff(r, u)) = *(const uint4*)(sh + c * 8);
    }
}

__global__ __launch_bounds__(256) void retention_hmma(const float* __restrict__ state)
{
    extern __shared__ char sm[];
    float* sEi = (float*)(sm + R_EI);
    float* sFj = (float*)(sm + R_FJ);
    float* sE0 = (float*)(sm + R_E0);

    const int h = blockIdx.y, bi = 15 - blockIdx.x;
    const int gi0 = bi * 128;
    const int tid = threadIdx.x;
    const int w = tid >> 5, lane = tid & 31;
    const uint32_t sb = smem_u32(sm);
    const int r_ = tid >> 1, half_ = tid & 1;

    auto issue_tile = [&](int dh, int dl, const __half* srch, const __half* srcl) {
        const __half* shp = srch + (size_t)r_ * TDM + half_ * 64;
        const __half* slp = srcl + (size_t)r_ * TDM + half_ * 64;
        #pragma unroll
        for (int c = 0; c < 8; c++) {
            int u = half_ * 8 + c;
            int off = swoff(r_, u);
            asm volatile("cp.async.cg.shared.global [%0], [%1], 16;"
                         :: "r"(sb + dh + off), "l"(shp + c * 8));
            asm volatile("cp.async.cg.shared.global [%0], [%1], 16;"
                         :: "r"(sb + dl + off), "l"(slp + c * 8));
        }
        asm volatile("cp.async.commit_group;" ::: "memory");
    };

    load_tile_hi(sm, R_QH, g_qkvh + (size_t)gi0 * TDM + h * DH, tid);

    issue_tile(R_KH, R_KL,
               g_qkvh + (size_t)gi0 * TDM + DM + h * DH,
               g_qkvl + (size_t)gi0 * TDM + DM + h * DH);

    const float Aref = g_A[h * SQ + gi0];
    const bool do_state = (Aref > -87.f);
    if (do_state) {   // split state fp32 -> V buffers (hi+lo)
        const float* sp = state + (size_t)h * DH * DH + (size_t)r_ * DH + half_ * 64;
        #pragma unroll
        for (int c = 0; c < 8; c++) {
            int u = half_ * 8 + c;
            float4 f0 = *(const float4*)(sp + c * 8);
            float4 f1 = *(const float4*)(sp + c * 8 + 4);
            uint4 hv, lv;
            hv.x = packh(f0.x, f0.y); hv.y = packh(f0.z, f0.w);
            hv.z = packh(f1.x, f1.y); hv.w = packh(f1.z, f1.w);
            lv.x = packh(f0.x - h16(f0.x), f0.y - h16(f0.y));
            lv.y = packh(f0.z - h16(f0.z), f0.w - h16(f0.w));
            lv.z = packh(f1.x - h16(f1.x), f1.y - h16(f1.y));
            lv.w = packh(f1.z - h16(f1.z), f1.w - h16(f1.w));
            int off = swoff(r_, u);
            *(uint4*)(sm + R_VH + off) = hv;
            *(uint4*)(sm + R_VL + off) = lv;
        }
    }
    if (tid < 128) {
        float Ai = g_A[h * SQ + gi0 + tid];
        sEi[tid] = __expf(Ai - Aref);
        sE0[tid] = __expf(Ai);
    }
    __syncthreads();

    float out[16][4] = {};
    const int rA = w * 16 + (lane & 15);
    const int uA = lane >> 4;
    const int tr = (lane & 7) + (((lane >> 3) & 1) << 3);
    const int tu = (lane >> 4) & 1;
    const int kr = (lane & 7) + ((lane & 16) ? 8 : 0);
    const int ku = (lane >> 3) & 1;
    const int row0 = w * 16 + (lane >> 2);

    if (do_state) {   // out = Qh @ (stateH + stateL)
        #pragma unroll
        for (int k16 = 0; k16 < 8; k16++) {
            uint32_t ah[4];
            ldsm4(ah[0], ah[1], ah[2], ah[3], sb + R_QH + swoff(rA, 2 * k16 + uA));
            #pragma unroll
            for (int en = 0; en < 8; en++) {
                int off = swoff(16 * k16 + tr, 2 * en + tu);
                uint32_t b0, b1, b2, b3;
                ldsm4t(b0, b1, b2, b3, sb + R_VH + off);
                mma_f32(out[2*en],   ah[0], ah[1], ah[2], ah[3], b0, b1);
                mma_f32(out[2*en+1], ah[0], ah[1], ah[2], ah[3], b2, b3);
                ldsm4t(b0, b1, b2, b3, sb + R_VL + off);
                mma_f32(out[2*en],   ah[0], ah[1], ah[2], ah[3], b0, b1);
                mma_f32(out[2*en+1], ah[0], ah[1], ah[2], ah[3], b2, b3);
            }
        }
        float e0a = sE0[row0], e0b = sE0[row0 + 8];
        #pragma unroll
        for (int t = 0; t < 16; t++) {
            out[t][0] *= e0a; out[t][1] *= e0a;
            out[t][2] *= e0b; out[t][3] *= e0b;
        }
    }
    __syncthreads();
    issue_tile(R_VH, R_VL,
               g_qkvh + (size_t)gi0 * TDM + 2 * DM + h * DH,
               g_qkvl + (size_t)gi0 * TDM + 2 * DM + h * DH);   // V(bi)

    int bj = bi;
    for (;;) {
        const int gj0 = bj * 128;
        asm volatile("cp.async.wait_group 1;" ::: "memory");    // K(bj) ready
        if (tid < 128) sFj[tid] = __expf(Aref - g_A[h * SQ + gj0 + tid]);
        __syncthreads();

        // S = Qh (Kh + Kl)^T
        float s[16][4] = {};
        #pragma unroll
        for (int k16 = 0; k16 < 8; k16++) {
            uint32_t ah[4];
            ldsm4(ah[0], ah[1], ah[2], ah[3], sb + R_QH + swoff(rA, 2 * k16 + uA));
            #pragma unroll
            for (int jn = 0; jn < 8; jn++) {
                int off = swoff(16 * jn + kr, 2 * k16 + ku);
                uint32_t b0, b1, b2, b3;
                ldsm4(b0, b1, b2, b3, sb + R_KH + off);
                mma_f32(s[2*jn],   ah[0], ah[1], ah[2], ah[3], b0, b1);
                mma_f32(s[2*jn+1], ah[0], ah[1], ah[2], ah[3], b2, b3);
                ldsm4(b0, b1, b2, b3, sb + R_KL + off);
                mma_f32(s[2*jn],   ah[0], ah[1], ah[2], ah[3], b0, b1);
                mma_f32(s[2*jn+1], ah[0], ah[1], ah[2], ah[3], b2, b3);
            }
        }
        __syncthreads();   // K buffers free

        const bool next_ok = (bj > 0) && (Aref - g_A[h * SQ + gj0 - 1] >= -80.f);
        if (next_ok) {
            issue_tile(R_KH, R_KL,
                       g_qkvh + (size_t)(gj0 - 128) * TDM + DM + h * DH,
                       g_qkvl + (size_t)(gj0 - 128) * TDM + DM + h * DH);  // K(bj-1)
        } else {
            asm volatile("cp.async.commit_group;" ::: "memory");
        }

        // decay + mask while V(bj) finishes
        {
            float ea = sEi[row0], eb = sEi[row0 + 8];
            bool diag = (bj == bi);
            #pragma unroll
            for (int t = 0; t < 16; t++) {
                int c0 = 8 * t + (lane & 3) * 2;
                float f0 = sFj[c0], f1 = sFj[c0 + 1];
                s[t][0] *= ea * f0; s[t][1] *= ea * f1;
                s[t][2] *= eb * f0; s[t][3] *= eb * f1;
                if (diag) {
                    if (c0     > row0)     s[t][0] = 0.f;
                    if (c0 + 1 > row0)     s[t][1] = 0.f;
                    if (c0     > row0 + 8) s[t][2] = 0.f;
                    if (c0 + 1 > row0 + 8) s[t][3] = 0.f;
                }
            }
        }
        asm volatile("cp.async.wait_group 1;" ::: "memory");    // V(bj) ready
        __syncthreads();

        // out += Sh @ (Vh + Vl); S hi fragments as A operands
        #pragma unroll
        for (int kk = 0; kk < 8; kk++) {
            const int t0 = 2 * kk, t1 = 2 * kk + 1;
            uint32_t ah[4];
            ah[0] = packh(s[t0][0], s[t0][1]);
            ah[1] = packh(s[t0][2], s[t0][3]);
            ah[2] = packh(s[t1][0], s[t1][1]);
            ah[3] = packh(s[t1][2], s[t1][3]);
            #pragma unroll
            for (int en = 0; en < 8; en++) {
                int off = swoff(16 * kk + tr, 2 * en + tu);
                uint32_t b0, b1, b2, b3;
                ldsm4t(b0, b1, b2, b3, sb + R_VH + off);
                mma_f32(out[2*en],   ah[0], ah[1], ah[2], ah[3], b0, b1);
                mma_f32(out[2*en+1], ah[0], ah[1], ah[2], ah[3], b2, b3);
                ldsm4t(b0, b1, b2, b3, sb + R_VL + off);
                mma_f32(out[2*en],   ah[0], ah[1], ah[2], ah[3], b0, b1);
                mma_f32(out[2*en+1], ah[0], ah[1], ah[2], ah[3], b2, b3);
            }
        }

        if (!next_ok) break;
        __syncthreads();   // V buffers free
        issue_tile(R_VH, R_VL,
                   g_qkvh + (size_t)(gj0 - 128) * TDM + 2 * DM + h * DH,
                   g_qkvl + (size_t)(gj0 - 128) * TDM + 2 * DM + h * DH);  // V(bj-1)
        bj--;
    }
    asm volatile("cp.async.wait_group 0;" ::: "memory");

    #pragma unroll
    for (int t = 0; t < 16; t++) {
        int c0 = 8 * t + (lane & 3) * 2;
        float* p = g_ret + (size_t)(gi0 + row0) * DM + h * DH + c0;
        *(float2*)p = make_float2(out[t][0], out[t][1]);
        *(float2*)(p + (size_t)8 * DM) = make_float2(out[t][2], out[t][3]);
    }
}

// ---------------- new_state ----------------
__global__ __launch_bounds__(256) void nstate_partial_kernel()
{
    const int ch = blockIdx.x, h = blockIdx.y;
    const int gi0 = ch * 128;
    const int tid = threadIdx.x;
    const int tx = tid & 15, ty = tid >> 4;
    float* out = g_nsp + (size_t)(h * 16 + ch) * DH * DH;

    float Alast = g_A[h * SQ + SQ - 1];
    if (Alast - g_A[h * SQ + gi0 + 127] < -80.f) {
        for (int idx = tid; idx < DH * DH; idx += 256) out[idx] = 0.f;
        return;
    }
    __shared__ float sK[16][SPAD];
    __shared__ float sV[16][SPAD];
    __shared__ float w[128];
    if (tid < 128) w[tid] = __expf(Alast - g_A[h * SQ + gi0 + tid]);
    __syncthreads();

    float acc[8][8] = {};
    for (int it = 0; it < 8; it++) {
        int i0 = gi0 + it * 16;
        #pragma unroll
        for (int q = 0; q < 2; q++) {
            int f = tid + 256 * q;
            int ir = f >> 5, d4 = (f & 31) * 4;
            float wi = w[it * 16 + ir];
            float4 kv = *(const float4*)(g_qkv + (size_t)(i0 + ir) * TDM + DM + h * DH + d4);
            float4 vv = *(const float4*)(g_qkv + (size_t)(i0 + ir) * TDM + 2 * DM + h * DH + d4);
            sK[ir][d4+0] = kv.x * wi; sK[ir][d4+1] = kv.y * wi;
            sK[ir][d4+2] = kv.z * wi; sK[ir][d4+3] = kv.w * wi;
            *(float4*)(&sV[ir][d4]) = vv;
        }
        __syncthreads();
        #pragma unroll
        for (int i = 0; i < 16; i++) {
            float4 a0 = *(const float4*)(&sK[i][ty*8]);
            float4 a1 = *(const float4*)(&sK[i][ty*8+4]);
            float4 b0 = *(const float4*)(&sV[i][tx*8]);
            float4 b1 = *(const float4*)(&sV[i][tx*8+4]);
            float av[8] = {a0.x,a0.y,a0.z,a0.w,a1.x,a1.y,a1.z,a1.w};
            float bv[8] = {b0.x,b0.y,b0.z,b0.w,b1.x,b1.y,b1.z,b1.w};
            #pragma unroll
            for (int r = 0; r < 8; r++)
                #pragma unroll
                for (int c = 0; c < 8; c++)
                    acc[r][c] = fmaf(av[r], bv[c], acc[r][c]);
        }
        __syncthreads();
    }
    #pragma unroll
    for (int r = 0; r < 8; r++)
        #pragma unroll
        for (int c = 0; c < 8; c++)
            out[(ty * 8 + r) * DH + tx * 8 + c] = acc[r][c];
}

__global__ __launch_bounds__(256) void nstate_reduce_kernel(const float* __restrict__ state,
                                                            float* __restrict__ outNS)
{
    int idx = blockIdx.x * 256 + threadIdx.x;
    int h = idx >> 14;
    float s = __expf(g_A[h * SQ + SQ - 1]) * state[idx];
    int de = idx & 16383;
    #pragma unroll
    for (int c = 0; c < 16; c++) s += g_nsp[(size_t)(h * 16 + c) * DH * DH + de];
    outNS[idx] = s;
}

// ---------------- group norm (fp32 g_ret + fp16 hi rh) ----------------
__global__ __launch_bounds__(256) void gnorm_kernel(const float* __restrict__ gw,
                                                    const float* __restrict__ gb)
{
    int warp = (blockIdx.x * 256 + threadIdx.x) >> 5;
    int lane = threadIdx.x & 31;
    int i = warp >> 4, h = warp & 15;
    float* p = g_ret + (size_t)i * DM + h * DH;
    float v[4], s = 0.f;
    #pragma unroll
    for (int c = 0; c < 4; c++) { v[c] = p[lane + 32 * c]; s += v[c]; }
    #pragma unroll
    for (int o = 16; o; o >>= 1) s += __shfl_xor_sync(0xffffffffu, s, o);
    float mu = s * (1.f / 128.f), q = 0.f;
    #pragma unroll
    for (int c = 0; c < 4; c++) { float d = v[c] - mu; q = fmaf(d, d, q); }
    #pragma unroll
    for (int o = 16; o; o >>= 1) q += __shfl_xor_sync(0xffffffffu, q, o);
    float rs = rsqrtf(q * (1.f / 128.f) + 1e-5f);
    #pragma unroll
    for (int c = 0; c < 4; c++) {
        int ch = h * DH + lane + 32 * c;
        float val = (v[c] - mu) * rs * gw[ch] + gb[ch];
        p[lane + 32 * c] = val;
        g_rh[(size_t)i * DM + ch] = __float2half_rn(val);
    }
}

// ---------------- swish: uh = hi(swish(u) * ret) ----------------
__global__ __launch_bounds__(256) void swish_kernel()
{
    int i = blockIdx.x * 256 + threadIdx.x;
    float4 g = ((const float4*)g_u)[i];
    float4 r = ((const float4*)g_ret)[i];
    float v0 = g.x / (1.f + __expf(-g.x)) * r.x;
    float v1 = g.y / (1.f + __expf(-g.y)) * r.y;
    float v2 = g.z / (1.f + __expf(-g.z)) * r.z;
    float v3 = g.w / (1.f + __expf(-g.w)) * r.w;
    ((uint32_t*)g_uh)[2*i]   = packh(v0, v1);
    ((uint32_t*)g_uh)[2*i+1] = packh(v2, v3);
}

extern "C" void kernel_launch(void* const* d_in, const int* in_sizes, int n_in,
                              void* d_out, int out_size)
{
    const float* x     = (const float*)d_in[0];
    const float* state = (const float*)d_in[1];
    const float* Wqkv  = (const float*)d_in[2];
    const float* Wa    = (const float*)d_in[3];
    const float* ba    = (const float*)d_in[4];
    const float* ab    = (const float*)d_in[5];
    const float* gw    = (const float*)d_in[6];
    const float* gb    = (const float*)d_in[7];
    const float* Wout  = (const float*)d_in[8];
    const float* Wgate = (const float*)d_in[9];
    const int*   offp  = (n_in > 10) ? (const int*)d_in[10] : nullptr;

    float* out   = (float*)d_out;
    float* outNS = out + (size_t)SQ * DM;

    float *qkv_p, *u_p;
    cudaGetSymbolAddress((void**)&qkv_p, g_qkv);
    cudaGetSymbolAddress((void**)&u_p,   g_u);
    __half *xh,*Wqh,*Wql,*Wgh,*Wgl,*Woh,*Wol,*rh,*uh;
    cudaGetSymbolAddress((void**)&xh,  g_xh);
    cudaGetSymbolAddress((void**)&Wqh, g_Wqh); cudaGetSymbolAddress((void**)&Wql, g_Wql);
    cudaGetSymbolAddress((void**)&Wgh, g_Wgh); cudaGetSymbolAddress((void**)&Wgl, g_Wgl);
    cudaGetSymbolAddress((void**)&Woh, g_Woh); cudaGetSymbolAddress((void**)&Wol, g_Wol);
    cudaGetSymbolAddress((void**)&rh,  g_rh);
    cudaGetSymbolAddress((void**)&uh,  g_uh);

    const int TG_SMEM = 147456;
    cudaFuncSetAttribute(tgemm, cudaFuncAttributeMaxDynamicSharedMemorySize, TG_SMEM);
    cudaFuncSetAttribute(retention_hmma, cudaFuncAttributeMaxDynamicSharedMemorySize, R_SMEM);

    split_hi_kernel<<<SQ * DM / 1024, 256>>>(x, xh);
    split_kernel<<<TDM * DM / 1024, 256>>>(Wqkv, Wqh, Wql);
    split_kernel<<<DM * DM / 1024, 256>>>(Wgate, Wgh, Wgl);
    split_kernel<<<DM * DM / 1024, 256>>>(Wout, Woh, Wol);

    tgemm<<<dim3(TDM/128, SQ/128), 256, TG_SMEM>>>(xh, Wqh, Wql, qkv_p, TDM, DM);

    alpha_kernel<<<SQ, 256>>>(x, Wa, ba, ab);
    cumsum_kernel<<<NH, 256>>>();
    xpos_kernel<<<SQ, 64>>>(offp);
    retention_hmma<<<dim3(16, NH), 256, R_SMEM>>>(state);
    nstate_partial_kernel<<<dim3(16, NH), 256>>>();
    nstate_reduce_kernel<<<NH * DH * DH / 256, 256>>>(state, outNS);
    gnorm_kernel<<<SQ * NH / 8, 256>>>(gw, gb);

    tgemm<<<dim3(DM/128, SQ/128), 256, TG_SMEM>>>(rh, Wgh, Wgl, u_p, DM, DM);
    swish_kernel<<<SQ * DM / 1024, 256>>>();
    tgemm<<<dim3(DM/128, SQ/128), 256, TG_SMEM>>>(uh, Woh, Wol, out, DM, DM);
}

// round 16
// speedup vs baseline: 4.2728x; 1.1980x over previous
#include <cuda_runtime.h>
#include <cuda_fp16.h>
#include <cstdint>

#define SQ   2048
#define DM   2048
#define NH   16
#define DH   128
#define TDM  6144
#define SPAD 132
#define PRUNE (-15.f)

// fp32 scratch
__device__ float g_qkv[SQ * TDM];
__device__ float g_a[NH * SQ];
__device__ float g_A[NH * SQ];
__device__ float g_ret[SQ * DM];
__device__ float g_nsp[NH * 16 * DH * DH];
// fp16 scratch: activations hi-only; weights + k/v hi+lo
__device__ __half g_xh[SQ*DM];
__device__ __half g_Wqh[TDM*DM], g_Wql[TDM*DM];
__device__ __half g_Wgh[DM*DM], g_Wgl[DM*DM];
__device__ __half g_Woh[DM*DM], g_Wol[DM*DM];
__device__ __half g_rh[SQ*DM];
__device__ __half g_uh[SQ*DM];
__device__ __half g_qkvh[SQ*TDM], g_qkvl[SQ*TDM];

// ---------------- PTX helpers (sm_80-family, valid on bare sm_103) ----------------
__device__ __forceinline__ uint32_t smem_u32(const void* p) {
    uint32_t a;
    asm("{ .reg .u64 t; cvta.to.shared.u64 t, %1; cvt.u32.u64 %0, t; }" : "=r"(a) : "l"(p));
    return a;
}
__device__ __forceinline__ void ldsm4(uint32_t& r0, uint32_t& r1, uint32_t& r2, uint32_t& r3,
                                      uint32_t addr) {
    asm volatile("ldmatrix.sync.aligned.m8n8.x4.shared.b16 {%0,%1,%2,%3}, [%4];"
                 : "=r"(r0), "=r"(r1), "=r"(r2), "=r"(r3) : "r"(addr));
}
__device__ __forceinline__ void ldsm4t(uint32_t& r0, uint32_t& r1, uint32_t& r2, uint32_t& r3,
                                       uint32_t addr) {
    asm volatile("ldmatrix.sync.aligned.m8n8.x4.trans.shared.b16 {%0,%1,%2,%3}, [%4];"
                 : "=r"(r0), "=r"(r1), "=r"(r2), "=r"(r3) : "r"(addr));
}
__device__ __forceinline__ void mma_f32(float* c, uint32_t a0, uint32_t a1, uint32_t a2,
                                        uint32_t a3, uint32_t b0, uint32_t b1) {
    asm volatile("mma.sync.aligned.m16n8k16.row.col.f32.f16.f16.f32 "
                 "{%0,%1,%2,%3}, {%4,%5,%6,%7}, {%8,%9}, {%0,%1,%2,%3};"
                 : "+f"(c[0]), "+f"(c[1]), "+f"(c[2]), "+f"(c[3])
                 : "r"(a0), "r"(a1), "r"(a2), "r"(a3), "r"(b0), "r"(b1));
}
__device__ __forceinline__ uint32_t packh(float x, float y) {
    __half2 p = __floats2half2_rn(x, y);
    return *(uint32_t*)&p;
}
__device__ __forceinline__ float h16(float v) {
    return __half2float(__float2half_rn(v));
}
// swizzled byte offset inside a 128x128 fp16 tile (256B rows, 16B units)
__device__ __forceinline__ int swoff(int row, int u) {
    return row * 256 + (((u & 8) | ((u ^ row) & 7)) << 4);
}

// ---------------- splits ----------------
__global__ __launch_bounds__(256) void split_kernel(const float* __restrict__ s,
                                                    __half* __restrict__ h,
                                                    __half* __restrict__ l)
{
    int i = blockIdx.x * 256 + threadIdx.x;
    float4 v = ((const float4*)s)[i];
    float h0 = h16(v.x), h1 = h16(v.y), h2 = h16(v.z), h3 = h16(v.w);
    ((uint32_t*)h)[2*i]   = packh(v.x, v.y);
    ((uint32_t*)h)[2*i+1] = packh(v.z, v.w);
    ((uint32_t*)l)[2*i]   = packh(v.x - h0, v.y - h1);
    ((uint32_t*)l)[2*i+1] = packh(v.z - h2, v.w - h3);
}
__global__ __launch_bounds__(256) void split_hi_kernel(const float* __restrict__ s,
                                                       __half* __restrict__ h)
{
    int i = blockIdx.x * 256 + threadIdx.x;
    float4 v = ((const float4*)s)[i];
    ((uint32_t*)h)[2*i]   = packh(v.x, v.y);
    ((uint32_t*)h)[2*i+1] = packh(v.z, v.w);
}

// ---------------- 2-pass HMMA GEMM, 2-stage cp.async, 2 CTAs/SM ----------------
// MODE 0: write fp32 C.  MODE 1: swish epilogue -> Ch = hi(swish(acc) * g_ret)
template<int MODE>
__global__ __launch_bounds__(256, 2) void tgemm(const __half* __restrict__ Ah,
                                                const __half* __restrict__ Bh,
                                                const __half* __restrict__ Bl,
                                                float* __restrict__ C,
                                                __half* __restrict__ Ch,
                                                int N, int K)
{
    extern __shared__ char smem[];   // 2 stages x 3 tiles x 16 KB = 96 KB
    const int tid  = threadIdx.x;
    const int wid  = tid >> 5, lane = tid & 31;
    const int mw   = wid & 3, nw = wid >> 2;
    const int bm   = blockIdx.y * 128, bn = blockIdx.x * 128;
    const uint32_t sbase = smem_u32(smem);

    const int rA = mw * 32 + (lane & 15);
    const int uA = lane >> 4;
    const int rB = nw * 64 + (lane & 7) + ((lane & 16) ? 8 : 0);
    const int uB = (lane >> 3) & 1;

    const __half* src[3] = { Ah + (size_t)bm * K, Bh + (size_t)bn * K, Bl + (size_t)bn * K };
    const int lm = tid >> 3;
    const int lc = tid & 7;

    const int nchunk = K >> 6;

    auto issue = [&](int kc, int st) {
        #pragma unroll
        for (int t = 0; t < 12; t++) {
            const int tile = t >> 2;
            const int m = (t & 3) * 32 + lm;
            const __half* gsrc = src[tile] + (size_t)m * K + kc * 64 + lc * 8;
            uint32_t dst = sbase + st * 49152 + tile * 16384 + m * 128 + ((lc ^ (m & 7)) << 4);
            asm volatile("cp.async.cg.shared.global [%0], [%1], 16;" :: "r"(dst), "l"(gsrc));
        }
        asm volatile("cp.async.commit_group;" ::: "memory");
    };

    float acc[2][8][4] = {};

    issue(0, 0);
    issue(1, 1);

    for (int kc = 0; kc < nchunk; kc++) {
        const int st = kc & 1;
        asm volatile("cp.async.wait_group 1;" ::: "memory");
        __syncthreads();

        const uint32_t stb = sbase + st * 49152;
        #pragma unroll
        for (int p = 0; p < 2; p++) {
            const uint32_t tA = stb;
            const uint32_t tB = stb + 16384 + p * 16384;
            #pragma unroll
            for (int k16 = 0; k16 < 4; k16++) {
                uint32_t a[2][4];
                #pragma unroll
                for (int t = 0; t < 2; t++) {
                    const int row = rA + t * 16;
                    ldsm4(a[t][0], a[t][1], a[t][2], a[t][3],
                          tA + row * 128 + (((2 * k16 + uA) ^ (row & 7)) << 4));
                }
                uint32_t b[8][2];
                #pragma unroll
                for (int j = 0; j < 4; j++) {
                    const int row = rB + j * 16;
                    uint32_t r0, r1, r2, r3;
                    ldsm4(r0, r1, r2, r3,
                          tB + row * 128 + (((2 * k16 + uB) ^ (row & 7)) << 4));
                    b[2*j][0] = r0; b[2*j][1] = r1;
                    b[2*j+1][0] = r2; b[2*j+1][1] = r3;
                }
                #pragma unroll
                for (int t = 0; t < 2; t++)
                    #pragma unroll
                    for (int s = 0; s < 8; s++)
                        mma_f32(acc[t][s], a[t][0], a[t][1], a[t][2], a[t][3],
                                b[s][0], b[s][1]);
            }
        }
        __syncthreads();
        if (kc + 2 < nchunk) issue(kc + 2, st);
        else asm volatile("cp.async.commit_group;" ::: "memory");
    }

    const int row0 = bm + mw * 32 + (lane >> 2);
    const int col0 = bn + nw * 64 + (lane & 3) * 2;
    #pragma unroll
    for (int t = 0; t < 2; t++)
        #pragma unroll
        for (int s = 0; s < 8; s++) {
            if (MODE == 0) {
                *(float2*)(C + (size_t)(row0 + t * 16)     * N + col0 + s * 8) =
                    make_float2(acc[t][s][0], acc[t][s][1]);
                *(float2*)(C + (size_t)(row0 + t * 16 + 8) * N + col0 + s * 8) =
                    make_float2(acc[t][s][2], acc[t][s][3]);
            } else {
                size_t i0 = (size_t)(row0 + t * 16) * N + col0 + s * 8;
                size_t i1 = (size_t)(row0 + t * 16 + 8) * N + col0 + s * 8;
                float2 r0 = *(const float2*)(g_ret + i0);
                float2 r1 = *(const float2*)(g_ret + i1);
                float g0 = acc[t][s][0], g1 = acc[t][s][1];
                float g2 = acc[t][s][2], g3 = acc[t][s][3];
                float v0 = g0 / (1.f + __expf(-g0)) * r0.x;
                float v1 = g1 / (1.f + __expf(-g1)) * r0.y;
                float v2 = g2 / (1.f + __expf(-g2)) * r1.x;
                float v3 = g3 / (1.f + __expf(-g3)) * r1.y;
                *(uint32_t*)(Ch + i0) = packh(v0, v1);
                *(uint32_t*)(Ch + i1) = packh(v2, v3);
            }
        }
}

// ---------------- alpha: one block per row, x staged in smem ----------------
__global__ __launch_bounds__(256) void alpha_kernel(const float* __restrict__ x,
                                                    const float* __restrict__ Wa,
                                                    const float* __restrict__ ba,
                                                    const float* __restrict__ ab)
{
    __shared__ float sx[DM];
    const int i = blockIdx.x;
    const int tid = threadIdx.x;
    #pragma unroll
    for (int t = 0; t < 2; t++) {
        int idx = (tid + t * 256) * 4;
        *(float4*)&sx[idx] = *(const float4*)(x + (size_t)i * DM + idx);
    }
    __syncthreads();
    const int w = tid >> 5, lane = tid & 31;
    #pragma unroll
    for (int hh = 0; hh < 2; hh++) {
        int h = w * 2 + hh;
        const float* wr = Wa + (size_t)h * DM;
        float s = 0.f;
        #pragma unroll 8
        for (int t = lane; t < DM; t += 32) s = fmaf(sx[t], wr[t], s);
        #pragma unroll
        for (int o = 16; o; o >>= 1) s += __shfl_xor_sync(0xffffffffu, s, o);
        if (lane == 0) {
            float sig = 1.f / (1.f + __expf(-(s + ba[h])));
            g_a[h * SQ + i] = ab[h] * 8.f * sig;
        }
    }
}

// ---------------- cumsum ----------------
__global__ __launch_bounds__(256) void cumsum_kernel()
{
    int h = blockIdx.x, t = threadIdx.x;
    __shared__ float tot[256];
    float v[8], run = 0.f;
    #pragma unroll
    for (int c = 0; c < 8; c++) { run += g_a[h * SQ + t * 8 + c]; v[c] = run; }
    tot[t] = run;
    __syncthreads();
    for (int off = 1; off < 256; off <<= 1) {
        float add = (t >= off) ? tot[t - off] : 0.f;
        __syncthreads();
        tot[t] += add;
        __syncthreads();
    }
    float base = (t > 0) ? tot[t - 1] : 0.f;
    #pragma unroll
    for (int c = 0; c < 8; c++) g_A[h * SQ + t * 8 + c] = v[c] + base;
}

// ---------------- xpos: rotate q,k; q hi fp16 only, k fp32+fp16, v fp16 ----------------
__global__ __launch_bounds__(64) void xpos_kernel(const int* __restrict__ offp)
{
    int i = blockIdx.x, j = threadIdx.x;
    float pos = (float)(i + (offp ? *offp : 0));
    float ps  = pos * (1.f / 512.f);
    float freq = exp2f((float)j * (-13.287712379549449f / 64.f));
    float ang  = pos * freq;
    float sn = sinf(ang), cs = cosf(ang);
    float zeta = ((float)(2 * j) + 51.2f) * (1.f / 179.2f);
    float e = log2f(zeta) * ps;
    float scq = exp2f(e), sck0 = exp2f(-e);

    #pragma unroll 4
    for (int h = 0; h < NH; h++) {
        float sck = sck0 * (1.f - __expf(g_a[h * SQ + i]));
        size_t base = (size_t)i * TDM + h * DH;
        float* qp = g_qkv + base;
        float* kp = qp + DM;
        float* vp = qp + 2 * DM;
        float q1 = qp[j], q2 = qp[j + 64];
        float k1 = kp[j], k2 = kp[j + 64];
        float qa = (q1 * cs - q2 * sn) * scq;
        float qb = (q2 * cs + q1 * sn) * scq;
        float ka = (k1 * cs - k2 * sn) * sck;
        float kb = (k2 * cs + k1 * sn) * sck;
        kp[j] = ka; kp[j + 64] = kb;        // fp32 K kept for nstate
        float va = vp[j], vb = vp[j + 64];
        __half* ph = g_qkvh + base;
        __half* pl = g_qkvl + base;
        ph[j]      = __float2half_rn(qa);
        ph[j + 64] = __float2half_rn(qb);
        ph[DM + j]      = __float2half_rn(ka); pl[DM + j]      = __float2half_rn(ka - h16(ka));
        ph[DM + j + 64] = __float2half_rn(kb); pl[DM + j + 64] = __float2half_rn(kb - h16(kb));
        ph[2*DM + j]      = __float2half_rn(va); pl[2*DM + j]      = __float2half_rn(va - h16(va));
        ph[2*DM + j + 64] = __float2half_rn(vb); pl[2*DM + j + 64] = __float2half_rn(vb - h16(vb));
    }
}

// ---------------- HMMA retention (cp.async K/V pipeline, Q/S hi-only) ----------------
#define R_QH 0
#define R_KH 32768
#define R_KL 65536
#define R_VH 98304
#define R_VL 131072
#define R_EI 163840
#define R_FJ 164352
#define R_E0 164864
#define R_SMEM 165376

__device__ __forceinline__ void load_tile_hi(char* sm, int dh,
                                             const __half* srch, int tid)
{
    int r = tid >> 1, half = tid & 1;
    const __half* sh = srch + (size_t)r * TDM + half * 64;
    #pragma unroll
    for (int c = 0; c < 8; c++) {
        int u = half * 8 + c;
        *(uint4*)(sm + dh + swoff(r, u)) = *(const uint4*)(sh + c * 8);
    }
}

__global__ __launch_bounds__(256) void retention_hmma(const float* __restrict__ state)
{
    extern __shared__ char sm[];
    float* sEi = (float*)(sm + R_EI);
    float* sFj = (float*)(sm + R_FJ);
    float* sE0 = (float*)(sm + R_E0);

    const int h = blockIdx.y, bi = 15 - blockIdx.x;
    const int gi0 = bi * 128;
    const int tid = threadIdx.x;
    const int w = tid >> 5, lane = tid & 31;
    const uint32_t sb = smem_u32(sm);
    const int r_ = tid >> 1, half_ = tid & 1;

    auto issue_tile = [&](int dh, int dl, const __half* srch, const __half* srcl) {
        const __half* shp = srch + (size_t)r_ * TDM + half_ * 64;
        const __half* slp = srcl + (size_t)r_ * TDM + half_ * 64;
        #pragma unroll
        for (int c = 0; c < 8; c++) {
            int u = half_ * 8 + c;
            int off = swoff(r_, u);
            asm volatile("cp.async.cg.shared.global [%0], [%1], 16;"
                         :: "r"(sb + dh + off), "l"(shp + c * 8));
            asm volatile("cp.async.cg.shared.global [%0], [%1], 16;"
                         :: "r"(sb + dl + off), "l"(slp + c * 8));
        }
        asm volatile("cp.async.commit_group;" ::: "memory");
    };

    load_tile_hi(sm, R_QH, g_qkvh + (size_t)gi0 * TDM + h * DH, tid);

    issue_tile(R_KH, R_KL,
               g_qkvh + (size_t)gi0 * TDM + DM + h * DH,
               g_qkvl + (size_t)gi0 * TDM + DM + h * DH);

    const float Aref = g_A[h * SQ + gi0];
    const bool do_state = (Aref > -20.f);
    if (do_state) {   // split state fp32 -> V buffers (hi+lo)
        const float* sp = state + (size_t)h * DH * DH + (size_t)r_ * DH + half_ * 64;
        #pragma unroll
        for (int c = 0; c < 8; c++) {
            int u = half_ * 8 + c;
            float4 f0 = *(const float4*)(sp + c * 8);
            float4 f1 = *(const float4*)(sp + c * 8 + 4);
            uint4 hv, lv;
            hv.x = packh(f0.x, f0.y); hv.y = packh(f0.z, f0.w);
            hv.z = packh(f1.x, f1.y); hv.w = packh(f1.z, f1.w);
            lv.x = packh(f0.x - h16(f0.x), f0.y - h16(f0.y));
            lv.y = packh(f0.z - h16(f0.z), f0.w - h16(f0.w));
            lv.z = packh(f1.x - h16(f1.x), f1.y - h16(f1.y));
            lv.w = packh(f1.z - h16(f1.z), f1.w - h16(f1.w));
            int off = swoff(r_, u);
            *(uint4*)(sm + R_VH + off) = hv;
            *(uint4*)(sm + R_VL + off) = lv;
        }
    }
    if (tid < 128) {
        float Ai = g_A[h * SQ + gi0 + tid];
        sEi[tid] = __expf(Ai - Aref);
        sE0[tid] = __expf(Ai);
    }
    __syncthreads();

    float out[16][4] = {};
    const int rA = w * 16 + (lane & 15);
    const int uA = lane >> 4;
    const int tr = (lane & 7) + (((lane >> 3) & 1) << 3);
    const int tu = (lane >> 4) & 1;
    const int kr = (lane & 7) + ((lane & 16) ? 8 : 0);
    const int ku = (lane >> 3) & 1;
    const int row0 = w * 16 + (lane >> 2);

    if (do_state) {   // out = Qh @ (stateH + stateL)
        #pragma unroll
        for (int k16 = 0; k16 < 8; k16++) {
            uint32_t ah[4];
            ldsm4(ah[0], ah[1], ah[2], ah[3], sb + R_QH + swoff(rA, 2 * k16 + uA));
            #pragma unroll
            for (int en = 0; en < 8; en++) {
                int off = swoff(16 * k16 + tr, 2 * en + tu);
                uint32_t b0, b1, b2, b3;
                ldsm4t(b0, b1, b2, b3, sb + R_VH + off);
                mma_f32(out[2*en],   ah[0], ah[1], ah[2], ah[3], b0, b1);
                mma_f32(out[2*en+1], ah[0], ah[1], ah[2], ah[3], b2, b3);
                ldsm4t(b0, b1, b2, b3, sb + R_VL + off);
                mma_f32(out[2*en],   ah[0], ah[1], ah[2], ah[3], b0, b1);
                mma_f32(out[2*en+1], ah[0], ah[1], ah[2], ah[3], b2, b3);
            }
        }
        float e0a = sE0[row0], e0b = sE0[row0 + 8];
        #pragma unroll
        for (int t = 0; t < 16; t++) {
            out[t][0] *= e0a; out[t][1] *= e0a;
            out[t][2] *= e0b; out[t][3] *= e0b;
        }
    }
    __syncthreads();
    issue_tile(R_VH, R_VL,
               g_qkvh + (size_t)gi0 * TDM + 2 * DM + h * DH,
               g_qkvl + (size_t)gi0 * TDM + 2 * DM + h * DH);   // V(bi)

    int bj = bi;
    for (;;) {
        const int gj0 = bj * 128;
        asm volatile("cp.async.wait_group 1;" ::: "memory");    // K(bj) ready
        if (tid < 128) sFj[tid] = __expf(Aref - g_A[h * SQ + gj0 + tid]);
        __syncthreads();

        // S = Qh (Kh + Kl)^T
        float s[16][4] = {};
        #pragma unroll
        for (int k16 = 0; k16 < 8; k16++) {
            uint32_t ah[4];
            ldsm4(ah[0], ah[1], ah[2], ah[3], sb + R_QH + swoff(rA, 2 * k16 + uA));
            #pragma unroll
            for (int jn = 0; jn < 8; jn++) {
                int off = swoff(16 * jn + kr, 2 * k16 + ku);
                uint32_t b0, b1, b2, b3;
                ldsm4(b0, b1, b2, b3, sb + R_KH + off);
                mma_f32(s[2*jn],   ah[0], ah[1], ah[2], ah[3], b0, b1);
                mma_f32(s[2*jn+1], ah[0], ah[1], ah[2], ah[3], b2, b3);
                ldsm4(b0, b1, b2, b3, sb + R_KL + off);
                mma_f32(s[2*jn],   ah[0], ah[1], ah[2], ah[3], b0, b1);
                mma_f32(s[2*jn+1], ah[0], ah[1], ah[2], ah[3], b2, b3);
            }
        }
        __syncthreads();   // K buffers free

        const bool next_ok = (bj > 0) && (Aref - g_A[h * SQ + gj0 - 1] >= PRUNE);
        if (next_ok) {
            issue_tile(R_KH, R_KL,
                       g_qkvh + (size_t)(gj0 - 128) * TDM + DM + h * DH,
                       g_qkvl + (size_t)(gj0 - 128) * TDM + DM + h * DH);  // K(bj-1)
        } else {
            asm volatile("cp.async.commit_group;" ::: "memory");
        }

        // decay + mask while V(bj) finishes
        {
            float ea = sEi[row0], eb = sEi[row0 + 8];
            bool diag = (bj == bi);
            #pragma unroll
            for (int t = 0; t < 16; t++) {
                int c0 = 8 * t + (lane & 3) * 2;
                float f0 = sFj[c0], f1 = sFj[c0 + 1];
                s[t][0] *= ea * f0; s[t][1] *= ea * f1;
                s[t][2] *= eb * f0; s[t][3] *= eb * f1;
                if (diag) {
                    if (c0     > row0)     s[t][0] = 0.f;
                    if (c0 + 1 > row0)     s[t][1] = 0.f;
                    if (c0     > row0 + 8) s[t][2] = 0.f;
                    if (c0 + 1 > row0 + 8) s[t][3] = 0.f;
                }
            }
        }
        asm volatile("cp.async.wait_group 1;" ::: "memory");    // V(bj) ready
        __syncthreads();

        // out += Sh @ (Vh + Vl); S hi fragments as A operands
        #pragma unroll
        for (int kk = 0; kk < 8; kk++) {
            const int t0 = 2 * kk, t1 = 2 * kk + 1;
            uint32_t ah[4];
            ah[0] = packh(s[t0][0], s[t0][1]);
            ah[1] = packh(s[t0][2], s[t0][3]);
            ah[2] = packh(s[t1][0], s[t1][1]);
            ah[3] = packh(s[t1][2], s[t1][3]);
            #pragma unroll
            for (int en = 0; en < 8; en++) {
                int off = swoff(16 * kk + tr, 2 * en + tu);
                uint32_t b0, b1, b2, b3;
                ldsm4t(b0, b1, b2, b3, sb + R_VH + off);
                mma_f32(out[2*en],   ah[0], ah[1], ah[2], ah[3], b0, b1);
                mma_f32(out[2*en+1], ah[0], ah[1], ah[2], ah[3], b2, b3);
                ldsm4t(b0, b1, b2, b3, sb + R_VL + off);
                mma_f32(out[2*en],   ah[0], ah[1], ah[2], ah[3], b0, b1);
                mma_f32(out[2*en+1], ah[0], ah[1], ah[2], ah[3], b2, b3);
            }
        }

        if (!next_ok) break;
        __syncthreads();   // V buffers free
        issue_tile(R_VH, R_VL,
                   g_qkvh + (size_t)(gj0 - 128) * TDM + 2 * DM + h * DH,
                   g_qkvl + (size_t)(gj0 - 128) * TDM + 2 * DM + h * DH);  // V(bj-1)
        bj--;
    }
    asm volatile("cp.async.wait_group 0;" ::: "memory");

    #pragma unroll
    for (int t = 0; t < 16; t++) {
        int c0 = 8 * t + (lane & 3) * 2;
        float* p = g_ret + (size_t)(gi0 + row0) * DM + h * DH + c0;
        *(float2*)p = make_float2(out[t][0], out[t][1]);
        *(float2*)(p + (size_t)8 * DM) = make_float2(out[t][2], out[t][3]);
    }
}

// ---------------- new_state ----------------
__global__ __launch_bounds__(256) void nstate_partial_kernel()
{
    const int ch = blockIdx.x, h = blockIdx.y;
    const int gi0 = ch * 128;
    const int tid = threadIdx.x;
    const int tx = tid & 15, ty = tid >> 4;
    float* out = g_nsp + (size_t)(h * 16 + ch) * DH * DH;

    float Alast = g_A[h * SQ + SQ - 1];
    if (Alast - g_A[h * SQ + gi0 + 127] < PRUNE) {
        for (int idx = tid; idx < DH * DH; idx += 256) out[idx] = 0.f;
        return;
    }
    __shared__ float sK[16][SPAD];
    __shared__ float sV[16][SPAD];
    __shared__ float w[128];
    if (tid < 128) w[tid] = __expf(Alast - g_A[h * SQ + gi0 + tid]);
    __syncthreads();

    float acc[8][8] = {};
    for (int it = 0; it < 8; it++) {
        int i0 = gi0 + it * 16;
        #pragma unroll
        for (int q = 0; q < 2; q++) {
            int f = tid + 256 * q;
            int ir = f >> 5, d4 = (f & 31) * 4;
            float wi = w[it * 16 + ir];
            float4 kv = *(const float4*)(g_qkv + (size_t)(i0 + ir) * TDM + DM + h * DH + d4);
            float4 vv = *(const float4*)(g_qkv + (size_t)(i0 + ir) * TDM + 2 * DM + h * DH + d4);
            sK[ir][d4+0] = kv.x * wi; sK[ir][d4+1] = kv.y * wi;
            sK[ir][d4+2] = kv.z * wi; sK[ir][d4+3] = kv.w * wi;
            *(float4*)(&sV[ir][d4]) = vv;
        }
        __syncthreads();
        #pragma unroll
        for (int i = 0; i < 16; i++) {
            float4 a0 = *(const float4*)(&sK[i][ty*8]);
            float4 a1 = *(const float4*)(&sK[i][ty*8+4]);
            float4 b0 = *(const float4*)(&sV[i][tx*8]);
            float4 b1 = *(const float4*)(&sV[i][tx*8+4]);
            float av[8] = {a0.x,a0.y,a0.z,a0.w,a1.x,a1.y,a1.z,a1.w};
            float bv[8] = {b0.x,b0.y,b0.z,b0.w,b1.x,b1.y,b1.z,b1.w};
            #pragma unroll
            for (int r = 0; r < 8; r++)
                #pragma unroll
                for (int c = 0; c < 8; c++)
                    acc[r][c] = fmaf(av[r], bv[c], acc[r][c]);
        }
        __syncthreads();
    }
    #pragma unroll
    for (int r = 0; r < 8; r++)
        #pragma unroll
        for (int c = 0; c < 8; c++)
            out[(ty * 8 + r) * DH + tx * 8 + c] = acc[r][c];
}

__global__ __launch_bounds__(256) void nstate_reduce_kernel(const float* __restrict__ state,
                                                            float* __restrict__ outNS)
{
    int idx = blockIdx.x * 256 + threadIdx.x;
    int h = idx >> 14;
    float s = __expf(g_A[h * SQ + SQ - 1]) * state[idx];
    int de = idx & 16383;
    #pragma unroll
    for (int c = 0; c < 16; c++) s += g_nsp[(size_t)(h * 16 + c) * DH * DH + de];
    outNS[idx] = s;
}

// ---------------- group norm (fp32 g_ret + fp16 hi rh) ----------------
__global__ __launch_bounds__(256) void gnorm_kernel(const float* __restrict__ gw,
                                                    const float* __restrict__ gb)
{
    int warp = (blockIdx.x * 256 + threadIdx.x) >> 5;
    int lane = threadIdx.x & 31;
    int i = warp >> 4, h = warp & 15;
    float* p = g_ret + (size_t)i * DM + h * DH;
    float v[4], s = 0.f;
    #pragma unroll
    for (int c = 0; c < 4; c++) { v[c] = p[lane + 32 * c]; s += v[c]; }
    #pragma unroll
    for (int o = 16; o; o >>= 1) s += __shfl_xor_sync(0xffffffffu, s, o);
    float mu = s * (1.f / 128.f), q = 0.f;
    #pragma unroll
    for (int c = 0; c < 4; c++) { float d = v[c] - mu; q = fmaf(d, d, q); }
    #pragma unroll
    for (int o = 16; o; o >>= 1) q += __shfl_xor_sync(0xffffffffu, q, o);
    float rs = rsqrtf(q * (1.f / 128.f) + 1e-5f);
    #pragma unroll
    for (int c = 0; c < 4; c++) {
        int ch = h * DH + lane + 32 * c;
        float val = (v[c] - mu) * rs * gw[ch] + gb[ch];
        p[lane + 32 * c] = val;
        g_rh[(size_t)i * DM + ch] = __float2half_rn(val);
    }
}

extern "C" void kernel_launch(void* const* d_in, const int* in_sizes, int n_in,
                              void* d_out, int out_size)
{
    const float* x     = (const float*)d_in[0];
    const float* state = (const float*)d_in[1];
    const float* Wqkv  = (const float*)d_in[2];
    const float* Wa    = (const float*)d_in[3];
    const float* ba    = (const float*)d_in[4];
    const float* ab    = (const float*)d_in[5];
    const float* gw    = (const float*)d_in[6];
    const float* gb    = (const float*)d_in[7];
    const float* Wout  = (const float*)d_in[8];
    const float* Wgate = (const float*)d_in[9];
    const int*   offp  = (n_in > 10) ? (const int*)d_in[10] : nullptr;

    float* out   = (float*)d_out;
    float* outNS = out + (size_t)SQ * DM;

    float *qkv_p;
    cudaGetSymbolAddress((void**)&qkv_p, g_qkv);
    __half *xh,*Wqh,*Wql,*Wgh,*Wgl,*Woh,*Wol,*rh,*uh;
    cudaGetSymbolAddress((void**)&xh,  g_xh);
    cudaGetSymbolAddress((void**)&Wqh, g_Wqh); cudaGetSymbolAddress((void**)&Wql, g_Wql);
    cudaGetSymbolAddress((void**)&Wgh, g_Wgh); cudaGetSymbolAddress((void**)&Wgl, g_Wgl);
    cudaGetSymbolAddress((void**)&Woh, g_Woh); cudaGetSymbolAddress((void**)&Wol, g_Wol);
    cudaGetSymbolAddress((void**)&rh,  g_rh);
    cudaGetSymbolAddress((void**)&uh,  g_uh);

    const int TG_SMEM = 98304;
    cudaFuncSetAttribute(tgemm<0>, cudaFuncAttributeMaxDynamicSharedMemorySize, TG_SMEM);
    cudaFuncSetAttribute(tgemm<1>, cudaFuncAttributeMaxDynamicSharedMemorySize, TG_SMEM);
    cudaFuncSetAttribute(retention_hmma, cudaFuncAttributeMaxDynamicSharedMemorySize, R_SMEM);

    split_hi_kernel<<<SQ * DM / 1024, 256>>>(x, xh);
    split_kernel<<<TDM * DM / 1024, 256>>>(Wqkv, Wqh, Wql);
    split_kernel<<<DM * DM / 1024, 256>>>(Wgate, Wgh, Wgl);
    split_kernel<<<DM * DM / 1024, 256>>>(Wout, Woh, Wol);

    tgemm<0><<<dim3(TDM/128, SQ/128), 256, TG_SMEM>>>(xh, Wqh, Wql, qkv_p, nullptr, TDM, DM);

    alpha_kernel<<<SQ, 256>>>(x, Wa, ba, ab);
    cumsum_kernel<<<NH, 256>>>();
    xpos_kernel<<<SQ, 64>>>(offp);
    retention_hmma<<<dim3(16, NH), 256, R_SMEM>>>(state);
    nstate_partial_kernel<<<dim3(16, NH), 256>>>();
    nstate_reduce_kernel<<<NH * DH * DH / 256, 256>>>(state, outNS);
    gnorm_kernel<<<SQ * NH / 8, 256>>>(gw, gb);

    tgemm<1><<<dim3(DM/128, SQ/128), 256, TG_SMEM>>>(rh, Wgh, Wgl, nullptr, uh, DM, DM);
    tgemm<0><<<dim3(DM/128, SQ/128), 256, TG_SMEM>>>(uh, Woh, Wol, out, nullptr, DM, DM);
}

// round 17
// speedup vs baseline: 6.1864x; 1.4479x over previous
#include <cuda_runtime.h>
#include <cuda_fp16.h>
#include <cstdint>

#define SQ   2048
#define DM   2048
#define NH   16
#define DH   128
#define TDM  6144
#define SPAD 132
#define PRUNE (-15.f)

// fp32 scratch
__device__ float g_qkv[SQ * TDM];
__device__ float g_a[NH * SQ];
__device__ float g_A[NH * SQ];
__device__ float g_ret[SQ * DM];
__device__ float g_nsp[NH * 16 * DH * DH];
// fp16 scratch: activations + weights hi-only; k/v hi+lo
__device__ __half g_xh[SQ*DM];
__device__ __half g_Wqh[TDM*DM];
__device__ __half g_Wgh[DM*DM];
__device__ __half g_Woh[DM*DM];
__device__ __half g_rh[SQ*DM];
__device__ __half g_uh[SQ*DM];
__device__ __half g_qkvh[SQ*TDM], g_qkvl[SQ*TDM];

// ---------------- PTX helpers (sm_80-family, valid on bare sm_103) ----------------
__device__ __forceinline__ uint32_t smem_u32(const void* p) {
    uint32_t a;
    asm("{ .reg .u64 t; cvta.to.shared.u64 t, %1; cvt.u32.u64 %0, t; }" : "=r"(a) : "l"(p));
    return a;
}
__device__ __forceinline__ void ldsm4(uint32_t& r0, uint32_t& r1, uint32_t& r2, uint32_t& r3,
                                      uint32_t addr) {
    asm volatile("ldmatrix.sync.aligned.m8n8.x4.shared.b16 {%0,%1,%2,%3}, [%4];"
                 : "=r"(r0), "=r"(r1), "=r"(r2), "=r"(r3) : "r"(addr));
}
__device__ __forceinline__ void ldsm4t(uint32_t& r0, uint32_t& r1, uint32_t& r2, uint32_t& r3,
                                       uint32_t addr) {
    asm volatile("ldmatrix.sync.aligned.m8n8.x4.trans.shared.b16 {%0,%1,%2,%3}, [%4];"
                 : "=r"(r0), "=r"(r1), "=r"(r2), "=r"(r3) : "r"(addr));
}
__device__ __forceinline__ void mma_f32(float* c, uint32_t a0, uint32_t a1, uint32_t a2,
                                        uint32_t a3, uint32_t b0, uint32_t b1) {
    asm volatile("mma.sync.aligned.m16n8k16.row.col.f32.f16.f16.f32 "
                 "{%0,%1,%2,%3}, {%4,%5,%6,%7}, {%8,%9}, {%0,%1,%2,%3};"
                 : "+f"(c[0]), "+f"(c[1]), "+f"(c[2]), "+f"(c[3])
                 : "r"(a0), "r"(a1), "r"(a2), "r"(a3), "r"(b0), "r"(b1));
}
__device__ __forceinline__ uint32_t packh(float x, float y) {
    __half2 p = __floats2half2_rn(x, y);
    return *(uint32_t*)&p;
}
__device__ __forceinline__ float h16(float v) {
    return __half2float(__float2half_rn(v));
}
// swizzled byte offset inside a 128x128 fp16 tile (256B rows, 16B units)
__device__ __forceinline__ int swoff(int row, int u) {
    return row * 256 + (((u & 8) | ((u ^ row) & 7)) << 4);
}

// ---------------- hi-only split ----------------
__global__ __launch_bounds__(256) void split_hi_kernel(const float* __restrict__ s,
                                                       __half* __restrict__ h)
{
    int i = blockIdx.x * 256 + threadIdx.x;
    float4 v = ((const float4*)s)[i];
    ((uint32_t*)h)[2*i]   = packh(v.x, v.y);
    ((uint32_t*)h)[2*i+1] = packh(v.z, v.w);
}

// ---------------- 1-pass HMMA GEMM, 3-stage cp.async, 2 CTAs/SM ----------------
// MODE 0: write fp32 C.  MODE 1: swish epilogue -> Ch = hi(swish(acc) * g_ret)
template<int MODE>
__global__ __launch_bounds__(256, 2) void tgemm(const __half* __restrict__ Ah,
                                                const __half* __restrict__ Bh,
                                                float* __restrict__ C,
                                                __half* __restrict__ Ch,
                                                int N, int K)
{
    extern __shared__ char smem[];   // 3 stages x 2 tiles x 16 KB = 96 KB
    const int tid  = threadIdx.x;
    const int wid  = tid >> 5, lane = tid & 31;
    const int mw   = wid & 3, nw = wid >> 2;
    const int bm   = blockIdx.y * 128, bn = blockIdx.x * 128;
    const uint32_t sbase = smem_u32(smem);

    const int rA = mw * 32 + (lane & 15);
    const int uA = lane >> 4;
    const int rB = nw * 64 + (lane & 7) + ((lane & 16) ? 8 : 0);
    const int uB = (lane >> 3) & 1;

    const __half* src[2] = { Ah + (size_t)bm * K, Bh + (size_t)bn * K };
    const int lm = tid >> 3;
    const int lc = tid & 7;

    const int nchunk = K >> 6;

    auto issue = [&](int kc, int st) {
        #pragma unroll
        for (int t = 0; t < 8; t++) {
            const int tile = t >> 2;
            const int m = (t & 3) * 32 + lm;
            const __half* gsrc = src[tile] + (size_t)m * K + kc * 64 + lc * 8;
            uint32_t dst = sbase + st * 32768 + tile * 16384 + m * 128 + ((lc ^ (m & 7)) << 4);
            asm volatile("cp.async.cg.shared.global [%0], [%1], 16;" :: "r"(dst), "l"(gsrc));
        }
        asm volatile("cp.async.commit_group;" ::: "memory");
    };

    float acc[2][8][4] = {};

    issue(0, 0);
    issue(1, 1);
    issue(2, 2);

    int st = 0;
    for (int kc = 0; kc < nchunk; kc++) {
        asm volatile("cp.async.wait_group 2;" ::: "memory");
        __syncthreads();

        const uint32_t stb = sbase + st * 32768;
        const uint32_t tA = stb;
        const uint32_t tB = stb + 16384;
        #pragma unroll
        for (int k16 = 0; k16 < 4; k16++) {
            uint32_t a[2][4];
            #pragma unroll
            for (int t = 0; t < 2; t++) {
                const int row = rA + t * 16;
                ldsm4(a[t][0], a[t][1], a[t][2], a[t][3],
                      tA + row * 128 + (((2 * k16 + uA) ^ (row & 7)) << 4));
            }
            uint32_t b[8][2];
            #pragma unroll
            for (int j = 0; j < 4; j++) {
                const int row = rB + j * 16;
                uint32_t r0, r1, r2, r3;
                ldsm4(r0, r1, r2, r3,
                      tB + row * 128 + (((2 * k16 + uB) ^ (row & 7)) << 4));
                b[2*j][0] = r0; b[2*j][1] = r1;
                b[2*j+1][0] = r2; b[2*j+1][1] = r3;
            }
            #pragma unroll
            for (int t = 0; t < 2; t++)
                #pragma unroll
                for (int s = 0; s < 8; s++)
                    mma_f32(acc[t][s], a[t][0], a[t][1], a[t][2], a[t][3],
                            b[s][0], b[s][1]);
        }
        __syncthreads();
        if (kc + 3 < nchunk) issue(kc + 3, st);
        else asm volatile("cp.async.commit_group;" ::: "memory");
        st = (st == 2) ? 0 : st + 1;
    }

    const int row0 = bm + mw * 32 + (lane >> 2);
    const int col0 = bn + nw * 64 + (lane & 3) * 2;
    #pragma unroll
    for (int t = 0; t < 2; t++)
        #pragma unroll
        for (int s = 0; s < 8; s++) {
            if (MODE == 0) {
                *(float2*)(C + (size_t)(row0 + t * 16)     * N + col0 + s * 8) =
                    make_float2(acc[t][s][0], acc[t][s][1]);
                *(float2*)(C + (size_t)(row0 + t * 16 + 8) * N + col0 + s * 8) =
                    make_float2(acc[t][s][2], acc[t][s][3]);
            } else {
                size_t i0 = (size_t)(row0 + t * 16) * N + col0 + s * 8;
                size_t i1 = (size_t)(row0 + t * 16 + 8) * N + col0 + s * 8;
                float2 r0 = *(const float2*)(g_ret + i0);
                float2 r1 = *(const float2*)(g_ret + i1);
                float g0 = acc[t][s][0], g1 = acc[t][s][1];
                float g2 = acc[t][s][2], g3 = acc[t][s][3];
                float v0 = g0 / (1.f + __expf(-g0)) * r0.x;
                float v1 = g1 / (1.f + __expf(-g1)) * r0.y;
                float v2 = g2 / (1.f + __expf(-g2)) * r1.x;
                float v3 = g3 / (1.f + __expf(-g3)) * r1.y;
                *(uint32_t*)(Ch + i0) = packh(v0, v1);
                *(uint32_t*)(Ch + i1) = packh(v2, v3);
            }
        }
}

// ---------------- alpha: one block per row; also emits xh ----------------
__global__ __launch_bounds__(256) void alpha_kernel(const float* __restrict__ x,
                                                    const float* __restrict__ Wa,
                                                    const float* __restrict__ ba,
                                                    const float* __restrict__ ab,
                                                    __half* __restrict__ xh)
{
    __shared__ float sx[DM];
    const int i = blockIdx.x;
    const int tid = threadIdx.x;
    #pragma unroll
    for (int t = 0; t < 2; t++) {
        int idx = (tid + t * 256) * 4;
        float4 v = *(const float4*)(x + (size_t)i * DM + idx);
        *(float4*)&sx[idx] = v;
        size_t g = ((size_t)i * DM + idx) >> 1;
        ((uint32_t*)xh)[g]     = packh(v.x, v.y);
        ((uint32_t*)xh)[g + 1] = packh(v.z, v.w);
    }
    __syncthreads();
    const int w = tid >> 5, lane = tid & 31;
    #pragma unroll
    for (int hh = 0; hh < 2; hh++) {
        int h = w * 2 + hh;
        const float* wr = Wa + (size_t)h * DM;
        float s = 0.f;
        #pragma unroll 8
        for (int t = lane; t < DM; t += 32) s = fmaf(sx[t], wr[t], s);
        #pragma unroll
        for (int o = 16; o; o >>= 1) s += __shfl_xor_sync(0xffffffffu, s, o);
        if (lane == 0) {
            float sig = 1.f / (1.f + __expf(-(s + ba[h])));
            g_a[h * SQ + i] = ab[h] * 8.f * sig;
        }
    }
}

// ---------------- cumsum ----------------
__global__ __launch_bounds__(256) void cumsum_kernel()
{
    int h = blockIdx.x, t = threadIdx.x;
    __shared__ float tot[256];
    float v[8], run = 0.f;
    #pragma unroll
    for (int c = 0; c < 8; c++) { run += g_a[h * SQ + t * 8 + c]; v[c] = run; }
    tot[t] = run;
    __syncthreads();
    for (int off = 1; off < 256; off <<= 1) {
        float add = (t >= off) ? tot[t - off] : 0.f;
        __syncthreads();
        tot[t] += add;
        __syncthreads();
    }
    float base = (t > 0) ? tot[t - 1] : 0.f;
    #pragma unroll
    for (int c = 0; c < 8; c++) g_A[h * SQ + t * 8 + c] = v[c] + base;
}

// ---------------- xpos: rotate q,k; q hi fp16 only, k fp32+fp16, v fp16 ----------------
__global__ __launch_bounds__(64) void xpos_kernel(const int* __restrict__ offp)
{
    int i = blockIdx.x, j = threadIdx.x;
    float pos = (float)(i + (offp ? *offp : 0));
    float ps  = pos * (1.f / 512.f);
    float freq = exp2f((float)j * (-13.287712379549449f / 64.f));
    float ang  = pos * freq;
    float sn = sinf(ang), cs = cosf(ang);
    float zeta = ((float)(2 * j) + 51.2f) * (1.f / 179.2f);
    float e = log2f(zeta) * ps;
    float scq = exp2f(e), sck0 = exp2f(-e);

    #pragma unroll 4
    for (int h = 0; h < NH; h++) {
        float sck = sck0 * (1.f - __expf(g_a[h * SQ + i]));
        size_t base = (size_t)i * TDM + h * DH;
        float* qp = g_qkv + base;
        float* kp = qp + DM;
        float* vp = qp + 2 * DM;
        float q1 = qp[j], q2 = qp[j + 64];
        float k1 = kp[j], k2 = kp[j + 64];
        float qa = (q1 * cs - q2 * sn) * scq;
        float qb = (q2 * cs + q1 * sn) * scq;
        float ka = (k1 * cs - k2 * sn) * sck;
        float kb = (k2 * cs + k1 * sn) * sck;
        kp[j] = ka; kp[j + 64] = kb;        // fp32 K kept for nstate
        float va = vp[j], vb = vp[j + 64];
        __half* ph = g_qkvh + base;
        __half* pl = g_qkvl + base;
        ph[j]      = __float2half_rn(qa);
        ph[j + 64] = __float2half_rn(qb);
        ph[DM + j]      = __float2half_rn(ka); pl[DM + j]      = __float2half_rn(ka - h16(ka));
        ph[DM + j + 64] = __float2half_rn(kb); pl[DM + j + 64] = __float2half_rn(kb - h16(kb));
        ph[2*DM + j]      = __float2half_rn(va); pl[2*DM + j]      = __float2half_rn(va - h16(va));
        ph[2*DM + j + 64] = __float2half_rn(vb); pl[2*DM + j + 64] = __float2half_rn(vb - h16(vb));
    }
}

// ---------------- HMMA retention (cp.async K/V pipeline, Q/S hi-only) ----------------
#define R_QH 0
#define R_KH 32768
#define R_KL 65536
#define R_VH 98304
#define R_VL 131072
#define R_EI 163840
#define R_FJ 164352
#define R_E0 164864
#define R_SMEM 165376

__device__ __forceinline__ void load_tile_hi(char* sm, int dh,
                                             const __half* srch, int tid)
{
    int r = tid >> 1, half = tid & 1;
    const __half* sh = srch + (size_t)r * TDM + half * 64;
    #pragma unroll
    for (int c = 0; c < 8; c++) {
        int u = half * 8 + c;
        *(uint4*)(sm + dh + swoff(r, u)) = *(const uint4*)(sh + c * 8);
    }
}

__global__ __launch_bounds__(256) void retention_hmma(const float* __restrict__ state)
{
    extern __shared__ char sm[];
    float* sEi = (float*)(sm + R_EI);
    float* sFj = (float*)(sm + R_FJ);
    float* sE0 = (float*)(sm + R_E0);

    const int h = blockIdx.y, bi = 15 - blockIdx.x;
    const int gi0 = bi * 128;
    const int tid = threadIdx.x;
    const int w = tid >> 5, lane = tid & 31;
    const uint32_t sb = smem_u32(sm);
    const int r_ = tid >> 1, half_ = tid & 1;

    auto issue_tile = [&](int dh, int dl, const __half* srch, const __half* srcl) {
        const __half* shp = srch + (size_t)r_ * TDM + half_ * 64;
        const __half* slp = srcl + (size_t)r_ * TDM + half_ * 64;
        #pragma unroll
        for (int c = 0; c < 8; c++) {
            int u = half_ * 8 + c;
            int off = swoff(r_, u);
            asm volatile("cp.async.cg.shared.global [%0], [%1], 16;"
                         :: "r"(sb + dh + off), "l"(shp + c * 8));
            asm volatile("cp.async.cg.shared.global [%0], [%1], 16;"
                         :: "r"(sb + dl + off), "l"(slp + c * 8));
        }
        asm volatile("cp.async.commit_group;" ::: "memory");
    };

    load_tile_hi(sm, R_QH, g_qkvh + (size_t)gi0 * TDM + h * DH, tid);

    issue_tile(R_KH, R_KL,
               g_qkvh + (size_t)gi0 * TDM + DM + h * DH,
               g_qkvl + (size_t)gi0 * TDM + DM + h * DH);

    const float Aref = g_A[h * SQ + gi0];
    const bool do_state = (Aref > -20.f);
    if (do_state) {   // split state fp32 -> V buffers (hi+lo)
        const float* sp = state + (size_t)h * DH * DH + (size_t)r_ * DH + half_ * 64;
        #pragma unroll
        for (int c = 0; c < 8; c++) {
            int u = half_ * 8 + c;
            float4 f0 = *(const float4*)(sp + c * 8);
            float4 f1 = *(const float4*)(sp + c * 8 + 4);
            uint4 hv, lv;
            hv.x = packh(f0.x, f0.y); hv.y = packh(f0.z, f0.w);
            hv.z = packh(f1.x, f1.y); hv.w = packh(f1.z, f1.w);
            lv.x = packh(f0.x - h16(f0.x), f0.y - h16(f0.y));
            lv.y = packh(f0.z - h16(f0.z), f0.w - h16(f0.w));
            lv.z = packh(f1.x - h16(f1.x), f1.y - h16(f1.y));
            lv.w = packh(f1.z - h16(f1.z), f1.w - h16(f1.w));
            int off = swoff(r_, u);
            *(uint4*)(sm + R_VH + off) = hv;
            *(uint4*)(sm + R_VL + off) = lv;
        }
    }
    if (tid < 128) {
        float Ai = g_A[h * SQ + gi0 + tid];
        sEi[tid] = __expf(Ai - Aref);
        sE0[tid] = __expf(Ai);
    }
    __syncthreads();

    float out[16][4] = {};
    const int rA = w * 16 + (lane & 15);
    const int uA = lane >> 4;
    const int tr = (lane & 7) + (((lane >> 3) & 1) << 3);
    const int tu = (lane >> 4) & 1;
    const int kr = (lane & 7) + ((lane & 16) ? 8 : 0);
    const int ku = (lane >> 3) & 1;
    const int row0 = w * 16 + (lane >> 2);

    if (do_state) {   // out = Qh @ (stateH + stateL)
        #pragma unroll
        for (int k16 = 0; k16 < 8; k16++) {
            uint32_t ah[4];
            ldsm4(ah[0], ah[1], ah[2], ah[3], sb + R_QH + swoff(rA, 2 * k16 + uA));
            #pragma unroll
            for (int en = 0; en < 8; en++) {
                int off = swoff(16 * k16 + tr, 2 * en + tu);
                uint32_t b0, b1, b2, b3;
                ldsm4t(b0, b1, b2, b3, sb + R_VH + off);
                mma_f32(out[2*en],   ah[0], ah[1], ah[2], ah[3], b0, b1);
                mma_f32(out[2*en+1], ah[0], ah[1], ah[2], ah[3], b2, b3);
                ldsm4t(b0, b1, b2, b3, sb + R_VL + off);
                mma_f32(out[2*en],   ah[0], ah[1], ah[2], ah[3], b0, b1);
                mma_f32(out[2*en+1], ah[0], ah[1], ah[2], ah[3], b2, b3);
            }
        }
        float e0a = sE0[row0], e0b = sE0[row0 + 8];
        #pragma unroll
        for (int t = 0; t < 16; t++) {
            out[t][0] *= e0a; out[t][1] *= e0a;
            out[t][2] *= e0b; out[t][3] *= e0b;
        }
    }
    __syncthreads();
    issue_tile(R_VH, R_VL,
               g_qkvh + (size_t)gi0 * TDM + 2 * DM + h * DH,
               g_qkvl + (size_t)gi0 * TDM + 2 * DM + h * DH);   // V(bi)

    int bj = bi;
    for (;;) {
        const int gj0 = bj * 128;
        asm volatile("cp.async.wait_group 1;" ::: "memory");    // K(bj) ready
        if (tid < 128) sFj[tid] = __expf(Aref - g_A[h * SQ + gj0 + tid]);
        __syncthreads();

        // S = Qh (Kh + Kl)^T
        float s[16][4] = {};
        #pragma unroll
        for (int k16 = 0; k16 < 8; k16++) {
            uint32_t ah[4];
            ldsm4(ah[0], ah[1], ah[2], ah[3], sb + R_QH + swoff(rA, 2 * k16 + uA));
            #pragma unroll
            for (int jn = 0; jn < 8; jn++) {
                int off = swoff(16 * jn + kr, 2 * k16 + ku);
                uint32_t b0, b1, b2, b3;
                ldsm4(b0, b1, b2, b3, sb + R_KH + off);
                mma_f32(s[2*jn],   ah[0], ah[1], ah[2], ah[3], b0, b1);
                mma_f32(s[2*jn+1], ah[0], ah[1], ah[2], ah[3], b2, b3);
                ldsm4(b0, b1, b2, b3, sb + R_KL + off);
                mma_f32(s[2*jn],   ah[0], ah[1], ah[2], ah[3], b0, b1);
                mma_f32(s[2*jn+1], ah[0], ah[1], ah[2], ah[3], b2, b3);
            }
        }
        __syncthreads();   // K buffers free

        const bool next_ok = (bj > 0) && (Aref - g_A[h * SQ + gj0 - 1] >= PRUNE);
        if (next_ok) {
            issue_tile(R_KH, R_KL,
                       g_qkvh + (size_t)(gj0 - 128) * TDM + DM + h * DH,
                       g_qkvl + (size_t)(gj0 - 128) * TDM + DM + h * DH);  // K(bj-1)
        } else {
            asm volatile("cp.async.commit_group;" ::: "memory");
        }

        // decay + mask while V(bj) finishes
        {
            float ea = sEi[row0], eb = sEi[row0 + 8];
            bool diag = (bj == bi);
            #pragma unroll
            for (int t = 0; t < 16; t++) {
                int c0 = 8 * t + (lane & 3) * 2;
                float f0 = sFj[c0], f1 = sFj[c0 + 1];
                s[t][0] *= ea * f0; s[t][1] *= ea * f1;
                s[t][2] *= eb * f0; s[t][3] *= eb * f1;
                if (diag) {
                    if (c0     > row0)     s[t][0] = 0.f;
                    if (c0 + 1 > row0)     s[t][1] = 0.f;
                    if (c0     > row0 + 8) s[t][2] = 0.f;
                    if (c0 + 1 > row0 + 8) s[t][3] = 0.f;
                }
            }
        }
        asm volatile("cp.async.wait_group 1;" ::: "memory");    // V(bj) ready
        __syncthreads();

        // out += Sh @ (Vh + Vl); S hi fragments as A operands
        #pragma unroll
        for (int kk = 0; kk < 8; kk++) {
            const int t0 = 2 * kk, t1 = 2 * kk + 1;
            uint32_t ah[4];
            ah[0] = packh(s[t0][0], s[t0][1]);
            ah[1] = packh(s[t0][2], s[t0][3]);
            ah[2] = packh(s[t1][0], s[t1][1]);
            ah[3] = packh(s[t1][2], s[t1][3]);
            #pragma unroll
            for (int en = 0; en < 8; en++) {
                int off = swoff(16 * kk + tr, 2 * en + tu);
                uint32_t b0, b1, b2, b3;
                ldsm4t(b0, b1, b2, b3, sb + R_VH + off);
                mma_f32(out[2*en],   ah[0], ah[1], ah[2], ah[3], b0, b1);
                mma_f32(out[2*en+1], ah[0], ah[1], ah[2], ah[3], b2, b3);
                ldsm4t(b0, b1, b2, b3, sb + R_VL + off);
                mma_f32(out[2*en],   ah[0], ah[1], ah[2], ah[3], b0, b1);
                mma_f32(out[2*en+1], ah[0], ah[1], ah[2], ah[3], b2, b3);
            }
        }

        if (!next_ok) break;
        __syncthreads();   // V buffers free
        issue_tile(R_VH, R_VL,
                   g_qkvh + (size_t)(gj0 - 128) * TDM + 2 * DM + h * DH,
                   g_qkvl + (size_t)(gj0 - 128) * TDM + 2 * DM + h * DH);  // V(bj-1)
        bj--;
    }
    asm volatile("cp.async.wait_group 0;" ::: "memory");

    #pragma unroll
    for (int t = 0; t < 16; t++) {
        int c0 = 8 * t + (lane & 3) * 2;
        float* p = g_ret + (size_t)(gi0 + row0) * DM + h * DH + c0;
        *(float2*)p = make_float2(out[t][0], out[t][1]);
        *(float2*)(p + (size_t)8 * DM) = make_float2(out[t][2], out[t][3]);
    }
}

// ---------------- new_state ----------------
__global__ __launch_bounds__(256) void nstate_partial_kernel()
{
    const int ch = blockIdx.x, h = blockIdx.y;
    const int gi0 = ch * 128;
    const int tid = threadIdx.x;
    const int tx = tid & 15, ty = tid >> 4;
    float* out = g_nsp + (size_t)(h * 16 + ch) * DH * DH;

    float Alast = g_A[h * SQ + SQ - 1];
    if (Alast - g_A[h * SQ + gi0 + 127] < PRUNE) {
        for (int idx = tid; idx < DH * DH; idx += 256) out[idx] = 0.f;
        return;
    }
    __shared__ float sK[16][SPAD];
    __shared__ float sV[16][SPAD];
    __shared__ float w[128];
    if (tid < 128) w[tid] = __expf(Alast - g_A[h * SQ + gi0 + tid]);
    __syncthreads();

    float acc[8][8] = {};
    for (int it = 0; it < 8; it++) {
        int i0 = gi0 + it * 16;
        #pragma unroll
        for (int q = 0; q < 2; q++) {
            int f = tid + 256 * q;
            int ir = f >> 5, d4 = (f & 31) * 4;
            float wi = w[it * 16 + ir];
            float4 kv = *(const float4*)(g_qkv + (size_t)(i0 + ir) * TDM + DM + h * DH + d4);
            float4 vv = *(const float4*)(g_qkv + (size_t)(i0 + ir) * TDM + 2 * DM + h * DH + d4);
            sK[ir][d4+0] = kv.x * wi; sK[ir][d4+1] = kv.y * wi;
            sK[ir][d4+2] = kv.z * wi; sK[ir][d4+3] = kv.w * wi;
            *(float4*)(&sV[ir][d4]) = vv;
        }
        __syncthreads();
        #pragma unroll
        for (int i = 0; i < 16; i++) {
            float4 a0 = *(const float4*)(&sK[i][ty*8]);
            float4 a1 = *(const float4*)(&sK[i][ty*8+4]);
            float4 b0 = *(const float4*)(&sV[i][tx*8]);
            float4 b1 = *(const float4*)(&sV[i][tx*8+4]);
            float av[8] = {a0.x,a0.y,a0.z,a0.w,a1.x,a1.y,a1.z,a1.w};
            float bv[8] = {b0.x,b0.y,b0.z,b0.w,b1.x,b1.y,b1.z,b1.w};
            #pragma unroll
            for (int r = 0; r < 8; r++)
                #pragma unroll
                for (int c = 0; c < 8; c++)
                    acc[r][c] = fmaf(av[r], bv[c], acc[r][c]);
        }
        __syncthreads();
    }
    #pragma unroll
    for (int r = 0; r < 8; r++)
        #pragma unroll
        for (int c = 0; c < 8; c++)
            out[(ty * 8 + r) * DH + tx * 8 + c] = acc[r][c];
}

__global__ __launch_bounds__(256) void nstate_reduce_kernel(const float* __restrict__ state,
                                                            float* __restrict__ outNS)
{
    int idx = blockIdx.x * 256 + threadIdx.x;
    int h = idx >> 14;
    float s = __expf(g_A[h * SQ + SQ - 1]) * state[idx];
    int de = idx & 16383;
    #pragma unroll
    for (int c = 0; c < 16; c++) s += g_nsp[(size_t)(h * 16 + c) * DH * DH + de];
    outNS[idx] = s;
}

// ---------------- group norm (fp32 g_ret + fp16 hi rh) ----------------
__global__ __launch_bounds__(256) void gnorm_kernel(const float* __restrict__ gw,
                                                    const float* __restrict__ gb)
{
    int warp = (blockIdx.x * 256 + threadIdx.x) >> 5;
    int lane = threadIdx.x & 31;
    int i = warp >> 4, h = warp & 15;
    float* p = g_ret + (size_t)i * DM + h * DH;
    float v[4], s = 0.f;
    #pragma unroll
    for (int c = 0; c < 4; c++) { v[c] = p[lane + 32 * c]; s += v[c]; }
    #pragma unroll
    for (int o = 16; o; o >>= 1) s += __shfl_xor_sync(0xffffffffu, s, o);
    float mu = s * (1.f / 128.f), q = 0.f;
    #pragma unroll
    for (int c = 0; c < 4; c++) { float d = v[c] - mu; q = fmaf(d, d, q); }
    #pragma unroll
    for (int o = 16; o; o >>= 1) q += __shfl_xor_sync(0xffffffffu, q, o);
    float rs = rsqrtf(q * (1.f / 128.f) + 1e-5f);
    #pragma unroll
    for (int c = 0; c < 4; c++) {
        int ch = h * DH + lane + 32 * c;
        float val = (v[c] - mu) * rs * gw[ch] + gb[ch];
        p[lane + 32 * c] = val;
        g_rh[(size_t)i * DM + ch] = __float2half_rn(val);
    }
}

extern "C" void kernel_launch(void* const* d_in, const int* in_sizes, int n_in,
                              void* d_out, int out_size)
{
    const float* x     = (const float*)d_in[0];
    const float* state = (const float*)d_in[1];
    const float* Wqkv  = (const float*)d_in[2];
    const float* Wa    = (const float*)d_in[3];
    const float* ba    = (const float*)d_in[4];
    const float* ab    = (const float*)d_in[5];
    const float* gw    = (const float*)d_in[6];
    const float* gb    = (const float*)d_in[7];
    const float* Wout  = (const float*)d_in[8];
    const float* Wgate = (const float*)d_in[9];
    const int*   offp  = (n_in > 10) ? (const int*)d_in[10] : nullptr;

    float* out   = (float*)d_out;
    float* outNS = out + (size_t)SQ * DM;

    float *qkv_p;
    cudaGetSymbolAddress((void**)&qkv_p, g_qkv);
    __half *xh,*Wqh,*Wgh,*Woh,*rh,*uh;
    cudaGetSymbolAddress((void**)&xh,  g_xh);
    cudaGetSymbolAddress((void**)&Wqh, g_Wqh);
    cudaGetSymbolAddress((void**)&Wgh, g_Wgh);
    cudaGetSymbolAddress((void**)&Woh, g_Woh);
    cudaGetSymbolAddress((void**)&rh,  g_rh);
    cudaGetSymbolAddress((void**)&uh,  g_uh);

    const int TG_SMEM = 98304;
    cudaFuncSetAttribute(tgemm<0>, cudaFuncAttributeMaxDynamicSharedMemorySize, TG_SMEM);
    cudaFuncSetAttribute(tgemm<1>, cudaFuncAttributeMaxDynamicSharedMemorySize, TG_SMEM);
    cudaFuncSetAttribute(retention_hmma, cudaFuncAttributeMaxDynamicSharedMemorySize, R_SMEM);

    alpha_kernel<<<SQ, 256>>>(x, Wa, ba, ab, xh);
    split_hi_kernel<<<TDM * DM / 1024, 256>>>(Wqkv, Wqh);
    split_hi_kernel<<<DM * DM / 1024, 256>>>(Wgate, Wgh);
    split_hi_kernel<<<DM * DM / 1024, 256>>>(Wout, Woh);

    tgemm<0><<<dim3(TDM/128, SQ/128), 256, TG_SMEM>>>(xh, Wqh, qkv_p, nullptr, TDM, DM);

    cumsum_kernel<<<NH, 256>>>();
    xpos_kernel<<<SQ, 64>>>(offp);
    retention_hmma<<<dim3(16, NH), 256, R_SMEM>>>(state);
    nstate_partial_kernel<<<dim3(16, NH), 256>>>();
    nstate_reduce_kernel<<<NH * DH * DH / 256, 256>>>(state, outNS);
    gnorm_kernel<<<SQ * NH / 8, 256>>>(gw, gb);

    tgemm<1><<<dim3(DM/128, SQ/128), 256, TG_SMEM>>>(rh, Wgh, nullptr, uh, DM, DM);
    tgemm<0><<<dim3(DM/128, SQ/128), 256, TG_SMEM>>>(uh, Woh, out, nullptr, DM, DM);
}